// round 2
// baseline (speedup 1.0000x reference)
#include <cuda_runtime.h>
#include <math.h>
#include <stdint.h>

#define Bb 4
#define Tt 2048
#define Dd 2048
#define Hh 32
#define HSz 64
#define BT (Bb*Tt)
#define E5c 160

// ---------------- scratch (device globals; no allocation allowed) ----------
__device__ float g_sx [BT*Dd];
__device__ float g_xxx[BT*Dd];
__device__ float g_m  [BT*E5c];
__device__ float g_wx [BT*Dd];
__device__ float g_kx [BT*Dd];
__device__ float g_vx [BT*Dd];
__device__ float g_rx [BT*Dd];
__device__ float g_gx [BT*Dd];
__device__ float g_r  [BT*Dd];
__device__ float g_k  [BT*Dd];
__device__ float g_v  [BT*Dd];
__device__ float g_g  [BT*Dd];
__device__ float g_h1 [BT*64];
__device__ float g_w  [BT*Dd];
__device__ float g_att[BT*Dd];
__device__ float g_gn [BT*Dd];

// ---------------- prep: sx = shifted - x ; xxx = x + sx*x_maa --------------
__global__ void __launch_bounds__(256) prep_k(
    const float* __restrict__ x, const float* __restrict__ prev,
    const float* __restrict__ xmaa, float* __restrict__ sx, float* __restrict__ xxx)
{
    size_t i = (size_t)blockIdx.x * 256 + threadIdx.x;
    int d = (int)(i % Dd);
    size_t bt = i / Dd;
    int t = (int)(bt % Tt);
    int b = (int)(bt / Tt);
    float xv = x[i];
    float sh = (t == 0) ? prev[(size_t)b * Dd + d] : x[i - Dd];
    float s = sh - xv;
    sx[i] = s;
    xxx[i] = fmaf(s, xmaa[d], xv);
}

// ---------------- generic SGEMM with epilogue ------------------------------
// C[M,N] = epi(A[M,K] @ B[K,N]); M % 128 == 0, K % 8 == 0, N arbitrary.
template<int EPI>
__device__ __forceinline__ float epi_f(float v, const float* extra, int col) {
    if (EPI == 1) return 1.f / (1.f + expf(-v));           // sigmoid
    if (EPI == 2) return tanhf(v);                         // tanh
    if (EPI == 3) return v / (1.f + expf(-v));             // silu
    if (EPI == 4) {                                        // w transform
        float t = v + extra[col];
        return expf(-expf(t));
    }
    return v;
}

template<int EPI>
__global__ void __launch_bounds__(256) sgemm_k(
    const float* __restrict__ A, const float* __restrict__ Bm,
    float* __restrict__ C, int M, int N, int K, const float* __restrict__ extra)
{
    __shared__ float As[8][128];
    __shared__ float Bs[8][128];
    const int tid  = threadIdx.x;
    const int tx   = tid & 15, ty = tid >> 4;
    const int rowA = tid >> 1, colA = (tid & 1) << 2;
    const int rowB = tid >> 5, colB = (tid & 31) << 2;
    const int mbase = blockIdx.y * 128;
    const int nbase = blockIdx.x * 128;
    const bool nfull = (nbase + 128 <= N);
    const float* Ap = A + (size_t)(mbase + rowA) * K + colA;

    float acc[8][8];
#pragma unroll
    for (int i = 0; i < 8; i++)
#pragma unroll
        for (int j = 0; j < 8; j++) acc[i][j] = 0.f;

    for (int k0 = 0; k0 < K; k0 += 8) {
        float4 av = *(const float4*)(Ap + k0);
        As[colA + 0][rowA] = av.x;
        As[colA + 1][rowA] = av.y;
        As[colA + 2][rowA] = av.z;
        As[colA + 3][rowA] = av.w;
        const float* Bp = Bm + (size_t)(k0 + rowB) * N + nbase + colB;
        if (nfull) {
            float4 bv = *(const float4*)Bp;
            *(float4*)&Bs[rowB][colB] = bv;
        } else {
#pragma unroll
            for (int j = 0; j < 4; j++) {
                int c = nbase + colB + j;
                Bs[rowB][colB + j] = (c < N) ? Bp[j] : 0.f;
            }
        }
        __syncthreads();
#pragma unroll
        for (int kk = 0; kk < 8; kk++) {
            float a[8], b[8];
            *(float4*)&a[0] = *(const float4*)&As[kk][ty * 8];
            *(float4*)&a[4] = *(const float4*)&As[kk][ty * 8 + 4];
            *(float4*)&b[0] = *(const float4*)&Bs[kk][tx * 8];
            *(float4*)&b[4] = *(const float4*)&Bs[kk][tx * 8 + 4];
#pragma unroll
            for (int i = 0; i < 8; i++)
#pragma unroll
                for (int j = 0; j < 8; j++)
                    acc[i][j] = fmaf(a[i], b[j], acc[i][j]);
        }
        __syncthreads();
    }
#pragma unroll
    for (int i = 0; i < 8; i++) {
        size_t rb = (size_t)(mbase + ty * 8 + i) * N;
#pragma unroll
        for (int j = 0; j < 8; j++) {
            int c = nbase + tx * 8 + j;
            if (c < N) C[rb + c] = epi_f<EPI>(acc[i][j], extra, c);
        }
    }
}

// ---------------- mix: 5 small GEMMs (K=32) fused with lerp ----------------
// block: 256 threads = 256 d-cols, 8 tokens, loops over 5 f-slices of tm_w2.
__global__ void __launch_bounds__(256) mix_k(
    const float* __restrict__ x, const float* __restrict__ sx,
    const float* __restrict__ m, const float* __restrict__ tmw2,
    const float* __restrict__ wmaa, const float* __restrict__ kmaa,
    const float* __restrict__ vmaa, const float* __restrict__ rmaa,
    const float* __restrict__ gmaa,
    float* __restrict__ wx, float* __restrict__ kx, float* __restrict__ vx,
    float* __restrict__ rx, float* __restrict__ gx)
{
    __shared__ float msh[8][E5c];
    __shared__ float tile[32][256];
    const int tid = threadIdx.x;
    const int dbase = blockIdx.x * 256;
    const int tb = blockIdx.y * 8;

    for (int i = tid; i < 8 * E5c; i += 256)
        msh[i / E5c][i % E5c] = m[(size_t)(tb + i / E5c) * E5c + (i % E5c)];

    float acc[8][5];
#pragma unroll
    for (int tok = 0; tok < 8; tok++)
#pragma unroll
        for (int f = 0; f < 5; f++) acc[tok][f] = 0.f;

#pragma unroll
    for (int f = 0; f < 5; f++) {
        __syncthreads();
        for (int e = 0; e < 32; e++)
            tile[e][tid] = tmw2[(size_t)(f * 32 + e) * Dd + dbase + tid];
        __syncthreads();
        for (int e = 0; e < 32; e++) {
            float tv = tile[e][tid];
#pragma unroll
            for (int tok = 0; tok < 8; tok++)
                acc[tok][f] = fmaf(msh[tok][f * 32 + e], tv, acc[tok][f]);
        }
    }

    const int d = dbase + tid;
    const float wm = wmaa[d], km = kmaa[d], vm = vmaa[d], rm = rmaa[d], gm = gmaa[d];
#pragma unroll
    for (int tok = 0; tok < 8; tok++) {
        size_t idx = (size_t)(tb + tok) * Dd + d;
        float xv = x[idx], sv = sx[idx];
        wx[idx] = fmaf(sv, wm + acc[tok][0], xv);
        kx[idx] = fmaf(sv, km + acc[tok][1], xv);
        vx[idx] = fmaf(sv, vm + acc[tok][2], xv);
        rx[idx] = fmaf(sv, rm + acc[tok][3], xv);
        gx[idx] = fmaf(sv, gm + acc[tok][4], xv);
    }
}

// ---------------- WKV sequential scan --------------------------------------
// one CTA per (b,h); thread tid = v-column; state column s[k] in registers.
__global__ void __launch_bounds__(64) wkv_k(
    const float* __restrict__ r, const float* __restrict__ k,
    const float* __restrict__ v, const float* __restrict__ w,
    const float* __restrict__ u, const float* __restrict__ s0,
    float* __restrict__ att, float* __restrict__ sout)
{
    const int bh = blockIdx.x;
    const int b = bh >> 5;      // / H
    const int h = bh & 31;
    const int tid = threadIdx.x;
    __shared__ float rsh[2][64], rush[2][64], ksh[2][64], wsh[2][64];

    float s[64];
    size_t sbase = (size_t)bh * 64 * 64;
#pragma unroll
    for (int i = 0; i < 64; i++) s[i] = s0[sbase + (size_t)i * 64 + tid];

    const float uo = u[h * 64 + tid];
    size_t base = (size_t)b * Tt * Dd + h * 64 + tid;
    int p = 0;
    for (int t = 0; t < Tt; t++) {
        float rv = r[base];
        float kv = k[base];
        float wv = w[base];
        float vm = v[base];
        rsh[p][tid]  = rv;
        rush[p][tid] = rv * uo;
        ksh[p][tid]  = kv;
        wsh[p][tid]  = wv;
        __syncthreads();
        float a0 = 0.f, a1 = 0.f, a2 = 0.f, a3 = 0.f;
#pragma unroll
        for (int kk = 0; kk < 64; kk += 4) {
            float t0 = ksh[p][kk + 0] * vm;
            a0 = fmaf(rsh[p][kk + 0], s[kk + 0], a0);
            a0 = fmaf(rush[p][kk + 0], t0, a0);
            s[kk + 0] = fmaf(s[kk + 0], wsh[p][kk + 0], t0);
            float t1 = ksh[p][kk + 1] * vm;
            a1 = fmaf(rsh[p][kk + 1], s[kk + 1], a1);
            a1 = fmaf(rush[p][kk + 1], t1, a1);
            s[kk + 1] = fmaf(s[kk + 1], wsh[p][kk + 1], t1);
            float t2 = ksh[p][kk + 2] * vm;
            a2 = fmaf(rsh[p][kk + 2], s[kk + 2], a2);
            a2 = fmaf(rush[p][kk + 2], t2, a2);
            s[kk + 2] = fmaf(s[kk + 2], wsh[p][kk + 2], t2);
            float t3 = ksh[p][kk + 3] * vm;
            a3 = fmaf(rsh[p][kk + 3], s[kk + 3], a3);
            a3 = fmaf(rush[p][kk + 3], t3, a3);
            s[kk + 3] = fmaf(s[kk + 3], wsh[p][kk + 3], t3);
        }
        att[base] = (a0 + a1) + (a2 + a3);
        base += Dd;
        p ^= 1;
    }
#pragma unroll
    for (int i = 0; i < 64; i++) sout[sbase + (size_t)i * 64 + tid] = s[i];
}

// ---------------- groupnorm over HS + ln + multiply by g -------------------
__global__ void __launch_bounds__(256) gnorm_k(
    const float* __restrict__ att, const float* __restrict__ g,
    const float* __restrict__ lng, const float* __restrict__ lnb,
    float* __restrict__ out)
{
    const int grp = blockIdx.x * 8 + (threadIdx.x >> 5);   // (bt, h) group
    const int lane = threadIdx.x & 31;
    const int bt = grp >> 5;
    const int h = grp & 31;
    size_t base = (size_t)bt * Dd + h * 64;
    float v0 = att[base + lane];
    float v1 = att[base + lane + 32];
    float sum = v0 + v1;
    float sq = v0 * v0 + v1 * v1;
#pragma unroll
    for (int o = 16; o > 0; o >>= 1) {
        sum += __shfl_xor_sync(0xffffffffu, sum, o);
        sq  += __shfl_xor_sync(0xffffffffu, sq, o);
    }
    float mu = sum * (1.f / 64.f);
    float var = sq * (1.f / 64.f) - mu * mu;
    float inv = rsqrtf(var + 1e-5f);
    int li = h * 64 + lane;
    out[base + lane]      = fmaf((v0 - mu) * inv, lng[li],      lnb[li])      * g[base + lane];
    out[base + lane + 32] = fmaf((v1 - mu) * inv, lng[li + 32], lnb[li + 32]) * g[base + lane + 32];
}

// ---------------- copy x[:, -1, :] -----------------------------------------
__global__ void __launch_bounds__(256) lastcopy_k(const float* __restrict__ x,
                                                  float* __restrict__ o)
{
    int i = blockIdx.x * 256 + threadIdx.x;    // 0 .. B*D-1
    int b = i / Dd, d = i % Dd;
    o[i] = x[((size_t)b * Tt + (Tt - 1)) * Dd + d];
}

// ---------------- host ------------------------------------------------------
extern "C" void kernel_launch(void* const* d_in, const int* in_sizes, int n_in,
                              void* d_out, int out_size)
{
    const float* x     = (const float*)d_in[0];
    const float* prev  = (const float*)d_in[1];
    const float* state = (const float*)d_in[2];
    const float* x_maa = (const float*)d_in[3];
    const float* w_maa = (const float*)d_in[4];
    const float* k_maa = (const float*)d_in[5];
    const float* v_maa = (const float*)d_in[6];
    const float* r_maa = (const float*)d_in[7];
    const float* g_maa = (const float*)d_in[8];
    const float* tm_w1 = (const float*)d_in[9];
    const float* tm_w2 = (const float*)d_in[10];
    const float* td_w1 = (const float*)d_in[11];
    const float* td_w2 = (const float*)d_in[12];
    const float* tdec  = (const float*)d_in[13];
    const float* tfirst= (const float*)d_in[14];
    const float* W_r   = (const float*)d_in[15];
    const float* W_k   = (const float*)d_in[16];
    const float* W_v   = (const float*)d_in[17];
    const float* W_g   = (const float*)d_in[18];
    const float* W_o   = (const float*)d_in[19];
    const float* ln_g  = (const float*)d_in[20];
    const float* ln_b  = (const float*)d_in[21];

    float *sx, *xxx, *m, *wx, *kx, *vx, *rx, *gx, *r, *k, *v, *g, *h1, *w, *att, *gn;
    cudaGetSymbolAddress((void**)&sx,  g_sx);
    cudaGetSymbolAddress((void**)&xxx, g_xxx);
    cudaGetSymbolAddress((void**)&m,   g_m);
    cudaGetSymbolAddress((void**)&wx,  g_wx);
    cudaGetSymbolAddress((void**)&kx,  g_kx);
    cudaGetSymbolAddress((void**)&vx,  g_vx);
    cudaGetSymbolAddress((void**)&rx,  g_rx);
    cudaGetSymbolAddress((void**)&gx,  g_gx);
    cudaGetSymbolAddress((void**)&r,   g_r);
    cudaGetSymbolAddress((void**)&k,   g_k);
    cudaGetSymbolAddress((void**)&v,   g_v);
    cudaGetSymbolAddress((void**)&g,   g_g);
    cudaGetSymbolAddress((void**)&h1,  g_h1);
    cudaGetSymbolAddress((void**)&w,   g_w);
    cudaGetSymbolAddress((void**)&att, g_att);
    cudaGetSymbolAddress((void**)&gn,  g_gn);

    float* out0 = (float*)d_out;                          // (B,T,D)
    float* out_xlast = out0 + (size_t)BT * Dd;            // (B,D)
    float* out_state = out_xlast + (size_t)Bb * Dd;       // (B,H,HS,HS)

    // 1) shift + xxx
    prep_k<<<(BT * Dd) / 256, 256>>>(x, prev, x_maa, sx, xxx);
    // 2) m = tanh(xxx @ tm_w1)   [8192 x 160, K=2048]
    sgemm_k<2><<<dim3((E5c + 127) / 128, BT / 128), 256>>>(xxx, tm_w1, m, BT, E5c, Dd, nullptr);
    // 3) mix + 5 lerps
    mix_k<<<dim3(Dd / 256, BT / 8), 256>>>(x, sx, m, tm_w2,
                                           w_maa, k_maa, v_maa, r_maa, g_maa,
                                           wx, kx, vx, rx, gx);
    // 4) big GEMMs
    dim3 gBig(Dd / 128, BT / 128);
    sgemm_k<1><<<gBig, 256>>>(rx, W_r, r, BT, Dd, Dd, nullptr);   // sigmoid
    sgemm_k<0><<<gBig, 256>>>(kx, W_k, k, BT, Dd, Dd, nullptr);
    sgemm_k<0><<<gBig, 256>>>(vx, W_v, v, BT, Dd, Dd, nullptr);
    sgemm_k<3><<<gBig, 256>>>(gx, W_g, g, BT, Dd, Dd, nullptr);   // silu
    // 5) w path: h1 = tanh(wx @ td_w1); w = exp(-exp(h1 @ td_w2 + decay))
    sgemm_k<2><<<dim3(1, BT / 128), 256>>>(wx, td_w1, h1, BT, 64, Dd, nullptr);
    sgemm_k<4><<<gBig, 256>>>(h1, td_w2, w, BT, Dd, 64, tdec);
    // 6) WKV scan (also writes new_state straight into d_out)
    wkv_k<<<Bb * Hh, 64>>>(r, k, v, w, tfirst, state, att, out_state);
    // 7) groupnorm * ln * g
    gnorm_k<<<(BT * Hh) / 8, 256>>>(att, g, ln_g, ln_b, gn);
    // 8) out = gn @ W_o -> d_out
    sgemm_k<0><<<gBig, 256>>>(gn, W_o, out0, BT, Dd, Dd, nullptr);
    // 9) x[:, -1]
    lastcopy_k<<<(Bb * Dd) / 256, 256>>>(x, out_xlast);
}

// round 4
// speedup vs baseline: 3.6876x; 3.6876x over previous
#include <cuda_runtime.h>
#include <cuda_bf16.h>
#include <math.h>
#include <stdint.h>

#define Bb 4
#define Tt 2048
#define Dd 2048
#define Hh 32
#define HSz 64
#define BT (Bb*Tt)
#define E5c 160

// ====================== device scratch (bss, no alloc) ======================
__device__ float g_sx [BT*Dd];
__device__ float g_m  [BT*E5c];
__device__ float g_r  [BT*Dd];
__device__ float g_k  [BT*Dd];
__device__ float g_v  [BT*Dd];
__device__ float g_g  [BT*Dd];
__device__ float g_w  [BT*Dd];
__device__ float g_att[BT*Dd];

__device__ __nv_bfloat16 g_xh [BT*Dd], g_xl [BT*Dd];
__device__ __nv_bfloat16 g_wxh[BT*Dd], g_wxl[BT*Dd];
__device__ __nv_bfloat16 g_kxh[BT*Dd], g_kxl[BT*Dd];
__device__ __nv_bfloat16 g_vxh[BT*Dd], g_vxl[BT*Dd];
__device__ __nv_bfloat16 g_rxh[BT*Dd], g_rxl[BT*Dd];
__device__ __nv_bfloat16 g_gxh[BT*Dd], g_gxl[BT*Dd];
__device__ __nv_bfloat16 g_gnh[BT*Dd], g_gnl[BT*Dd];
__device__ __nv_bfloat16 g_h1h[BT*64], g_h1l[BT*64];

__device__ __nv_bfloat16 g_wrh[Dd*Dd], g_wrl[Dd*Dd];
__device__ __nv_bfloat16 g_wkh[Dd*Dd], g_wkl[Dd*Dd];
__device__ __nv_bfloat16 g_wvh[Dd*Dd], g_wvl[Dd*Dd];
__device__ __nv_bfloat16 g_wgh[Dd*Dd], g_wgl[Dd*Dd];
__device__ __nv_bfloat16 g_woh[Dd*Dd], g_wol[Dd*Dd];
__device__ __nv_bfloat16 g_tm1h[256*Dd], g_tm1l[256*Dd];
__device__ __nv_bfloat16 g_td1h[128*Dd], g_td1l[128*Dd];
__device__ __nv_bfloat16 g_td2h[Dd*64],  g_td2l[Dd*64];

// ====================== PTX helpers (sm_80-class only) ======================
__device__ __forceinline__ uint32_t smem_u32(const void* p) {
    uint32_t a;
    asm("{ .reg .u64 t; cvta.to.shared.u64 t, %1; cvt.u32.u64 %0, t; }"
        : "=r"(a) : "l"(p));
    return a;
}

#define CP_ASYNC16(dst, src) \
    asm volatile("cp.async.cg.shared.global [%0], [%1], 16;" \
        :: "r"(dst), "l"(src) : "memory")
#define CP_COMMIT() asm volatile("cp.async.commit_group;" ::: "memory")
#define CP_WAIT0()  asm volatile("cp.async.wait_group 0;" ::: "memory")
#define CP_WAIT1()  asm volatile("cp.async.wait_group 1;" ::: "memory")

__device__ __forceinline__ void ldsm4(uint32_t* r, uint32_t addr) {
    asm volatile("ldmatrix.sync.aligned.m8n8.x4.shared.b16 {%0,%1,%2,%3},[%4];"
        : "=r"(r[0]), "=r"(r[1]), "=r"(r[2]), "=r"(r[3]) : "r"(addr));
}

__device__ __forceinline__ void mma16816(float* c, const uint32_t* a, const uint32_t* b) {
    asm volatile(
        "mma.sync.aligned.m16n8k16.row.col.f32.bf16.bf16.f32 "
        "{%0,%1,%2,%3},{%4,%5,%6,%7},{%8,%9},{%0,%1,%2,%3};"
        : "+f"(c[0]), "+f"(c[1]), "+f"(c[2]), "+f"(c[3])
        : "r"(a[0]), "r"(a[1]), "r"(a[2]), "r"(a[3]), "r"(b[0]), "r"(b[1]));
}

__device__ __forceinline__ uint32_t swz(uint32_t bo) { return bo ^ ((bo >> 3) & 0x70); }

// ====================== tensor-core GEMM (HMMA mma.sync) ====================
// C[M, Nout] = epi(A[M,K] @ Bt[Npad,K]^T);  K % 64 == 0, M % 128 == 0.
// A split Ah+Al bf16 (row-major, K contiguous); Bt split Bh+Bl bf16 ([N][K]).
// 3-split: Ah*Bh + Ah*Bl + Al*Bh in fp32 accumulators.

template<int EPI>
__device__ __forceinline__ float gepi(float v, const float* extra, int n) {
    if (EPI == 1) return 1.f / (1.f + expf(-v));     // sigmoid
    if (EPI == 2) return tanhf(v);                   // tanh
    if (EPI == 3) return v / (1.f + expf(-v));       // silu
    if (EPI == 4) return expf(-expf(v + extra[n]));  // w transform
    return v;
}

// async-load one 128x64 bf16 tile into SW128-swizzled smem (256 threads)
__device__ __forceinline__ void load_tile_async(uint32_t sbase,
    const __nv_bfloat16* __restrict__ src, int row0, int k0, int ldK, int tid)
{
#pragma unroll
    for (int i = 0; i < 4; i++) {
        int u = i * 256 + tid;
        int row = u >> 3, cc = u & 7;
        uint32_t bo = (uint32_t)(row * 128 + cc * 16);
        CP_ASYNC16(sbase + swz(bo),
                   src + (size_t)(row0 + row) * ldK + k0 + cc * 8);
    }
}

#define ST_SZ 65536u   // 4 sub-tiles x 16KB
#define GEMM_SMEM (2 * ST_SZ)

template<int EPI, int OUT>
__global__ void __launch_bounds__(256, 1) gemm_tc(
    const __nv_bfloat16* __restrict__ Ah, const __nv_bfloat16* __restrict__ Al,
    const __nv_bfloat16* __restrict__ Bh, const __nv_bfloat16* __restrict__ Bl,
    float* __restrict__ Cf, __nv_bfloat16* __restrict__ Ch, __nv_bfloat16* __restrict__ Cl,
    int M, int Nout, int K, const float* __restrict__ extra)
{
    extern __shared__ char sm[];
    const uint32_t sb = smem_u32(sm);
    const int tid = threadIdx.x, lane = tid & 31, wid = tid >> 5;
    const int wm = wid >> 1, wn = wid & 1;           // 4 x 2 warp grid
    const int mbase = blockIdx.y * 128, nbase = blockIdx.x * 128;

    float acc[2][8][4];
#pragma unroll
    for (int mf = 0; mf < 2; mf++)
#pragma unroll
        for (int nf = 0; nf < 8; nf++)
#pragma unroll
            for (int q = 0; q < 4; q++) acc[mf][nf][q] = 0.f;

    const int nc = K / 64;

    // prologue: chunk 0 -> stage 0
    {
        uint32_t st = sb;
        load_tile_async(st +     0, Ah, mbase, 0, K, tid);
        load_tile_async(st + 16384, Al, mbase, 0, K, tid);
        load_tile_async(st + 32768, Bh, nbase, 0, K, tid);
        load_tile_async(st + 49152, Bl, nbase, 0, K, tid);
        CP_COMMIT();
    }

    // precomputed ldmatrix lane geometry
    const int a_row = (lane & 15);                 // + wm*32 + mf*16
    const int a_cb  = ((lane >> 4) & 1) * 16;      // + ks*32
    const int mat   = lane >> 3;
    const int b_row = (lane & 7) + ((mat >> 1) & 1) * 8;  // + wn*64 + bq*16
    const int b_cb  = (mat & 1) * 16;              // + ks*32

    for (int c = 0; c < nc; c++) {
        if (c + 1 < nc) {
            uint32_t st = sb + ((c + 1) & 1) * ST_SZ;
            int k0 = (c + 1) * 64;
            load_tile_async(st +     0, Ah, mbase, k0, K, tid);
            load_tile_async(st + 16384, Al, mbase, k0, K, tid);
            load_tile_async(st + 32768, Bh, nbase, k0, K, tid);
            load_tile_async(st + 49152, Bl, nbase, k0, K, tid);
            CP_COMMIT();
            CP_WAIT1();
        } else {
            CP_WAIT0();
        }
        __syncthreads();

        const uint32_t base = sb + (c & 1) * ST_SZ;
#pragma unroll
        for (int ks = 0; ks < 4; ks++) {
            uint32_t ah[2][4], al[2][4];
#pragma unroll
            for (int mf = 0; mf < 2; mf++) {
                uint32_t bo = (uint32_t)((wm * 32 + mf * 16 + a_row) * 128 + ks * 32 + a_cb);
                uint32_t sw = swz(bo);
                ldsm4(ah[mf], base + sw);
                ldsm4(al[mf], base + 16384 + sw);
            }
            uint32_t bh[4][4], bl[4][4];
#pragma unroll
            for (int bq = 0; bq < 4; bq++) {
                uint32_t bo = (uint32_t)((wn * 64 + bq * 16 + b_row) * 128 + ks * 32 + b_cb);
                uint32_t sw = swz(bo);
                ldsm4(bh[bq], base + 32768 + sw);
                ldsm4(bl[bq], base + 49152 + sw);
            }
#pragma unroll
            for (int mf = 0; mf < 2; mf++)
#pragma unroll
                for (int bq = 0; bq < 4; bq++) {
                    mma16816(acc[mf][2 * bq],     ah[mf], &bh[bq][0]);
                    mma16816(acc[mf][2 * bq + 1], ah[mf], &bh[bq][2]);
                    mma16816(acc[mf][2 * bq],     ah[mf], &bl[bq][0]);
                    mma16816(acc[mf][2 * bq + 1], ah[mf], &bl[bq][2]);
                    mma16816(acc[mf][2 * bq],     al[mf], &bh[bq][0]);
                    mma16816(acc[mf][2 * bq + 1], al[mf], &bh[bq][2]);
                }
        }
        __syncthreads();
    }

    // epilogue: fragment -> gmem (pairs of columns are contiguous)
    const int r_in = lane >> 2, c_in = (lane & 3) * 2;
#pragma unroll
    for (int mf = 0; mf < 2; mf++)
#pragma unroll
        for (int nf = 0; nf < 8; nf++) {
            int row0 = mbase + wm * 32 + mf * 16 + r_in;
            int col  = nbase + wn * 64 + nf * 8 + c_in;
            if (col >= Nout) continue;
            float* q = acc[mf][nf];
            float e0 = gepi<EPI>(q[0], extra, col);
            float e1 = gepi<EPI>(q[1], extra, col + 1);
            float e2 = gepi<EPI>(q[2], extra, col);
            float e3 = gepi<EPI>(q[3], extra, col + 1);
            if (OUT == 0) {
                float2 u0 = make_float2(e0, e1);
                float2 u1 = make_float2(e2, e3);
                *(float2*)(Cf + (size_t)row0 * Nout + col) = u0;
                *(float2*)(Cf + (size_t)(row0 + 8) * Nout + col) = u1;
            } else {
                size_t o0 = (size_t)row0 * Nout + col;
                size_t o1 = (size_t)(row0 + 8) * Nout + col;
                __nv_bfloat16 h;
                h = __float2bfloat16(e0); Ch[o0]     = h; Cl[o0]     = __float2bfloat16(e0 - __bfloat162float(h));
                h = __float2bfloat16(e1); Ch[o0 + 1] = h; Cl[o0 + 1] = __float2bfloat16(e1 - __bfloat162float(h));
                h = __float2bfloat16(e2); Ch[o1]     = h; Cl[o1]     = __float2bfloat16(e2 - __bfloat162float(h));
                h = __float2bfloat16(e3); Ch[o1 + 1] = h; Cl[o1 + 1] = __float2bfloat16(e3 - __bfloat162float(h));
            }
        }
}

// ====================== weight transpose + bf16 split =======================
__global__ void __launch_bounds__(256) tsplit_k(
    const float* __restrict__ W, __nv_bfloat16* __restrict__ bh,
    __nv_bfloat16* __restrict__ bl, int K, int N)
{
    __shared__ float t[32][33];
    const int k0 = blockIdx.x * 32, n0 = blockIdx.y * 32;
    const int tx = threadIdx.x & 31, ty = threadIdx.x >> 5;
#pragma unroll
    for (int i = 0; i < 4; i++) {
        int kk = ty + i * 8;
        int n = n0 + tx;
        t[kk][tx] = (n < N) ? W[(size_t)(k0 + kk) * N + n] : 0.f;
    }
    __syncthreads();
#pragma unroll
    for (int i = 0; i < 4; i++) {
        int nn = ty + i * 8;
        float v = t[tx][nn];
        __nv_bfloat16 h = __float2bfloat16(v);
        size_t o = (size_t)(n0 + nn) * K + k0 + tx;
        bh[o] = h;
        bl[o] = __float2bfloat16(v - __bfloat162float(h));
    }
}

// ====================== prep: sx + split(xxx) ===============================
__global__ void __launch_bounds__(256) prep_k(
    const float* __restrict__ x, const float* __restrict__ prev,
    const float* __restrict__ xmaa, float* __restrict__ sx,
    __nv_bfloat16* __restrict__ xh, __nv_bfloat16* __restrict__ xl)
{
    size_t i = (size_t)blockIdx.x * 256 + threadIdx.x;
    int d = (int)(i % Dd);
    size_t bt = i / Dd;
    int t = (int)(bt % Tt);
    int b = (int)(bt / Tt);
    float xv = x[i];
    float sh = (t == 0) ? prev[(size_t)b * Dd + d] : x[i - Dd];
    float s = sh - xv;
    sx[i] = s;
    float xxx = fmaf(s, xmaa[d], xv);
    __nv_bfloat16 h = __float2bfloat16(xxx);
    xh[i] = h;
    xl[i] = __float2bfloat16(xxx - __bfloat162float(h));
}

// ====================== mix: 5 lerps, writes bf16 splits ====================
__global__ void __launch_bounds__(256) mix_k(
    const float* __restrict__ x, const float* __restrict__ sx,
    const float* __restrict__ m, const float* __restrict__ tmw2,
    const float* __restrict__ wmaa, const float* __restrict__ kmaa,
    const float* __restrict__ vmaa, const float* __restrict__ rmaa,
    const float* __restrict__ gmaa,
    __nv_bfloat16* __restrict__ wxh, __nv_bfloat16* __restrict__ wxl,
    __nv_bfloat16* __restrict__ kxh, __nv_bfloat16* __restrict__ kxl,
    __nv_bfloat16* __restrict__ vxh, __nv_bfloat16* __restrict__ vxl,
    __nv_bfloat16* __restrict__ rxh, __nv_bfloat16* __restrict__ rxl,
    __nv_bfloat16* __restrict__ gxh, __nv_bfloat16* __restrict__ gxl)
{
    __shared__ float msh[8][E5c];
    __shared__ float tile[32][256];
    const int tid = threadIdx.x;
    const int dbase = blockIdx.x * 256;
    const int tb = blockIdx.y * 8;

    for (int i = tid; i < 8 * E5c; i += 256)
        msh[i / E5c][i % E5c] = m[(size_t)(tb + i / E5c) * E5c + (i % E5c)];

    float acc[8][5];
#pragma unroll
    for (int tok = 0; tok < 8; tok++)
#pragma unroll
        for (int f = 0; f < 5; f++) acc[tok][f] = 0.f;

#pragma unroll
    for (int f = 0; f < 5; f++) {
        __syncthreads();
        for (int e = 0; e < 32; e++)
            tile[e][tid] = tmw2[(size_t)(f * 32 + e) * Dd + dbase + tid];
        __syncthreads();
        for (int e = 0; e < 32; e++) {
            float tv = tile[e][tid];
#pragma unroll
            for (int tok = 0; tok < 8; tok++)
                acc[tok][f] = fmaf(msh[tok][f * 32 + e], tv, acc[tok][f]);
        }
    }

    const int d = dbase + tid;
    const float wm = wmaa[d], km = kmaa[d], vm = vmaa[d], rm = rmaa[d], gm = gmaa[d];
#pragma unroll
    for (int tok = 0; tok < 8; tok++) {
        size_t idx = (size_t)(tb + tok) * Dd + d;
        float xv = x[idx], sv = sx[idx];
        float w_ = fmaf(sv, wm + acc[tok][0], xv);
        float k_ = fmaf(sv, km + acc[tok][1], xv);
        float v_ = fmaf(sv, vm + acc[tok][2], xv);
        float r_ = fmaf(sv, rm + acc[tok][3], xv);
        float g_ = fmaf(sv, gm + acc[tok][4], xv);
        __nv_bfloat16 h;
        h = __float2bfloat16(w_); wxh[idx] = h; wxl[idx] = __float2bfloat16(w_ - __bfloat162float(h));
        h = __float2bfloat16(k_); kxh[idx] = h; kxl[idx] = __float2bfloat16(k_ - __bfloat162float(h));
        h = __float2bfloat16(v_); vxh[idx] = h; vxl[idx] = __float2bfloat16(v_ - __bfloat162float(h));
        h = __float2bfloat16(r_); rxh[idx] = h; rxl[idx] = __float2bfloat16(r_ - __bfloat162float(h));
        h = __float2bfloat16(g_); gxh[idx] = h; gxl[idx] = __float2bfloat16(g_ - __bfloat162float(h));
    }
}

// ====================== WKV sequential scan =================================
__global__ void __launch_bounds__(64) wkv_k(
    const float* __restrict__ r, const float* __restrict__ k,
    const float* __restrict__ v, const float* __restrict__ w,
    const float* __restrict__ u, const float* __restrict__ s0,
    float* __restrict__ att, float* __restrict__ sout)
{
    const int bh = blockIdx.x;
    const int b = bh >> 5;
    const int h = bh & 31;
    const int tid = threadIdx.x;
    __shared__ float rsh[2][64], rush[2][64], ksh[2][64], wsh[2][64];

    float s[64];
    size_t sbase = (size_t)bh * 64 * 64;
#pragma unroll
    for (int i = 0; i < 64; i++) s[i] = s0[sbase + (size_t)i * 64 + tid];

    const float uo = u[h * 64 + tid];
    size_t base = (size_t)b * Tt * Dd + h * 64 + tid;
    int p = 0;
    for (int t = 0; t < Tt; t++) {
        float rv = r[base];
        float kv = k[base];
        float wv = w[base];
        float vm = v[base];
        rsh[p][tid]  = rv;
        rush[p][tid] = rv * uo;
        ksh[p][tid]  = kv;
        wsh[p][tid]  = wv;
        __syncthreads();
        float a0 = 0.f, a1 = 0.f, a2 = 0.f, a3 = 0.f;
#pragma unroll
        for (int kk = 0; kk < 64; kk += 4) {
            float t0 = ksh[p][kk + 0] * vm;
            a0 = fmaf(rsh[p][kk + 0], s[kk + 0], a0);
            a0 = fmaf(rush[p][kk + 0], t0, a0);
            s[kk + 0] = fmaf(s[kk + 0], wsh[p][kk + 0], t0);
            float t1 = ksh[p][kk + 1] * vm;
            a1 = fmaf(rsh[p][kk + 1], s[kk + 1], a1);
            a1 = fmaf(rush[p][kk + 1], t1, a1);
            s[kk + 1] = fmaf(s[kk + 1], wsh[p][kk + 1], t1);
            float t2 = ksh[p][kk + 2] * vm;
            a2 = fmaf(rsh[p][kk + 2], s[kk + 2], a2);
            a2 = fmaf(rush[p][kk + 2], t2, a2);
            s[kk + 2] = fmaf(s[kk + 2], wsh[p][kk + 2], t2);
            float t3 = ksh[p][kk + 3] * vm;
            a3 = fmaf(rsh[p][kk + 3], s[kk + 3], a3);
            a3 = fmaf(rush[p][kk + 3], t3, a3);
            s[kk + 3] = fmaf(s[kk + 3], wsh[p][kk + 3], t3);
        }
        att[base] = (a0 + a1) + (a2 + a3);
        base += Dd;
        p ^= 1;
    }
#pragma unroll
    for (int i = 0; i < 64; i++) sout[sbase + (size_t)i * 64 + tid] = s[i];
}

// ====================== groupnorm + ln + *g, writes bf16 splits =============
__global__ void __launch_bounds__(256) gnorm_k(
    const float* __restrict__ att, const float* __restrict__ g,
    const float* __restrict__ lng, const float* __restrict__ lnb,
    __nv_bfloat16* __restrict__ oh, __nv_bfloat16* __restrict__ ol)
{
    const int grp = blockIdx.x * 8 + (threadIdx.x >> 5);
    const int lane = threadIdx.x & 31;
    const int bt = grp >> 5;
    const int h = grp & 31;
    size_t base = (size_t)bt * Dd + h * 64;
    float v0 = att[base + lane];
    float v1 = att[base + lane + 32];
    float sum = v0 + v1;
    float sq = v0 * v0 + v1 * v1;
#pragma unroll
    for (int o = 16; o > 0; o >>= 1) {
        sum += __shfl_xor_sync(0xffffffffu, sum, o);
        sq  += __shfl_xor_sync(0xffffffffu, sq, o);
    }
    float mu = sum * (1.f / 64.f);
    float var = sq * (1.f / 64.f) - mu * mu;
    float inv = rsqrtf(var + 1e-5f);
    int li = h * 64 + lane;
    float o0 = fmaf((v0 - mu) * inv, lng[li],      lnb[li])      * g[base + lane];
    float o1 = fmaf((v1 - mu) * inv, lng[li + 32], lnb[li + 32]) * g[base + lane + 32];
    __nv_bfloat16 hh;
    hh = __float2bfloat16(o0); oh[base + lane]      = hh; ol[base + lane]      = __float2bfloat16(o0 - __bfloat162float(hh));
    hh = __float2bfloat16(o1); oh[base + lane + 32] = hh; ol[base + lane + 32] = __float2bfloat16(o1 - __bfloat162float(hh));
}

// ====================== copy x[:, -1, :] ====================================
__global__ void __launch_bounds__(256) lastcopy_k(const float* __restrict__ x,
                                                  float* __restrict__ o)
{
    int i = blockIdx.x * 256 + threadIdx.x;
    int b = i / Dd, d = i % Dd;
    o[i] = x[((size_t)b * Tt + (Tt - 1)) * Dd + d];
}

// ====================== host ================================================
extern "C" void kernel_launch(void* const* d_in, const int* in_sizes, int n_in,
                              void* d_out, int out_size)
{
    const float* x     = (const float*)d_in[0];
    const float* prev  = (const float*)d_in[1];
    const float* state = (const float*)d_in[2];
    const float* x_maa = (const float*)d_in[3];
    const float* w_maa = (const float*)d_in[4];
    const float* k_maa = (const float*)d_in[5];
    const float* v_maa = (const float*)d_in[6];
    const float* r_maa = (const float*)d_in[7];
    const float* g_maa = (const float*)d_in[8];
    const float* tm_w1 = (const float*)d_in[9];
    const float* tm_w2 = (const float*)d_in[10];
    const float* td_w1 = (const float*)d_in[11];
    const float* td_w2 = (const float*)d_in[12];
    const float* tdec  = (const float*)d_in[13];
    const float* tfirst= (const float*)d_in[14];
    const float* W_r   = (const float*)d_in[15];
    const float* W_k   = (const float*)d_in[16];
    const float* W_v   = (const float*)d_in[17];
    const float* W_g   = (const float*)d_in[18];
    const float* W_o   = (const float*)d_in[19];
    const float* ln_g  = (const float*)d_in[20];
    const float* ln_b  = (const float*)d_in[21];

    float *sx, *m, *r, *k, *v, *g, *w, *att;
    cudaGetSymbolAddress((void**)&sx,  g_sx);
    cudaGetSymbolAddress((void**)&m,   g_m);
    cudaGetSymbolAddress((void**)&r,   g_r);
    cudaGetSymbolAddress((void**)&k,   g_k);
    cudaGetSymbolAddress((void**)&v,   g_v);
    cudaGetSymbolAddress((void**)&g,   g_g);
    cudaGetSymbolAddress((void**)&w,   g_w);
    cudaGetSymbolAddress((void**)&att, g_att);

    __nv_bfloat16 *xh, *xl, *wxh, *wxl, *kxh, *kxl, *vxh, *vxl, *rxh, *rxl, *gxh, *gxl;
    __nv_bfloat16 *gnh, *gnl, *h1h, *h1l;
    __nv_bfloat16 *wrh, *wrl, *wkh, *wkl, *wvh, *wvl, *wgh, *wgl, *woh, *wol;
    __nv_bfloat16 *tm1h, *tm1l, *td1h, *td1l, *td2h, *td2l;
    cudaGetSymbolAddress((void**)&xh,  g_xh);  cudaGetSymbolAddress((void**)&xl,  g_xl);
    cudaGetSymbolAddress((void**)&wxh, g_wxh); cudaGetSymbolAddress((void**)&wxl, g_wxl);
    cudaGetSymbolAddress((void**)&kxh, g_kxh); cudaGetSymbolAddress((void**)&kxl, g_kxl);
    cudaGetSymbolAddress((void**)&vxh, g_vxh); cudaGetSymbolAddress((void**)&vxl, g_vxl);
    cudaGetSymbolAddress((void**)&rxh, g_rxh); cudaGetSymbolAddress((void**)&rxl, g_rxl);
    cudaGetSymbolAddress((void**)&gxh, g_gxh); cudaGetSymbolAddress((void**)&gxl, g_gxl);
    cudaGetSymbolAddress((void**)&gnh, g_gnh); cudaGetSymbolAddress((void**)&gnl, g_gnl);
    cudaGetSymbolAddress((void**)&h1h, g_h1h); cudaGetSymbolAddress((void**)&h1l, g_h1l);
    cudaGetSymbolAddress((void**)&wrh, g_wrh); cudaGetSymbolAddress((void**)&wrl, g_wrl);
    cudaGetSymbolAddress((void**)&wkh, g_wkh); cudaGetSymbolAddress((void**)&wkl, g_wkl);
    cudaGetSymbolAddress((void**)&wvh, g_wvh); cudaGetSymbolAddress((void**)&wvl, g_wvl);
    cudaGetSymbolAddress((void**)&wgh, g_wgh); cudaGetSymbolAddress((void**)&wgl, g_wgl);
    cudaGetSymbolAddress((void**)&woh, g_woh); cudaGetSymbolAddress((void**)&wol, g_wol);
    cudaGetSymbolAddress((void**)&tm1h, g_tm1h); cudaGetSymbolAddress((void**)&tm1l, g_tm1l);
    cudaGetSymbolAddress((void**)&td1h, g_td1h); cudaGetSymbolAddress((void**)&td1l, g_td1l);
    cudaGetSymbolAddress((void**)&td2h, g_td2h); cudaGetSymbolAddress((void**)&td2l, g_td2l);

    float* out0 = (float*)d_out;
    float* out_xlast = out0 + (size_t)BT * Dd;
    float* out_state = out_xlast + (size_t)Bb * Dd;

    cudaFuncSetAttribute(gemm_tc<0,0>, cudaFuncAttributeMaxDynamicSharedMemorySize, GEMM_SMEM);
    cudaFuncSetAttribute(gemm_tc<1,0>, cudaFuncAttributeMaxDynamicSharedMemorySize, GEMM_SMEM);
    cudaFuncSetAttribute(gemm_tc<2,0>, cudaFuncAttributeMaxDynamicSharedMemorySize, GEMM_SMEM);
    cudaFuncSetAttribute(gemm_tc<2,1>, cudaFuncAttributeMaxDynamicSharedMemorySize, GEMM_SMEM);
    cudaFuncSetAttribute(gemm_tc<3,0>, cudaFuncAttributeMaxDynamicSharedMemorySize, GEMM_SMEM);
    cudaFuncSetAttribute(gemm_tc<4,0>, cudaFuncAttributeMaxDynamicSharedMemorySize, GEMM_SMEM);

    // ---- weight transpose + split ----
    tsplit_k<<<dim3(Dd/32, Dd/32), 256>>>(W_r, wrh, wrl, Dd, Dd);
    tsplit_k<<<dim3(Dd/32, Dd/32), 256>>>(W_k, wkh, wkl, Dd, Dd);
    tsplit_k<<<dim3(Dd/32, Dd/32), 256>>>(W_v, wvh, wvl, Dd, Dd);
    tsplit_k<<<dim3(Dd/32, Dd/32), 256>>>(W_g, wgh, wgl, Dd, Dd);
    tsplit_k<<<dim3(Dd/32, Dd/32), 256>>>(W_o, woh, wol, Dd, Dd);
    tsplit_k<<<dim3(Dd/32, 256/32), 256>>>(tm_w1, tm1h, tm1l, Dd, E5c);
    tsplit_k<<<dim3(Dd/32, 128/32), 256>>>(td_w1, td1h, td1l, Dd, 64);
    tsplit_k<<<dim3(64/32, Dd/32), 256>>>(td_w2, td2h, td2l, 64, Dd);

    // ---- 1) shift + split(xxx) ----
    prep_k<<<(BT * Dd) / 256, 256>>>(x, prev, x_maa, sx, xh, xl);
    // ---- 2) m = tanh(xxx @ tm_w1)  [8192 x 160, K=2048] ----
    gemm_tc<2,0><<<dim3(2, BT/128), 256, GEMM_SMEM>>>(xh, xl, tm1h, tm1l,
        m, nullptr, nullptr, BT, E5c, Dd, nullptr);
    // ---- 3) mix + 5 lerps (bf16 splits) ----
    mix_k<<<dim3(Dd/256, BT/8), 256>>>(x, sx, m, tm_w2,
        w_maa, k_maa, v_maa, r_maa, g_maa,
        wxh, wxl, kxh, kxl, vxh, vxl, rxh, rxl, gxh, gxl);
    // ---- 4) big GEMMs ----
    dim3 gBig(Dd/128, BT/128);
    gemm_tc<1,0><<<gBig, 256, GEMM_SMEM>>>(rxh, rxl, wrh, wrl, r, nullptr, nullptr, BT, Dd, Dd, nullptr);
    gemm_tc<0,0><<<gBig, 256, GEMM_SMEM>>>(kxh, kxl, wkh, wkl, k, nullptr, nullptr, BT, Dd, Dd, nullptr);
    gemm_tc<0,0><<<gBig, 256, GEMM_SMEM>>>(vxh, vxl, wvh, wvl, v, nullptr, nullptr, BT, Dd, Dd, nullptr);
    gemm_tc<3,0><<<gBig, 256, GEMM_SMEM>>>(gxh, gxl, wgh, wgl, g, nullptr, nullptr, BT, Dd, Dd, nullptr);
    // ---- 5) w path ----
    gemm_tc<2,1><<<dim3(1, BT/128), 256, GEMM_SMEM>>>(wxh, wxl, td1h, td1l,
        nullptr, h1h, h1l, BT, 64, Dd, nullptr);
    gemm_tc<4,0><<<gBig, 256, GEMM_SMEM>>>(h1h, h1l, td2h, td2l,
        w, nullptr, nullptr, BT, Dd, 64, tdec);
    // ---- 6) WKV scan ----
    wkv_k<<<Bb * Hh, 64>>>(r, k, v, w, tfirst, state, att, out_state);
    // ---- 7) groupnorm * ln * g (bf16 splits) ----
    gnorm_k<<<(BT * Hh) / 8, 256>>>(att, g, ln_g, ln_b, gnh, gnl);
    // ---- 8) out = gn @ W_o ----
    gemm_tc<0,0><<<gBig, 256, GEMM_SMEM>>>(gnh, gnl, woh, wol,
        out0, nullptr, nullptr, BT, Dd, Dd, nullptr);
    // ---- 9) x[:, -1] ----
    lastcopy_k<<<(Bb * Dd) / 256, 256>>>(x, out_xlast);
}

// round 5
// speedup vs baseline: 4.0042x; 1.0859x over previous
#include <cuda_runtime.h>
#include <cuda_bf16.h>
#include <math.h>
#include <stdint.h>

#define Bb 4
#define Tt 2048
#define Dd 2048
#define Hh 32
#define HSz 64
#define BT (Bb*Tt)
#define E5c 160

typedef __nv_bfloat16 bf16;

// ====================== device scratch (bss, no alloc) ======================
__device__ float g_sx [BT*Dd];
__device__ float g_m  [BT*E5c];
__device__ float g_r  [BT*Dd];
__device__ float g_k  [BT*Dd];
__device__ float g_v  [BT*Dd];
__device__ float g_g  [BT*Dd];
__device__ float g_w  [BT*Dd];
__device__ float g_att[BT*Dd];

__device__ bf16 g_xh [BT*Dd], g_xl [BT*Dd];
__device__ bf16 g_wxh[BT*Dd], g_wxl[BT*Dd];
__device__ bf16 g_kxh[BT*Dd], g_kxl[BT*Dd];
__device__ bf16 g_vxh[BT*Dd], g_vxl[BT*Dd];
__device__ bf16 g_rxh[BT*Dd], g_rxl[BT*Dd];
__device__ bf16 g_gxh[BT*Dd], g_gxl[BT*Dd];
__device__ bf16 g_gnh[BT*Dd], g_gnl[BT*Dd];
__device__ bf16 g_h1h[BT*64], g_h1l[BT*64];

__device__ bf16 g_wrh[Dd*Dd], g_wrl[Dd*Dd];
__device__ bf16 g_wkh[Dd*Dd], g_wkl[Dd*Dd];
__device__ bf16 g_wvh[Dd*Dd], g_wvl[Dd*Dd];
__device__ bf16 g_wgh[Dd*Dd], g_wgl[Dd*Dd];
__device__ bf16 g_woh[Dd*Dd], g_wol[Dd*Dd];
__device__ bf16 g_tm1h[256*Dd], g_tm1l[256*Dd];
__device__ bf16 g_td1h[128*Dd], g_td1l[128*Dd];
__device__ bf16 g_td2h[Dd*64],  g_td2l[Dd*64];

// ====================== PTX helpers (sm_80-class only) ======================
__device__ __forceinline__ uint32_t smem_u32(const void* p) {
    uint32_t a;
    asm("{ .reg .u64 t; cvta.to.shared.u64 t, %1; cvt.u32.u64 %0, t; }"
        : "=r"(a) : "l"(p));
    return a;
}

#define CP_ASYNC16(dst, src) \
    asm volatile("cp.async.cg.shared.global [%0], [%1], 16;" \
        :: "r"(dst), "l"(src) : "memory")
#define CP_ASYNC8(dst, src) \
    asm volatile("cp.async.ca.shared.global [%0], [%1], 8;" \
        :: "r"(dst), "l"(src) : "memory")
#define CP_COMMIT() asm volatile("cp.async.commit_group;" ::: "memory")
#define CP_WAIT0()  asm volatile("cp.async.wait_group 0;" ::: "memory")
#define CP_WAIT1()  asm volatile("cp.async.wait_group 1;" ::: "memory")

__device__ __forceinline__ void ldsm4(uint32_t* r, uint32_t addr) {
    asm volatile("ldmatrix.sync.aligned.m8n8.x4.shared.b16 {%0,%1,%2,%3},[%4];"
        : "=r"(r[0]), "=r"(r[1]), "=r"(r[2]), "=r"(r[3]) : "r"(addr));
}

__device__ __forceinline__ void mma16816(float* c, const uint32_t* a, const uint32_t* b) {
    asm volatile(
        "mma.sync.aligned.m16n8k16.row.col.f32.bf16.bf16.f32 "
        "{%0,%1,%2,%3},{%4,%5,%6,%7},{%8,%9},{%0,%1,%2,%3};"
        : "+f"(c[0]), "+f"(c[1]), "+f"(c[2]), "+f"(c[3])
        : "r"(a[0]), "r"(a[1]), "r"(a[2]), "r"(a[3]), "r"(b[0]), "r"(b[1]));
}

__device__ __forceinline__ uint32_t swz(uint32_t bo) { return bo ^ ((bo >> 3) & 0x70); }

// ====================== tensor-core GEMM (HMMA, 256x128 tile) ===============
// C[M, Nout] = epi(A[M,K] @ Bt[Npad,K]^T);  K % 64 == 0, M % 256 == 0.
// 3-split: Ah*Bh + Ah*Bl + Al*Bh in fp32 accumulators.

__device__ __forceinline__ float repi(float v, int epi, const float* extra, int n) {
    switch (epi) {
        case 1: return 1.f / (1.f + expf(-v));
        case 2: return tanhf(v);
        case 3: return v / (1.f + expf(-v));
        case 4: return expf(-expf(v + extra[n]));
        default: return v;
    }
}

// async-load rows x 64 bf16 tile into SW128-swizzled smem (256 threads)
template<int ROWS>
__device__ __forceinline__ void load_tile_async(uint32_t sbase,
    const bf16* __restrict__ src, int row0, int k0, int ldK, int tid)
{
#pragma unroll
    for (int i = 0; i < ROWS / 32; i++) {
        int u = i * 256 + tid;
        int row = u >> 3, cc = u & 7;
        uint32_t bo = (uint32_t)(row * 128 + cc * 16);
        CP_ASYNC16(sbase + swz(bo),
                   src + (size_t)(row0 + row) * ldK + k0 + cc * 8);
    }
}

#define ST_SZ 98304u            // Ah 32K + Al 32K + Bh 16K + Bl 16K
#define GEMM_SMEM (2 * ST_SZ)   // 196608

__device__ __forceinline__ void gemm_stage(uint32_t st,
    const bf16* Ah, const bf16* Al, const bf16* Bh, const bf16* Bl,
    int mbase, int nbase, int k0, int K, int tid)
{
    load_tile_async<256>(st +     0, Ah, mbase, k0, K, tid);
    load_tile_async<256>(st + 32768, Al, mbase, k0, K, tid);
    load_tile_async<128>(st + 65536, Bh, nbase, k0, K, tid);
    load_tile_async<128>(st + 81920, Bl, nbase, k0, K, tid);
    CP_COMMIT();
}

__device__ __forceinline__ void gemm_core(
    const bf16* __restrict__ Ah, const bf16* __restrict__ Al,
    const bf16* __restrict__ Bh, const bf16* __restrict__ Bl,
    float* __restrict__ Cf, bf16* __restrict__ Ch, bf16* __restrict__ Cl,
    int Nout, int K, const float* __restrict__ extra, int epi)
{
    extern __shared__ char sm[];
    const uint32_t sb = smem_u32(sm);
    const int tid = threadIdx.x, lane = tid & 31, wid = tid >> 5;
    const int wm = wid >> 1, wn = wid & 1;           // 4 x 2 warp grid, warp tile 64x64
    const int mbase = blockIdx.y * 256, nbase = blockIdx.x * 128;

    float acc[4][8][4];
#pragma unroll
    for (int mf = 0; mf < 4; mf++)
#pragma unroll
        for (int nf = 0; nf < 8; nf++)
#pragma unroll
            for (int q = 0; q < 4; q++) acc[mf][nf][q] = 0.f;

    const int nc = K / 64;
    gemm_stage(sb, Ah, Al, Bh, Bl, mbase, nbase, 0, K, tid);

    const int a_row = (lane & 15);
    const int a_cb  = ((lane >> 4) & 1) * 16;
    const int mat   = lane >> 3;
    const int b_row = (lane & 7) + ((mat >> 1) & 1) * 8;
    const int b_cb  = (mat & 1) * 16;

    for (int c = 0; c < nc; c++) {
        if (c + 1 < nc) {
            gemm_stage(sb + ((c + 1) & 1) * ST_SZ, Ah, Al, Bh, Bl,
                       mbase, nbase, (c + 1) * 64, K, tid);
            CP_WAIT1();
        } else {
            CP_WAIT0();
        }
        __syncthreads();

        const uint32_t base = sb + (c & 1) * ST_SZ;
#pragma unroll
        for (int ks = 0; ks < 4; ks++) {
            uint32_t ah[4][4], al[4][4];
#pragma unroll
            for (int mf = 0; mf < 4; mf++) {
                uint32_t bo = (uint32_t)((wm * 64 + mf * 16 + a_row) * 128 + ks * 32 + a_cb);
                uint32_t sw = swz(bo);
                ldsm4(ah[mf], base + sw);
                ldsm4(al[mf], base + 32768 + sw);
            }
            uint32_t bh[4][4], bl[4][4];
#pragma unroll
            for (int bq = 0; bq < 4; bq++) {
                uint32_t bo = (uint32_t)((wn * 64 + bq * 16 + b_row) * 128 + ks * 32 + b_cb);
                uint32_t sw = swz(bo);
                ldsm4(bh[bq], base + 65536 + sw);
                ldsm4(bl[bq], base + 81920 + sw);
            }
#pragma unroll
            for (int mf = 0; mf < 4; mf++)
#pragma unroll
                for (int bq = 0; bq < 4; bq++) {
                    mma16816(acc[mf][2 * bq],     ah[mf], &bh[bq][0]);
                    mma16816(acc[mf][2 * bq + 1], ah[mf], &bh[bq][2]);
                    mma16816(acc[mf][2 * bq],     ah[mf], &bl[bq][0]);
                    mma16816(acc[mf][2 * bq + 1], ah[mf], &bl[bq][2]);
                    mma16816(acc[mf][2 * bq],     al[mf], &bh[bq][0]);
                    mma16816(acc[mf][2 * bq + 1], al[mf], &bh[bq][2]);
                }
        }
        __syncthreads();
    }

    const int r_in = lane >> 2, c_in = (lane & 3) * 2;
#pragma unroll
    for (int mf = 0; mf < 4; mf++)
#pragma unroll
        for (int nf = 0; nf < 8; nf++) {
            int row0 = mbase + wm * 64 + mf * 16 + r_in;
            int col  = nbase + wn * 64 + nf * 8 + c_in;
            if (col >= Nout) continue;
            float* q = acc[mf][nf];
            float e0 = repi(q[0], epi, extra, col);
            float e1 = repi(q[1], epi, extra, col + 1);
            float e2 = repi(q[2], epi, extra, col);
            float e3 = repi(q[3], epi, extra, col + 1);
            if (Ch == nullptr) {
                *(float2*)(Cf + (size_t)row0 * Nout + col) = make_float2(e0, e1);
                *(float2*)(Cf + (size_t)(row0 + 8) * Nout + col) = make_float2(e2, e3);
            } else {
                size_t o0 = (size_t)row0 * Nout + col;
                size_t o1 = (size_t)(row0 + 8) * Nout + col;
                bf16 h;
                h = __float2bfloat16(e0); Ch[o0]     = h; Cl[o0]     = __float2bfloat16(e0 - __bfloat162float(h));
                h = __float2bfloat16(e1); Ch[o0 + 1] = h; Cl[o0 + 1] = __float2bfloat16(e1 - __bfloat162float(h));
                h = __float2bfloat16(e2); Ch[o1]     = h; Cl[o1]     = __float2bfloat16(e2 - __bfloat162float(h));
                h = __float2bfloat16(e3); Ch[o1 + 1] = h; Cl[o1 + 1] = __float2bfloat16(e3 - __bfloat162float(h));
            }
        }
}

__global__ void __launch_bounds__(256, 1) gemm_one(
    const bf16* __restrict__ Ah, const bf16* __restrict__ Al,
    const bf16* __restrict__ Bh, const bf16* __restrict__ Bl,
    float* __restrict__ Cf, bf16* __restrict__ Ch, bf16* __restrict__ Cl,
    int Nout, int K, const float* __restrict__ extra, int epi)
{
    gemm_core(Ah, Al, Bh, Bl, Cf, Ch, Cl, Nout, K, extra, epi);
}

__global__ void __launch_bounds__(256, 1) gemm_rkvg(
    const bf16* rxh, const bf16* rxl, const bf16* wrh, const bf16* wrl, float* r,
    const bf16* kxh, const bf16* kxl, const bf16* wkh, const bf16* wkl, float* k,
    const bf16* vxh, const bf16* vxl, const bf16* wvh, const bf16* wvl, float* v,
    const bf16* gxh, const bf16* gxl, const bf16* wgh, const bf16* wgl, float* g)
{
    const bf16 *Ah, *Al, *Bh, *Bl; float* C; int epi;
    switch (blockIdx.z) {
        case 0:  Ah = rxh; Al = rxl; Bh = wrh; Bl = wrl; C = r; epi = 1; break;
        case 1:  Ah = kxh; Al = kxl; Bh = wkh; Bl = wkl; C = k; epi = 0; break;
        case 2:  Ah = vxh; Al = vxl; Bh = wvh; Bl = wvl; C = v; epi = 0; break;
        default: Ah = gxh; Al = gxl; Bh = wgh; Bl = wgl; C = g; epi = 3; break;
    }
    gemm_core(Ah, Al, Bh, Bl, C, nullptr, nullptr, Dd, Dd, nullptr, epi);
}

// ====================== weight transpose + bf16 split =======================
__global__ void __launch_bounds__(256) tsplit_k(
    const float* __restrict__ W, bf16* __restrict__ bh,
    bf16* __restrict__ bl, int K, int N)
{
    __shared__ float t[32][33];
    const int k0 = blockIdx.x * 32, n0 = blockIdx.y * 32;
    const int tx = threadIdx.x & 31, ty = threadIdx.x >> 5;
#pragma unroll
    for (int i = 0; i < 4; i++) {
        int kk = ty + i * 8;
        int n = n0 + tx;
        t[kk][tx] = (n < N) ? W[(size_t)(k0 + kk) * N + n] : 0.f;
    }
    __syncthreads();
#pragma unroll
    for (int i = 0; i < 4; i++) {
        int nn = ty + i * 8;
        float v = t[tx][nn];
        bf16 h = __float2bfloat16(v);
        size_t o = (size_t)(n0 + nn) * K + k0 + tx;
        bh[o] = h;
        bl[o] = __float2bfloat16(v - __bfloat162float(h));
    }
}

// ====================== prep: sx + split(xxx) ===============================
__global__ void __launch_bounds__(256) prep_k(
    const float* __restrict__ x, const float* __restrict__ prev,
    const float* __restrict__ xmaa, float* __restrict__ sx,
    bf16* __restrict__ xh, bf16* __restrict__ xl)
{
    size_t i = (size_t)blockIdx.x * 256 + threadIdx.x;
    int d = (int)(i % Dd);
    size_t bt = i / Dd;
    int t = (int)(bt % Tt);
    int b = (int)(bt / Tt);
    float xv = x[i];
    float sh = (t == 0) ? prev[(size_t)b * Dd + d] : x[i - Dd];
    float s = sh - xv;
    sx[i] = s;
    float xxx = fmaf(s, xmaa[d], xv);
    bf16 h = __float2bfloat16(xxx);
    xh[i] = h;
    xl[i] = __float2bfloat16(xxx - __bfloat162float(h));
}

// ====================== mix: 5 lerps, writes bf16 splits ====================
__global__ void __launch_bounds__(256) mix_k(
    const float* __restrict__ x, const float* __restrict__ sx,
    const float* __restrict__ m, const float* __restrict__ tmw2,
    const float* __restrict__ wmaa, const float* __restrict__ kmaa,
    const float* __restrict__ vmaa, const float* __restrict__ rmaa,
    const float* __restrict__ gmaa,
    bf16* __restrict__ wxh, bf16* __restrict__ wxl,
    bf16* __restrict__ kxh, bf16* __restrict__ kxl,
    bf16* __restrict__ vxh, bf16* __restrict__ vxl,
    bf16* __restrict__ rxh, bf16* __restrict__ rxl,
    bf16* __restrict__ gxh, bf16* __restrict__ gxl)
{
    __shared__ float msh[8][E5c];
    __shared__ float tile[32][256];
    const int tid = threadIdx.x;
    const int dbase = blockIdx.x * 256;
    const int tb = blockIdx.y * 8;

    for (int i = tid; i < 8 * E5c; i += 256)
        msh[i / E5c][i % E5c] = m[(size_t)(tb + i / E5c) * E5c + (i % E5c)];

    float acc[8][5];
#pragma unroll
    for (int tok = 0; tok < 8; tok++)
#pragma unroll
        for (int f = 0; f < 5; f++) acc[tok][f] = 0.f;

#pragma unroll
    for (int f = 0; f < 5; f++) {
        __syncthreads();
        for (int e = 0; e < 32; e++)
            tile[e][tid] = tmw2[(size_t)(f * 32 + e) * Dd + dbase + tid];
        __syncthreads();
        for (int e = 0; e < 32; e++) {
            float tv = tile[e][tid];
#pragma unroll
            for (int tok = 0; tok < 8; tok++)
                acc[tok][f] = fmaf(msh[tok][f * 32 + e], tv, acc[tok][f]);
        }
    }

    const int d = dbase + tid;
    const float wm = wmaa[d], km = kmaa[d], vm = vmaa[d], rm = rmaa[d], gm = gmaa[d];
#pragma unroll
    for (int tok = 0; tok < 8; tok++) {
        size_t idx = (size_t)(tb + tok) * Dd + d;
        float xv = x[idx], sv = sx[idx];
        float w_ = fmaf(sv, wm + acc[tok][0], xv);
        float k_ = fmaf(sv, km + acc[tok][1], xv);
        float v_ = fmaf(sv, vm + acc[tok][2], xv);
        float r_ = fmaf(sv, rm + acc[tok][3], xv);
        float g_ = fmaf(sv, gm + acc[tok][4], xv);
        bf16 h;
        h = __float2bfloat16(w_); wxh[idx] = h; wxl[idx] = __float2bfloat16(w_ - __bfloat162float(h));
        h = __float2bfloat16(k_); kxh[idx] = h; kxl[idx] = __float2bfloat16(k_ - __bfloat162float(h));
        h = __float2bfloat16(v_); vxh[idx] = h; vxl[idx] = __float2bfloat16(v_ - __bfloat162float(h));
        h = __float2bfloat16(r_); rxh[idx] = h; rxl[idx] = __float2bfloat16(r_ - __bfloat162float(h));
        h = __float2bfloat16(g_); gxh[idx] = h; gxl[idx] = __float2bfloat16(g_ - __bfloat162float(h));
    }
}

// ====================== WKV scan: 256 thr, cp.async pipelined ===============
// CTA per (b,h). thread = (vcol = tid>>2, kg = tid&3); 16 state elems/thread.
// Blocks of 8 timesteps staged via cp.async triple buffer; shfl-reduce over kg.
__global__ void __launch_bounds__(256) wkv_k(
    const float* __restrict__ r, const float* __restrict__ k,
    const float* __restrict__ v, const float* __restrict__ w,
    const float* __restrict__ u, const float* __restrict__ s0,
    float* __restrict__ att, float* __restrict__ sout)
{
    __shared__ float rs[3][8][64], ksm[3][8][64], wsm[3][8][64], vsm[3][8][64];
    __shared__ float rus[3][8][64], osh[3][8][64], ush[64];

    const int bh = blockIdx.x, b = bh >> 5, h = bh & 31;
    const int tid = threadIdx.x;
    const int vcol = tid >> 2, kg = tid & 3;
    const int st_ = tid >> 5;          // staging row (timestep within block)
    const int si  = (tid & 31) * 2;    // staging col (2 floats)

    const size_t base0 = (size_t)b * Tt * Dd + h * 64;
    const size_t sbase = (size_t)bh * 4096;

    float s[16];
#pragma unroll
    for (int j = 0; j < 16; j++)
        s[j] = s0[sbase + (size_t)(kg * 16 + j) * 64 + vcol];
    if (tid < 64) ush[tid] = u[h * 64 + tid];

    // prologue: stage block 0 into buffer 0
    {
        size_t g = base0 + (size_t)st_ * Dd + si;
        CP_ASYNC8(smem_u32(&rs[0][st_][si]),  r + g);
        CP_ASYNC8(smem_u32(&ksm[0][st_][si]), k + g);
        CP_ASYNC8(smem_u32(&wsm[0][st_][si]), w + g);
        CP_ASYNC8(smem_u32(&vsm[0][st_][si]), v + g);
        CP_COMMIT();
    }

    const int NB = Tt / 8;   // 256
    int buf = 0;
    for (int nb = 0; nb < NB; nb++) {
        buf = nb % 3;
        const int nxt = (nb + 1) % 3;
        if (nb + 1 < NB) {
            size_t g = base0 + (size_t)((nb + 1) * 8 + st_) * Dd + si;
            CP_ASYNC8(smem_u32(&rs[nxt][st_][si]),  r + g);
            CP_ASYNC8(smem_u32(&ksm[nxt][st_][si]), k + g);
            CP_ASYNC8(smem_u32(&wsm[nxt][st_][si]), w + g);
            CP_ASYNC8(smem_u32(&vsm[nxt][st_][si]), v + g);
            CP_COMMIT();
            CP_WAIT1();
        } else {
            CP_WAIT0();
        }
        __syncthreads();   // staged buf visible; prior compute done

        // write previous block's output (coalesced) + compute r*u for this block
        if (nb > 0) {
            const int pb = (nb - 1) % 3;
            *(float2*)&att[base0 + (size_t)((nb - 1) * 8 + st_) * Dd + si] =
                *(const float2*)&osh[pb][st_][si];
        }
        {
            float2 rr = *(const float2*)&rs[buf][st_][si];
            float2 uu = *(const float2*)&ush[si];
            rus[buf][st_][si]     = rr.x * uu.x;
            rus[buf][st_][si + 1] = rr.y * uu.y;
        }
        __syncthreads();

#pragma unroll
        for (int t = 0; t < 8; t++) {
            const float vm = vsm[buf][t][vcol];
            float a = 0.f;
            const float* rp = &rs[buf][t][kg * 16];
            const float* up = &rus[buf][t][kg * 16];
            const float* kp = &ksm[buf][t][kg * 16];
            const float* wp = &wsm[buf][t][kg * 16];
#pragma unroll
            for (int q = 0; q < 4; q++) {
                float4 r4  = *(const float4*)(rp + 4 * q);
                float4 ru4 = *(const float4*)(up + 4 * q);
                float4 k4  = *(const float4*)(kp + 4 * q);
                float4 w4  = *(const float4*)(wp + 4 * q);
                float kv;
                kv = k4.x * vm; a = fmaf(r4.x, s[4*q+0], a); a = fmaf(ru4.x, kv, a); s[4*q+0] = fmaf(s[4*q+0], w4.x, kv);
                kv = k4.y * vm; a = fmaf(r4.y, s[4*q+1], a); a = fmaf(ru4.y, kv, a); s[4*q+1] = fmaf(s[4*q+1], w4.y, kv);
                kv = k4.z * vm; a = fmaf(r4.z, s[4*q+2], a); a = fmaf(ru4.z, kv, a); s[4*q+2] = fmaf(s[4*q+2], w4.z, kv);
                kv = k4.w * vm; a = fmaf(r4.w, s[4*q+3], a); a = fmaf(ru4.w, kv, a); s[4*q+3] = fmaf(s[4*q+3], w4.w, kv);
            }
            a += __shfl_xor_sync(0xffffffffu, a, 1);
            a += __shfl_xor_sync(0xffffffffu, a, 2);
            if (kg == 0) osh[buf][t][vcol] = a;
        }
    }
    __syncthreads();
    *(float2*)&att[base0 + (size_t)((NB - 1) * 8 + st_) * Dd + si] =
        *(const float2*)&osh[buf][st_][si];
#pragma unroll
    for (int j = 0; j < 16; j++)
        sout[sbase + (size_t)(kg * 16 + j) * 64 + vcol] = s[j];
}

// ====================== groupnorm + ln + *g, writes bf16 splits =============
__global__ void __launch_bounds__(256) gnorm_k(
    const float* __restrict__ att, const float* __restrict__ g,
    const float* __restrict__ lng, const float* __restrict__ lnb,
    bf16* __restrict__ oh, bf16* __restrict__ ol)
{
    const int grp = blockIdx.x * 8 + (threadIdx.x >> 5);
    const int lane = threadIdx.x & 31;
    const int bt = grp >> 5;
    const int h = grp & 31;
    size_t base = (size_t)bt * Dd + h * 64;
    float v0 = att[base + lane];
    float v1 = att[base + lane + 32];
    float sum = v0 + v1;
    float sq = v0 * v0 + v1 * v1;
#pragma unroll
    for (int o = 16; o > 0; o >>= 1) {
        sum += __shfl_xor_sync(0xffffffffu, sum, o);
        sq  += __shfl_xor_sync(0xffffffffu, sq, o);
    }
    float mu = sum * (1.f / 64.f);
    float var = sq * (1.f / 64.f) - mu * mu;
    float inv = rsqrtf(var + 1e-5f);
    int li = h * 64 + lane;
    float o0 = fmaf((v0 - mu) * inv, lng[li],      lnb[li])      * g[base + lane];
    float o1 = fmaf((v1 - mu) * inv, lng[li + 32], lnb[li + 32]) * g[base + lane + 32];
    bf16 hh;
    hh = __float2bfloat16(o0); oh[base + lane]      = hh; ol[base + lane]      = __float2bfloat16(o0 - __bfloat162float(hh));
    hh = __float2bfloat16(o1); oh[base + lane + 32] = hh; ol[base + lane + 32] = __float2bfloat16(o1 - __bfloat162float(hh));
}

// ====================== copy x[:, -1, :] ====================================
__global__ void __launch_bounds__(256) lastcopy_k(const float* __restrict__ x,
                                                  float* __restrict__ o)
{
    int i = blockIdx.x * 256 + threadIdx.x;
    int b = i / Dd, d = i % Dd;
    o[i] = x[((size_t)b * Tt + (Tt - 1)) * Dd + d];
}

// ====================== host ================================================
extern "C" void kernel_launch(void* const* d_in, const int* in_sizes, int n_in,
                              void* d_out, int out_size)
{
    const float* x     = (const float*)d_in[0];
    const float* prev  = (const float*)d_in[1];
    const float* state = (const float*)d_in[2];
    const float* x_maa = (const float*)d_in[3];
    const float* w_maa = (const float*)d_in[4];
    const float* k_maa = (const float*)d_in[5];
    const float* v_maa = (const float*)d_in[6];
    const float* r_maa = (const float*)d_in[7];
    const float* g_maa = (const float*)d_in[8];
    const float* tm_w1 = (const float*)d_in[9];
    const float* tm_w2 = (const float*)d_in[10];
    const float* td_w1 = (const float*)d_in[11];
    const float* td_w2 = (const float*)d_in[12];
    const float* tdec  = (const float*)d_in[13];
    const float* tfirst= (const float*)d_in[14];
    const float* W_r   = (const float*)d_in[15];
    const float* W_k   = (const float*)d_in[16];
    const float* W_v   = (const float*)d_in[17];
    const float* W_g   = (const float*)d_in[18];
    const float* W_o   = (const float*)d_in[19];
    const float* ln_g  = (const float*)d_in[20];
    const float* ln_b  = (const float*)d_in[21];

    float *sx, *m, *r, *k, *v, *g, *w, *att;
    cudaGetSymbolAddress((void**)&sx,  g_sx);
    cudaGetSymbolAddress((void**)&m,   g_m);
    cudaGetSymbolAddress((void**)&r,   g_r);
    cudaGetSymbolAddress((void**)&k,   g_k);
    cudaGetSymbolAddress((void**)&v,   g_v);
    cudaGetSymbolAddress((void**)&g,   g_g);
    cudaGetSymbolAddress((void**)&w,   g_w);
    cudaGetSymbolAddress((void**)&att, g_att);

    bf16 *xh, *xl, *wxh, *wxl, *kxh, *kxl, *vxh, *vxl, *rxh, *rxl, *gxh, *gxl;
    bf16 *gnh, *gnl, *h1h, *h1l;
    bf16 *wrh, *wrl, *wkh, *wkl, *wvh, *wvl, *wgh, *wgl, *woh, *wol;
    bf16 *tm1h, *tm1l, *td1h, *td1l, *td2h, *td2l;
    cudaGetSymbolAddress((void**)&xh,  g_xh);  cudaGetSymbolAddress((void**)&xl,  g_xl);
    cudaGetSymbolAddress((void**)&wxh, g_wxh); cudaGetSymbolAddress((void**)&wxl, g_wxl);
    cudaGetSymbolAddress((void**)&kxh, g_kxh); cudaGetSymbolAddress((void**)&kxl, g_kxl);
    cudaGetSymbolAddress((void**)&vxh, g_vxh); cudaGetSymbolAddress((void**)&vxl, g_vxl);
    cudaGetSymbolAddress((void**)&rxh, g_rxh); cudaGetSymbolAddress((void**)&rxl, g_rxl);
    cudaGetSymbolAddress((void**)&gxh, g_gxh); cudaGetSymbolAddress((void**)&gxl, g_gxl);
    cudaGetSymbolAddress((void**)&gnh, g_gnh); cudaGetSymbolAddress((void**)&gnl, g_gnl);
    cudaGetSymbolAddress((void**)&h1h, g_h1h); cudaGetSymbolAddress((void**)&h1l, g_h1l);
    cudaGetSymbolAddress((void**)&wrh, g_wrh); cudaGetSymbolAddress((void**)&wrl, g_wrl);
    cudaGetSymbolAddress((void**)&wkh, g_wkh); cudaGetSymbolAddress((void**)&wkl, g_wkl);
    cudaGetSymbolAddress((void**)&wvh, g_wvh); cudaGetSymbolAddress((void**)&wvl, g_wvl);
    cudaGetSymbolAddress((void**)&wgh, g_wgh); cudaGetSymbolAddress((void**)&wgl, g_wgl);
    cudaGetSymbolAddress((void**)&woh, g_woh); cudaGetSymbolAddress((void**)&wol, g_wol);
    cudaGetSymbolAddress((void**)&tm1h, g_tm1h); cudaGetSymbolAddress((void**)&tm1l, g_tm1l);
    cudaGetSymbolAddress((void**)&td1h, g_td1h); cudaGetSymbolAddress((void**)&td1l, g_td1l);
    cudaGetSymbolAddress((void**)&td2h, g_td2h); cudaGetSymbolAddress((void**)&td2l, g_td2l);

    float* out0 = (float*)d_out;
    float* out_xlast = out0 + (size_t)BT * Dd;
    float* out_state = out_xlast + (size_t)Bb * Dd;

    cudaFuncSetAttribute(gemm_one,  cudaFuncAttributeMaxDynamicSharedMemorySize, GEMM_SMEM);
    cudaFuncSetAttribute(gemm_rkvg, cudaFuncAttributeMaxDynamicSharedMemorySize, GEMM_SMEM);

    // ---- weight transpose + split ----
    tsplit_k<<<dim3(Dd/32, Dd/32), 256>>>(W_r, wrh, wrl, Dd, Dd);
    tsplit_k<<<dim3(Dd/32, Dd/32), 256>>>(W_k, wkh, wkl, Dd, Dd);
    tsplit_k<<<dim3(Dd/32, Dd/32), 256>>>(W_v, wvh, wvl, Dd, Dd);
    tsplit_k<<<dim3(Dd/32, Dd/32), 256>>>(W_g, wgh, wgl, Dd, Dd);
    tsplit_k<<<dim3(Dd/32, Dd/32), 256>>>(W_o, woh, wol, Dd, Dd);
    tsplit_k<<<dim3(Dd/32, 256/32), 256>>>(tm_w1, tm1h, tm1l, Dd, E5c);
    tsplit_k<<<dim3(Dd/32, 128/32), 256>>>(td_w1, td1h, td1l, Dd, 64);
    tsplit_k<<<dim3(64/32, Dd/32), 256>>>(td_w2, td2h, td2l, 64, Dd);

    // ---- 1) shift + split(xxx) ----
    prep_k<<<(BT * Dd) / 256, 256>>>(x, prev, x_maa, sx, xh, xl);
    // ---- 2) m = tanh(xxx @ tm_w1)  [8192 x 160, K=2048] ----
    gemm_one<<<dim3(2, BT/256), 256, GEMM_SMEM>>>(xh, xl, tm1h, tm1l,
        m, nullptr, nullptr, E5c, Dd, nullptr, 2);
    // ---- 3) mix + 5 lerps (bf16 splits) ----
    mix_k<<<dim3(Dd/256, BT/8), 256>>>(x, sx, m, tm_w2,
        w_maa, k_maa, v_maa, r_maa, g_maa,
        wxh, wxl, kxh, kxl, vxh, vxl, rxh, rxl, gxh, gxl);
    // ---- 4) big GEMMs r/k/v/g in one launch ----
    gemm_rkvg<<<dim3(Dd/128, BT/256, 4), 256, GEMM_SMEM>>>(
        rxh, rxl, wrh, wrl, r,
        kxh, kxl, wkh, wkl, k,
        vxh, vxl, wvh, wvl, v,
        gxh, gxl, wgh, wgl, g);
    // ---- 5) w path ----
    gemm_one<<<dim3(1, BT/256), 256, GEMM_SMEM>>>(wxh, wxl, td1h, td1l,
        nullptr, h1h, h1l, 64, Dd, nullptr, 2);
    gemm_one<<<dim3(Dd/128, BT/256), 256, GEMM_SMEM>>>(h1h, h1l, td2h, td2l,
        w, nullptr, nullptr, Dd, 64, tdec, 4);
    // ---- 6) WKV scan ----
    wkv_k<<<Bb * Hh, 256>>>(r, k, v, w, tfirst, state, att, out_state);
    // ---- 7) groupnorm * ln * g (bf16 splits) ----
    gnorm_k<<<(BT * Hh) / 8, 256>>>(att, g, ln_g, ln_b, gnh, gnl);
    // ---- 8) out = gn @ W_o ----
    gemm_one<<<dim3(Dd/128, BT/256), 256, GEMM_SMEM>>>(gnh, gnl, woh, wol,
        out0, nullptr, nullptr, Dd, Dd, nullptr, 0);
    // ---- 9) x[:, -1] ----
    lastcopy_k<<<(Bb * Dd) / 256, 256>>>(x, out_xlast);
}

// round 6
// speedup vs baseline: 4.0235x; 1.0048x over previous
#include <cuda_runtime.h>
#include <cuda_bf16.h>
#include <math.h>
#include <stdint.h>

#define Bb 4
#define Tt 2048
#define Dd 2048
#define Hh 32
#define HSz 64
#define BT (Bb*Tt)
#define E5c 160

typedef __nv_bfloat16 bf16;

// ====================== device scratch (bss, no alloc) ======================
__device__ float g_m  [BT*E5c];
__device__ float g_r  [BT*Dd];
__device__ float g_k  [BT*Dd];
__device__ float g_v  [BT*Dd];
__device__ float g_g  [BT*Dd];
__device__ float g_w  [BT*Dd];
__device__ float g_att[BT*Dd];

__device__ bf16 g_xh [BT*Dd], g_xl [BT*Dd];
__device__ bf16 g_wxh[BT*Dd], g_wxl[BT*Dd];
__device__ bf16 g_kxh[BT*Dd], g_kxl[BT*Dd];
__device__ bf16 g_vxh[BT*Dd], g_vxl[BT*Dd];
__device__ bf16 g_rxh[BT*Dd], g_rxl[BT*Dd];
__device__ bf16 g_gxh[BT*Dd], g_gxl[BT*Dd];
__device__ bf16 g_gnh[BT*Dd], g_gnl[BT*Dd];
__device__ bf16 g_h1h[BT*64], g_h1l[BT*64];

__device__ bf16 g_wrh[Dd*Dd], g_wrl[Dd*Dd];
__device__ bf16 g_wkh[Dd*Dd], g_wkl[Dd*Dd];
__device__ bf16 g_wvh[Dd*Dd], g_wvl[Dd*Dd];
__device__ bf16 g_wgh[Dd*Dd], g_wgl[Dd*Dd];
__device__ bf16 g_woh[Dd*Dd], g_wol[Dd*Dd];
__device__ bf16 g_tm1h[256*Dd], g_tm1l[256*Dd];
__device__ bf16 g_td1h[128*Dd], g_td1l[128*Dd];
__device__ bf16 g_td2h[Dd*64],  g_td2l[Dd*64];

// ====================== PTX helpers (sm_80-class only) ======================
__device__ __forceinline__ uint32_t smem_u32(const void* p) {
    uint32_t a;
    asm("{ .reg .u64 t; cvta.to.shared.u64 t, %1; cvt.u32.u64 %0, t; }"
        : "=r"(a) : "l"(p));
    return a;
}

#define CP_ASYNC16(dst, src) \
    asm volatile("cp.async.cg.shared.global [%0], [%1], 16;" \
        :: "r"(dst), "l"(src) : "memory")
#define CP_ASYNC8(dst, src) \
    asm volatile("cp.async.ca.shared.global [%0], [%1], 8;" \
        :: "r"(dst), "l"(src) : "memory")
#define CP_COMMIT() asm volatile("cp.async.commit_group;" ::: "memory")
#define CP_WAIT0()  asm volatile("cp.async.wait_group 0;" ::: "memory")
#define CP_WAIT1()  asm volatile("cp.async.wait_group 1;" ::: "memory")

__device__ __forceinline__ void ldsm4(uint32_t* r, uint32_t addr) {
    asm volatile("ldmatrix.sync.aligned.m8n8.x4.shared.b16 {%0,%1,%2,%3},[%4];"
        : "=r"(r[0]), "=r"(r[1]), "=r"(r[2]), "=r"(r[3]) : "r"(addr));
}

__device__ __forceinline__ void mma16816(float* c, const uint32_t* a, const uint32_t* b) {
    asm volatile(
        "mma.sync.aligned.m16n8k16.row.col.f32.bf16.bf16.f32 "
        "{%0,%1,%2,%3},{%4,%5,%6,%7},{%8,%9},{%0,%1,%2,%3};"
        : "+f"(c[0]), "+f"(c[1]), "+f"(c[2]), "+f"(c[3])
        : "r"(a[0]), "r"(a[1]), "r"(a[2]), "r"(a[3]), "r"(b[0]), "r"(b[1]));
}

__device__ __forceinline__ uint32_t swz(uint32_t bo) { return bo ^ ((bo >> 3) & 0x70); }

// ====================== tensor-core GEMM (HMMA, 256x128 tile) ===============
__device__ __forceinline__ float repi(float v, int epi, const float* extra, int n) {
    switch (epi) {
        case 1: return 1.f / (1.f + expf(-v));
        case 2: return tanhf(v);
        case 3: return v / (1.f + expf(-v));
        case 4: return expf(-expf(v + extra[n]));
        default: return v;
    }
}

template<int ROWS>
__device__ __forceinline__ void load_tile_async(uint32_t sbase,
    const bf16* __restrict__ src, int row0, int k0, int ldK, int tid)
{
#pragma unroll
    for (int i = 0; i < ROWS / 32; i++) {
        int u = i * 256 + tid;
        int row = u >> 3, cc = u & 7;
        uint32_t bo = (uint32_t)(row * 128 + cc * 16);
        CP_ASYNC16(sbase + swz(bo),
                   src + (size_t)(row0 + row) * ldK + k0 + cc * 8);
    }
}

#define ST_SZ 98304u            // Ah 32K + Al 32K + Bh 16K + Bl 16K
#define GEMM_SMEM (2 * ST_SZ)   // 196608

__device__ __forceinline__ void gemm_stage(uint32_t st,
    const bf16* Ah, const bf16* Al, const bf16* Bh, const bf16* Bl,
    int mbase, int nbase, int k0, int K, int tid)
{
    load_tile_async<256>(st +     0, Ah, mbase, k0, K, tid);
    load_tile_async<256>(st + 32768, Al, mbase, k0, K, tid);
    load_tile_async<128>(st + 65536, Bh, nbase, k0, K, tid);
    load_tile_async<128>(st + 81920, Bl, nbase, k0, K, tid);
    CP_COMMIT();
}

__device__ __forceinline__ void gemm_core(
    const bf16* __restrict__ Ah, const bf16* __restrict__ Al,
    const bf16* __restrict__ Bh, const bf16* __restrict__ Bl,
    float* __restrict__ Cf, bf16* __restrict__ Ch, bf16* __restrict__ Cl,
    int Nout, int K, const float* __restrict__ extra, int epi)
{
    extern __shared__ char sm[];
    const uint32_t sb = smem_u32(sm);
    const int tid = threadIdx.x, lane = tid & 31, wid = tid >> 5;
    const int wm = wid >> 1, wn = wid & 1;           // 4 x 2 warp grid, warp tile 64x64
    const int mbase = blockIdx.y * 256, nbase = blockIdx.x * 128;

    float acc[4][8][4];
#pragma unroll
    for (int mf = 0; mf < 4; mf++)
#pragma unroll
        for (int nf = 0; nf < 8; nf++)
#pragma unroll
            for (int q = 0; q < 4; q++) acc[mf][nf][q] = 0.f;

    const int nc = K / 64;
    gemm_stage(sb, Ah, Al, Bh, Bl, mbase, nbase, 0, K, tid);

    const int a_row = (lane & 15);
    const int a_cb  = ((lane >> 4) & 1) * 16;
    const int mat   = lane >> 3;
    const int b_row = (lane & 7) + ((mat >> 1) & 1) * 8;
    const int b_cb  = (mat & 1) * 16;

    for (int c = 0; c < nc; c++) {
        if (c + 1 < nc) {
            gemm_stage(sb + ((c + 1) & 1) * ST_SZ, Ah, Al, Bh, Bl,
                       mbase, nbase, (c + 1) * 64, K, tid);
            CP_WAIT1();
        } else {
            CP_WAIT0();
        }
        __syncthreads();

        const uint32_t base = sb + (c & 1) * ST_SZ;
#pragma unroll
        for (int ks = 0; ks < 4; ks++) {
            uint32_t ah[4][4], al[4][4];
#pragma unroll
            for (int mf = 0; mf < 4; mf++) {
                uint32_t bo = (uint32_t)((wm * 64 + mf * 16 + a_row) * 128 + ks * 32 + a_cb);
                uint32_t sw = swz(bo);
                ldsm4(ah[mf], base + sw);
                ldsm4(al[mf], base + 32768 + sw);
            }
            uint32_t bh[4][4], bl[4][4];
#pragma unroll
            for (int bq = 0; bq < 4; bq++) {
                uint32_t bo = (uint32_t)((wn * 64 + bq * 16 + b_row) * 128 + ks * 32 + b_cb);
                uint32_t sw = swz(bo);
                ldsm4(bh[bq], base + 65536 + sw);
                ldsm4(bl[bq], base + 81920 + sw);
            }
            // 3 passes: same-accumulator reuse distance = 32 MMAs (kills RAW stalls)
#pragma unroll
            for (int mf = 0; mf < 4; mf++)
#pragma unroll
                for (int bq = 0; bq < 4; bq++) {
                    mma16816(acc[mf][2 * bq],     ah[mf], &bh[bq][0]);
                    mma16816(acc[mf][2 * bq + 1], ah[mf], &bh[bq][2]);
                }
#pragma unroll
            for (int mf = 0; mf < 4; mf++)
#pragma unroll
                for (int bq = 0; bq < 4; bq++) {
                    mma16816(acc[mf][2 * bq],     ah[mf], &bl[bq][0]);
                    mma16816(acc[mf][2 * bq + 1], ah[mf], &bl[bq][2]);
                }
#pragma unroll
            for (int mf = 0; mf < 4; mf++)
#pragma unroll
                for (int bq = 0; bq < 4; bq++) {
                    mma16816(acc[mf][2 * bq],     al[mf], &bh[bq][0]);
                    mma16816(acc[mf][2 * bq + 1], al[mf], &bh[bq][2]);
                }
        }
        __syncthreads();
    }

    const int r_in = lane >> 2, c_in = (lane & 3) * 2;
#pragma unroll
    for (int mf = 0; mf < 4; mf++)
#pragma unroll
        for (int nf = 0; nf < 8; nf++) {
            int row0 = mbase + wm * 64 + mf * 16 + r_in;
            int col  = nbase + wn * 64 + nf * 8 + c_in;
            if (col >= Nout) continue;
            float* q = acc[mf][nf];
            float e0 = repi(q[0], epi, extra, col);
            float e1 = repi(q[1], epi, extra, col + 1);
            float e2 = repi(q[2], epi, extra, col);
            float e3 = repi(q[3], epi, extra, col + 1);
            if (Ch == nullptr) {
                *(float2*)(Cf + (size_t)row0 * Nout + col) = make_float2(e0, e1);
                *(float2*)(Cf + (size_t)(row0 + 8) * Nout + col) = make_float2(e2, e3);
            } else {
                size_t o0 = (size_t)row0 * Nout + col;
                size_t o1 = (size_t)(row0 + 8) * Nout + col;
                bf16 h;
                h = __float2bfloat16(e0); Ch[o0]     = h; Cl[o0]     = __float2bfloat16(e0 - __bfloat162float(h));
                h = __float2bfloat16(e1); Ch[o0 + 1] = h; Cl[o0 + 1] = __float2bfloat16(e1 - __bfloat162float(h));
                h = __float2bfloat16(e2); Ch[o1]     = h; Cl[o1]     = __float2bfloat16(e2 - __bfloat162float(h));
                h = __float2bfloat16(e3); Ch[o1 + 1] = h; Cl[o1 + 1] = __float2bfloat16(e3 - __bfloat162float(h));
            }
        }
}

__global__ void __launch_bounds__(256, 1) gemm_one(
    const bf16* __restrict__ Ah, const bf16* __restrict__ Al,
    const bf16* __restrict__ Bh, const bf16* __restrict__ Bl,
    float* __restrict__ Cf, bf16* __restrict__ Ch, bf16* __restrict__ Cl,
    int Nout, int K, const float* __restrict__ extra, int epi)
{
    gemm_core(Ah, Al, Bh, Bl, Cf, Ch, Cl, Nout, K, extra, epi);
}

__global__ void __launch_bounds__(256, 1) gemm_rkvg(
    const bf16* rxh, const bf16* rxl, const bf16* wrh, const bf16* wrl, float* r,
    const bf16* kxh, const bf16* kxl, const bf16* wkh, const bf16* wkl, float* k,
    const bf16* vxh, const bf16* vxl, const bf16* wvh, const bf16* wvl, float* v,
    const bf16* gxh, const bf16* gxl, const bf16* wgh, const bf16* wgl, float* g)
{
    const bf16 *Ah, *Al, *Bh, *Bl; float* C; int epi;
    switch (blockIdx.z) {
        case 0:  Ah = rxh; Al = rxl; Bh = wrh; Bl = wrl; C = r; epi = 1; break;
        case 1:  Ah = kxh; Al = kxl; Bh = wkh; Bl = wkl; C = k; epi = 0; break;
        case 2:  Ah = vxh; Al = vxl; Bh = wvh; Bl = wvl; C = v; epi = 0; break;
        default: Ah = gxh; Al = gxl; Bh = wgh; Bl = wgl; C = g; epi = 3; break;
    }
    gemm_core(Ah, Al, Bh, Bl, C, nullptr, nullptr, Dd, Dd, nullptr, epi);
}

// ====================== all weight transposes + bf16 splits in ONE launch ===
struct TsArgs {
    const float* src[8];
    bf16* bh[8];
    bf16* bl[8];
    int K[8], N[8], gx[8], gy[8];
};

__global__ void __launch_bounds__(256) tsplit_all(TsArgs a)
{
    const int z = blockIdx.z;
    if ((int)blockIdx.x >= a.gx[z] || (int)blockIdx.y >= a.gy[z]) return;
    const float* __restrict__ W = a.src[z];
    bf16* __restrict__ bh = a.bh[z];
    bf16* __restrict__ bl = a.bl[z];
    const int K = a.K[z], N = a.N[z];

    __shared__ float t[32][33];
    const int k0 = blockIdx.x * 32, n0 = blockIdx.y * 32;
    const int tx = threadIdx.x & 31, ty = threadIdx.x >> 5;
#pragma unroll
    for (int i = 0; i < 4; i++) {
        int kk = ty + i * 8;
        int n = n0 + tx;
        t[kk][tx] = (n < N) ? W[(size_t)(k0 + kk) * N + n] : 0.f;
    }
    __syncthreads();
#pragma unroll
    for (int i = 0; i < 4; i++) {
        int nn = ty + i * 8;
        float v = t[tx][nn];
        bf16 h = __float2bfloat16(v);
        size_t o = (size_t)(n0 + nn) * K + k0 + tx;
        bh[o] = h;
        bl[o] = __float2bfloat16(v - __bfloat162float(h));
    }
}

// ====================== prep: split(xxx) ====================================
__global__ void __launch_bounds__(256) prep_k(
    const float* __restrict__ x, const float* __restrict__ prev,
    const float* __restrict__ xmaa,
    bf16* __restrict__ xh, bf16* __restrict__ xl)
{
    size_t i = (size_t)blockIdx.x * 256 + threadIdx.x;
    int d = (int)(i % Dd);
    size_t bt = i / Dd;
    int t = (int)(bt % Tt);
    int b = (int)(bt / Tt);
    float xv = x[i];
    float sh = (t == 0) ? prev[(size_t)b * Dd + d] : x[i - Dd];
    float s = sh - xv;
    float xxx = fmaf(s, xmaa[d], xv);
    bf16 h = __float2bfloat16(xxx);
    xh[i] = h;
    xl[i] = __float2bfloat16(xxx - __bfloat162float(h));
}

// ====================== mix: 5 lerps, recompute sx, write bf16 splits =======
__global__ void __launch_bounds__(256) mix_k(
    const float* __restrict__ x, const float* __restrict__ prev,
    const float* __restrict__ m, const float* __restrict__ tmw2,
    const float* __restrict__ wmaa, const float* __restrict__ kmaa,
    const float* __restrict__ vmaa, const float* __restrict__ rmaa,
    const float* __restrict__ gmaa,
    bf16* __restrict__ wxh, bf16* __restrict__ wxl,
    bf16* __restrict__ kxh, bf16* __restrict__ kxl,
    bf16* __restrict__ vxh, bf16* __restrict__ vxl,
    bf16* __restrict__ rxh, bf16* __restrict__ rxl,
    bf16* __restrict__ gxh, bf16* __restrict__ gxl)
{
    __shared__ float msh[8][E5c];
    __shared__ float tile[32][256];
    const int tid = threadIdx.x;
    const int dbase = blockIdx.x * 256;
    const int tb = blockIdx.y * 8;

    for (int i = tid; i < 8 * E5c; i += 256)
        msh[i / E5c][i % E5c] = m[(size_t)(tb + i / E5c) * E5c + (i % E5c)];

    float acc[8][5];
#pragma unroll
    for (int tok = 0; tok < 8; tok++)
#pragma unroll
        for (int f = 0; f < 5; f++) acc[tok][f] = 0.f;

#pragma unroll
    for (int f = 0; f < 5; f++) {
        __syncthreads();
        for (int e = 0; e < 32; e++)
            tile[e][tid] = tmw2[(size_t)(f * 32 + e) * Dd + dbase + tid];
        __syncthreads();
        for (int e = 0; e < 32; e++) {
            float tv = tile[e][tid];
#pragma unroll
            for (int tok = 0; tok < 8; tok++)
                acc[tok][f] = fmaf(msh[tok][f * 32 + e], tv, acc[tok][f]);
        }
    }

    const int d = dbase + tid;
    const float wm = wmaa[d], km = kmaa[d], vm = vmaa[d], rm = rmaa[d], gm = gmaa[d];
#pragma unroll
    for (int tok = 0; tok < 8; tok++) {
        int bt = tb + tok;
        int t = bt & (Tt - 1), b = bt >> 11;
        size_t idx = (size_t)bt * Dd + d;
        float xv = x[idx];
        float sh = (t == 0) ? prev[(size_t)b * Dd + d] : x[idx - Dd];
        float sv = sh - xv;
        float w_ = fmaf(sv, wm + acc[tok][0], xv);
        float k_ = fmaf(sv, km + acc[tok][1], xv);
        float v_ = fmaf(sv, vm + acc[tok][2], xv);
        float r_ = fmaf(sv, rm + acc[tok][3], xv);
        float g_ = fmaf(sv, gm + acc[tok][4], xv);
        bf16 h;
        h = __float2bfloat16(w_); wxh[idx] = h; wxl[idx] = __float2bfloat16(w_ - __bfloat162float(h));
        h = __float2bfloat16(k_); kxh[idx] = h; kxl[idx] = __float2bfloat16(k_ - __bfloat162float(h));
        h = __float2bfloat16(v_); vxh[idx] = h; vxl[idx] = __float2bfloat16(v_ - __bfloat162float(h));
        h = __float2bfloat16(r_); rxh[idx] = h; rxl[idx] = __float2bfloat16(r_ - __bfloat162float(h));
        h = __float2bfloat16(g_); gxh[idx] = h; gxl[idx] = __float2bfloat16(g_ - __bfloat162float(h));
    }
}

// ====================== WKV scan: 256 thr, cp.async pipelined ===============
__global__ void __launch_bounds__(256) wkv_k(
    const float* __restrict__ r, const float* __restrict__ k,
    const float* __restrict__ v, const float* __restrict__ w,
    const float* __restrict__ u, const float* __restrict__ s0,
    float* __restrict__ att, float* __restrict__ sout)
{
    __shared__ float rs[3][8][64], ksm[3][8][64], wsm[3][8][64], vsm[3][8][64];
    __shared__ float rus[3][8][64], osh[3][8][64], ush[64];

    const int bh = blockIdx.x, b = bh >> 5, h = bh & 31;
    const int tid = threadIdx.x;
    const int vcol = tid >> 2, kg = tid & 3;
    const int st_ = tid >> 5;
    const int si  = (tid & 31) * 2;

    const size_t base0 = (size_t)b * Tt * Dd + h * 64;
    const size_t sbase = (size_t)bh * 4096;

    float s[16];
#pragma unroll
    for (int j = 0; j < 16; j++)
        s[j] = s0[sbase + (size_t)(kg * 16 + j) * 64 + vcol];
    if (tid < 64) ush[tid] = u[h * 64 + tid];

    {
        size_t g = base0 + (size_t)st_ * Dd + si;
        CP_ASYNC8(smem_u32(&rs[0][st_][si]),  r + g);
        CP_ASYNC8(smem_u32(&ksm[0][st_][si]), k + g);
        CP_ASYNC8(smem_u32(&wsm[0][st_][si]), w + g);
        CP_ASYNC8(smem_u32(&vsm[0][st_][si]), v + g);
        CP_COMMIT();
    }

    const int NB = Tt / 8;
    int buf = 0;
    for (int nb = 0; nb < NB; nb++) {
        buf = nb % 3;
        const int nxt = (nb + 1) % 3;
        if (nb + 1 < NB) {
            size_t g = base0 + (size_t)((nb + 1) * 8 + st_) * Dd + si;
            CP_ASYNC8(smem_u32(&rs[nxt][st_][si]),  r + g);
            CP_ASYNC8(smem_u32(&ksm[nxt][st_][si]), k + g);
            CP_ASYNC8(smem_u32(&wsm[nxt][st_][si]), w + g);
            CP_ASYNC8(smem_u32(&vsm[nxt][st_][si]), v + g);
            CP_COMMIT();
            CP_WAIT1();
        } else {
            CP_WAIT0();
        }
        __syncthreads();

        if (nb > 0) {
            const int pb = (nb - 1) % 3;
            *(float2*)&att[base0 + (size_t)((nb - 1) * 8 + st_) * Dd + si] =
                *(const float2*)&osh[pb][st_][si];
        }
        {
            float2 rr = *(const float2*)&rs[buf][st_][si];
            float2 uu = *(const float2*)&ush[si];
            rus[buf][st_][si]     = rr.x * uu.x;
            rus[buf][st_][si + 1] = rr.y * uu.y;
        }
        __syncthreads();

#pragma unroll
        for (int t = 0; t < 8; t++) {
            const float vm = vsm[buf][t][vcol];
            float a = 0.f;
            const float* rp = &rs[buf][t][kg * 16];
            const float* up = &rus[buf][t][kg * 16];
            const float* kp = &ksm[buf][t][kg * 16];
            const float* wp = &wsm[buf][t][kg * 16];
#pragma unroll
            for (int q = 0; q < 4; q++) {
                float4 r4  = *(const float4*)(rp + 4 * q);
                float4 ru4 = *(const float4*)(up + 4 * q);
                float4 k4  = *(const float4*)(kp + 4 * q);
                float4 w4  = *(const float4*)(wp + 4 * q);
                float kv;
                kv = k4.x * vm; a = fmaf(r4.x, s[4*q+0], a); a = fmaf(ru4.x, kv, a); s[4*q+0] = fmaf(s[4*q+0], w4.x, kv);
                kv = k4.y * vm; a = fmaf(r4.y, s[4*q+1], a); a = fmaf(ru4.y, kv, a); s[4*q+1] = fmaf(s[4*q+1], w4.y, kv);
                kv = k4.z * vm; a = fmaf(r4.z, s[4*q+2], a); a = fmaf(ru4.z, kv, a); s[4*q+2] = fmaf(s[4*q+2], w4.z, kv);
                kv = k4.w * vm; a = fmaf(r4.w, s[4*q+3], a); a = fmaf(ru4.w, kv, a); s[4*q+3] = fmaf(s[4*q+3], w4.w, kv);
            }
            a += __shfl_xor_sync(0xffffffffu, a, 1);
            a += __shfl_xor_sync(0xffffffffu, a, 2);
            if (kg == 0) osh[buf][t][vcol] = a;
        }
    }
    __syncthreads();
    *(float2*)&att[base0 + (size_t)((NB - 1) * 8 + st_) * Dd + si] =
        *(const float2*)&osh[buf][st_][si];
#pragma unroll
    for (int j = 0; j < 16; j++)
        sout[sbase + (size_t)(kg * 16 + j) * 64 + vcol] = s[j];
}

// ====================== groupnorm + ln + *g, writes bf16 splits =============
__global__ void __launch_bounds__(256) gnorm_k(
    const float* __restrict__ att, const float* __restrict__ g,
    const float* __restrict__ lng, const float* __restrict__ lnb,
    bf16* __restrict__ oh, bf16* __restrict__ ol)
{
    const int grp = blockIdx.x * 8 + (threadIdx.x >> 5);
    const int lane = threadIdx.x & 31;
    const int bt = grp >> 5;
    const int h = grp & 31;
    size_t base = (size_t)bt * Dd + h * 64;
    float v0 = att[base + lane];
    float v1 = att[base + lane + 32];
    float sum = v0 + v1;
    float sq = v0 * v0 + v1 * v1;
#pragma unroll
    for (int o = 16; o > 0; o >>= 1) {
        sum += __shfl_xor_sync(0xffffffffu, sum, o);
        sq  += __shfl_xor_sync(0xffffffffu, sq, o);
    }
    float mu = sum * (1.f / 64.f);
    float var = sq * (1.f / 64.f) - mu * mu;
    float inv = rsqrtf(var + 1e-5f);
    int li = h * 64 + lane;
    float o0 = fmaf((v0 - mu) * inv, lng[li],      lnb[li])      * g[base + lane];
    float o1 = fmaf((v1 - mu) * inv, lng[li + 32], lnb[li + 32]) * g[base + lane + 32];
    bf16 hh;
    hh = __float2bfloat16(o0); oh[base + lane]      = hh; ol[base + lane]      = __float2bfloat16(o0 - __bfloat162float(hh));
    hh = __float2bfloat16(o1); oh[base + lane + 32] = hh; ol[base + lane + 32] = __float2bfloat16(o1 - __bfloat162float(hh));
}

// ====================== copy x[:, -1, :] ====================================
__global__ void __launch_bounds__(256) lastcopy_k(const float* __restrict__ x,
                                                  float* __restrict__ o)
{
    int i = blockIdx.x * 256 + threadIdx.x;
    int b = i / Dd, d = i % Dd;
    o[i] = x[((size_t)b * Tt + (Tt - 1)) * Dd + d];
}

// ====================== host ================================================
extern "C" void kernel_launch(void* const* d_in, const int* in_sizes, int n_in,
                              void* d_out, int out_size)
{
    const float* x     = (const float*)d_in[0];
    const float* prev  = (const float*)d_in[1];
    const float* state = (const float*)d_in[2];
    const float* x_maa = (const float*)d_in[3];
    const float* w_maa = (const float*)d_in[4];
    const float* k_maa = (const float*)d_in[5];
    const float* v_maa = (const float*)d_in[6];
    const float* r_maa = (const float*)d_in[7];
    const float* g_maa = (const float*)d_in[8];
    const float* tm_w1 = (const float*)d_in[9];
    const float* tm_w2 = (const float*)d_in[10];
    const float* td_w1 = (const float*)d_in[11];
    const float* td_w2 = (const float*)d_in[12];
    const float* tdec  = (const float*)d_in[13];
    const float* tfirst= (const float*)d_in[14];
    const float* W_r   = (const float*)d_in[15];
    const float* W_k   = (const float*)d_in[16];
    const float* W_v   = (const float*)d_in[17];
    const float* W_g   = (const float*)d_in[18];
    const float* W_o   = (const float*)d_in[19];
    const float* ln_g  = (const float*)d_in[20];
    const float* ln_b  = (const float*)d_in[21];

    float *m, *r, *k, *v, *g, *w, *att;
    cudaGetSymbolAddress((void**)&m,   g_m);
    cudaGetSymbolAddress((void**)&r,   g_r);
    cudaGetSymbolAddress((void**)&k,   g_k);
    cudaGetSymbolAddress((void**)&v,   g_v);
    cudaGetSymbolAddress((void**)&g,   g_g);
    cudaGetSymbolAddress((void**)&w,   g_w);
    cudaGetSymbolAddress((void**)&att, g_att);

    bf16 *xh, *xl, *wxh, *wxl, *kxh, *kxl, *vxh, *vxl, *rxh, *rxl, *gxh, *gxl;
    bf16 *gnh, *gnl, *h1h, *h1l;
    bf16 *wrh, *wrl, *wkh, *wkl, *wvh, *wvl, *wgh, *wgl, *woh, *wol;
    bf16 *tm1h, *tm1l, *td1h, *td1l, *td2h, *td2l;
    cudaGetSymbolAddress((void**)&xh,  g_xh);  cudaGetSymbolAddress((void**)&xl,  g_xl);
    cudaGetSymbolAddress((void**)&wxh, g_wxh); cudaGetSymbolAddress((void**)&wxl, g_wxl);
    cudaGetSymbolAddress((void**)&kxh, g_kxh); cudaGetSymbolAddress((void**)&kxl, g_kxl);
    cudaGetSymbolAddress((void**)&vxh, g_vxh); cudaGetSymbolAddress((void**)&vxl, g_vxl);
    cudaGetSymbolAddress((void**)&rxh, g_rxh); cudaGetSymbolAddress((void**)&rxl, g_rxl);
    cudaGetSymbolAddress((void**)&gxh, g_gxh); cudaGetSymbolAddress((void**)&gxl, g_gxl);
    cudaGetSymbolAddress((void**)&gnh, g_gnh); cudaGetSymbolAddress((void**)&gnl, g_gnl);
    cudaGetSymbolAddress((void**)&h1h, g_h1h); cudaGetSymbolAddress((void**)&h1l, g_h1l);
    cudaGetSymbolAddress((void**)&wrh, g_wrh); cudaGetSymbolAddress((void**)&wrl, g_wrl);
    cudaGetSymbolAddress((void**)&wkh, g_wkh); cudaGetSymbolAddress((void**)&wkl, g_wkl);
    cudaGetSymbolAddress((void**)&wvh, g_wvh); cudaGetSymbolAddress((void**)&wvl, g_wvl);
    cudaGetSymbolAddress((void**)&wgh, g_wgh); cudaGetSymbolAddress((void**)&wgl, g_wgl);
    cudaGetSymbolAddress((void**)&woh, g_woh); cudaGetSymbolAddress((void**)&wol, g_wol);
    cudaGetSymbolAddress((void**)&tm1h, g_tm1h); cudaGetSymbolAddress((void**)&tm1l, g_tm1l);
    cudaGetSymbolAddress((void**)&td1h, g_td1h); cudaGetSymbolAddress((void**)&td1l, g_td1l);
    cudaGetSymbolAddress((void**)&td2h, g_td2h); cudaGetSymbolAddress((void**)&td2l, g_td2l);

    float* out0 = (float*)d_out;
    float* out_xlast = out0 + (size_t)BT * Dd;
    float* out_state = out_xlast + (size_t)Bb * Dd;

    cudaFuncSetAttribute(gemm_one,  cudaFuncAttributeMaxDynamicSharedMemorySize, GEMM_SMEM);
    cudaFuncSetAttribute(gemm_rkvg, cudaFuncAttributeMaxDynamicSharedMemorySize, GEMM_SMEM);

    // ---- [0] all 8 weight transposes+splits in one launch ----
    TsArgs ta;
    ta.src[0]=W_r;  ta.bh[0]=wrh;  ta.bl[0]=wrl;  ta.K[0]=Dd; ta.N[0]=Dd;  ta.gx[0]=64; ta.gy[0]=64;
    ta.src[1]=W_k;  ta.bh[1]=wkh;  ta.bl[1]=wkl;  ta.K[1]=Dd; ta.N[1]=Dd;  ta.gx[1]=64; ta.gy[1]=64;
    ta.src[2]=W_v;  ta.bh[2]=wvh;  ta.bl[2]=wvl;  ta.K[2]=Dd; ta.N[2]=Dd;  ta.gx[2]=64; ta.gy[2]=64;
    ta.src[3]=W_g;  ta.bh[3]=wgh;  ta.bl[3]=wgl;  ta.K[3]=Dd; ta.N[3]=Dd;  ta.gx[3]=64; ta.gy[3]=64;
    ta.src[4]=W_o;  ta.bh[4]=woh;  ta.bl[4]=wol;  ta.K[4]=Dd; ta.N[4]=Dd;  ta.gx[4]=64; ta.gy[4]=64;
    ta.src[5]=tm_w1;ta.bh[5]=tm1h; ta.bl[5]=tm1l; ta.K[5]=Dd; ta.N[5]=E5c; ta.gx[5]=64; ta.gy[5]=8;
    ta.src[6]=td_w1;ta.bh[6]=td1h; ta.bl[6]=td1l; ta.K[6]=Dd; ta.N[6]=64;  ta.gx[6]=64; ta.gy[6]=4;
    ta.src[7]=td_w2;ta.bh[7]=td2h; ta.bl[7]=td2l; ta.K[7]=64; ta.N[7]=Dd;  ta.gx[7]=2;  ta.gy[7]=64;
    tsplit_all<<<dim3(64, 64, 8), 256>>>(ta);

    // ---- [1] shift + split(xxx) ----
    prep_k<<<(BT * Dd) / 256, 256>>>(x, prev, x_maa, xh, xl);
    // ---- [2] m = tanh(xxx @ tm_w1) ----
    gemm_one<<<dim3(2, BT/256), 256, GEMM_SMEM>>>(xh, xl, tm1h, tm1l,
        m, nullptr, nullptr, E5c, Dd, nullptr, 2);
    // ---- [3] mix + 5 lerps ----
    mix_k<<<dim3(Dd/256, BT/8), 256>>>(x, prev, m, tm_w2,
        w_maa, k_maa, v_maa, r_maa, g_maa,
        wxh, wxl, kxh, kxl, vxh, vxl, rxh, rxl, gxh, gxl);
    // ---- [4] x[:, -1] (independent; placed here so ncu -s 5 captures rkvg) ----
    lastcopy_k<<<(Bb * Dd) / 256, 256>>>(x, out_xlast);
    // ---- [5] big GEMMs r/k/v/g ----
    gemm_rkvg<<<dim3(Dd/128, BT/256, 4), 256, GEMM_SMEM>>>(
        rxh, rxl, wrh, wrl, r,
        kxh, kxl, wkh, wkl, k,
        vxh, vxl, wvh, wvl, v,
        gxh, gxl, wgh, wgl, g);
    // ---- [6,7] w path ----
    gemm_one<<<dim3(1, BT/256), 256, GEMM_SMEM>>>(wxh, wxl, td1h, td1l,
        nullptr, h1h, h1l, 64, Dd, nullptr, 2);
    gemm_one<<<dim3(Dd/128, BT/256), 256, GEMM_SMEM>>>(h1h, h1l, td2h, td2l,
        w, nullptr, nullptr, Dd, 64, tdec, 4);
    // ---- [8] WKV scan ----
    wkv_k<<<Bb * Hh, 256>>>(r, k, v, w, tfirst, state, att, out_state);
    // ---- [9] groupnorm * ln * g ----
    gnorm_k<<<(BT * Hh) / 8, 256>>>(att, g, ln_g, ln_b, gnh, gnl);
    // ---- [10] out = gn @ W_o ----
    gemm_one<<<dim3(Dd/128, BT/256), 256, GEMM_SMEM>>>(gnh, gnl, woh, wol,
        out0, nullptr, nullptr, Dd, Dd, nullptr, 0);
}

// round 7
// speedup vs baseline: 4.5456x; 1.1298x over previous
#include <cuda_runtime.h>
#include <cuda_bf16.h>
#include <math.h>
#include <stdint.h>

#define Bb 4
#define Tt 2048
#define Dd 2048
#define Hh 32
#define HSz 64
#define BT (Bb*Tt)
#define E5c 160

typedef __nv_bfloat16 bf16;

// ====================== device scratch (bss, no alloc) ======================
__device__ float g_m  [BT*E5c];
__device__ float g_r  [BT*Dd];
__device__ float g_k  [BT*Dd];
__device__ float g_v  [BT*Dd];
__device__ float g_g  [BT*Dd];
__device__ float g_w  [BT*Dd];
__device__ float g_att[BT*Dd];

__device__ bf16 g_xh [BT*Dd], g_xl [BT*Dd];
__device__ bf16 g_wxh[BT*Dd], g_wxl[BT*Dd];
__device__ bf16 g_kxh[BT*Dd], g_kxl[BT*Dd];
__device__ bf16 g_vxh[BT*Dd], g_vxl[BT*Dd];
__device__ bf16 g_rxh[BT*Dd], g_rxl[BT*Dd];
__device__ bf16 g_gxh[BT*Dd], g_gxl[BT*Dd];
__device__ bf16 g_gnh[BT*Dd], g_gnl[BT*Dd];
__device__ bf16 g_h1h[BT*64], g_h1l[BT*64];

__device__ bf16 g_wrh[Dd*Dd], g_wrl[Dd*Dd];
__device__ bf16 g_wkh[Dd*Dd], g_wkl[Dd*Dd];
__device__ bf16 g_wvh[Dd*Dd], g_wvl[Dd*Dd];
__device__ bf16 g_wgh[Dd*Dd], g_wgl[Dd*Dd];
__device__ bf16 g_woh[Dd*Dd], g_wol[Dd*Dd];
__device__ bf16 g_tm1h[256*Dd], g_tm1l[256*Dd];
__device__ bf16 g_td1h[128*Dd], g_td1l[128*Dd];
__device__ bf16 g_td2h[Dd*64],  g_td2l[Dd*64];

// ====================== PTX helpers (sm_80-class only) ======================
__device__ __forceinline__ uint32_t smem_u32(const void* p) {
    uint32_t a;
    asm("{ .reg .u64 t; cvta.to.shared.u64 t, %1; cvt.u32.u64 %0, t; }"
        : "=r"(a) : "l"(p));
    return a;
}

#define CP_ASYNC16(dst, src) \
    asm volatile("cp.async.cg.shared.global [%0], [%1], 16;" \
        :: "r"(dst), "l"(src) : "memory")
#define CP_ASYNC8(dst, src) \
    asm volatile("cp.async.ca.shared.global [%0], [%1], 8;" \
        :: "r"(dst), "l"(src) : "memory")
#define CP_COMMIT() asm volatile("cp.async.commit_group;" ::: "memory")
#define CP_WAIT0()  asm volatile("cp.async.wait_group 0;" ::: "memory")
#define CP_WAIT1()  asm volatile("cp.async.wait_group 1;" ::: "memory")

__device__ __forceinline__ void ldsm4(uint32_t* r, uint32_t addr) {
    asm volatile("ldmatrix.sync.aligned.m8n8.x4.shared.b16 {%0,%1,%2,%3},[%4];"
        : "=r"(r[0]), "=r"(r[1]), "=r"(r[2]), "=r"(r[3]) : "r"(addr));
}

__device__ __forceinline__ void mma16816(float* c, const uint32_t* a, const uint32_t* b) {
    asm volatile(
        "mma.sync.aligned.m16n8k16.row.col.f32.bf16.bf16.f32 "
        "{%0,%1,%2,%3},{%4,%5,%6,%7},{%8,%9},{%0,%1,%2,%3};"
        : "+f"(c[0]), "+f"(c[1]), "+f"(c[2]), "+f"(c[3])
        : "r"(a[0]), "r"(a[1]), "r"(a[2]), "r"(a[3]), "r"(b[0]), "r"(b[1]));
}

__device__ __forceinline__ uint32_t swz(uint32_t bo) { return bo ^ ((bo >> 3) & 0x70); }

// ====================== tensor-core GEMM (HMMA, 256x128 tile) ===============
__device__ __forceinline__ float repi(float v, int epi, const float* extra, int n) {
    switch (epi) {
        case 1: return 1.f / (1.f + expf(-v));
        case 2: return tanhf(v);
        case 3: return v / (1.f + expf(-v));
        case 4: return expf(-expf(v + extra[n]));
        default: return v;
    }
}

template<int ROWS>
__device__ __forceinline__ void load_tile_async(uint32_t sbase,
    const bf16* __restrict__ src, int row0, int k0, int ldK, int tid)
{
#pragma unroll
    for (int i = 0; i < ROWS / 32; i++) {
        int u = i * 256 + tid;
        int row = u >> 3, cc = u & 7;
        uint32_t bo = (uint32_t)(row * 128 + cc * 16);
        CP_ASYNC16(sbase + swz(bo),
                   src + (size_t)(row0 + row) * ldK + k0 + cc * 8);
    }
}

#define ST_SZ 98304u            // Ah 32K + Al 32K + Bh 16K + Bl 16K
#define GEMM_SMEM (2 * ST_SZ)   // 196608

__device__ __forceinline__ void gemm_stage(uint32_t st,
    const bf16* Ah, const bf16* Al, const bf16* Bh, const bf16* Bl,
    int mbase, int nbase, int k0, int K, int tid)
{
    load_tile_async<256>(st +     0, Ah, mbase, k0, K, tid);
    load_tile_async<256>(st + 32768, Al, mbase, k0, K, tid);
    load_tile_async<128>(st + 65536, Bh, nbase, k0, K, tid);
    load_tile_async<128>(st + 81920, Bl, nbase, k0, K, tid);
    CP_COMMIT();
}

__device__ __forceinline__ void gemm_core(
    const bf16* __restrict__ Ah, const bf16* __restrict__ Al,
    const bf16* __restrict__ Bh, const bf16* __restrict__ Bl,
    float* __restrict__ Cf, bf16* __restrict__ Ch, bf16* __restrict__ Cl,
    int Nout, int K, const float* __restrict__ extra, int epi)
{
    extern __shared__ char sm[];
    const uint32_t sb = smem_u32(sm);
    const int tid = threadIdx.x, lane = tid & 31, wid = tid >> 5;
    const int wm = wid >> 1, wn = wid & 1;           // 4 x 2 warp grid, warp tile 64x64
    const int mbase = blockIdx.y * 256, nbase = blockIdx.x * 128;

    float acc[4][8][4];
#pragma unroll
    for (int mf = 0; mf < 4; mf++)
#pragma unroll
        for (int nf = 0; nf < 8; nf++)
#pragma unroll
            for (int q = 0; q < 4; q++) acc[mf][nf][q] = 0.f;

    const int nc = K / 64;
    gemm_stage(sb, Ah, Al, Bh, Bl, mbase, nbase, 0, K, tid);

    const int a_row = (lane & 15);
    const int a_cb  = ((lane >> 4) & 1) * 16;
    const int mat   = lane >> 3;
    const int b_row = (lane & 7) + ((mat >> 1) & 1) * 8;
    const int b_cb  = (mat & 1) * 16;

    for (int c = 0; c < nc; c++) {
        if (c + 1 < nc) {
            gemm_stage(sb + ((c + 1) & 1) * ST_SZ, Ah, Al, Bh, Bl,
                       mbase, nbase, (c + 1) * 64, K, tid);
            CP_WAIT1();
        } else {
            CP_WAIT0();
        }
        __syncthreads();

        const uint32_t base = sb + (c & 1) * ST_SZ;
#pragma unroll
        for (int ks = 0; ks < 4; ks++) {
            uint32_t ah[4][4], al[4][4];
#pragma unroll
            for (int mf = 0; mf < 4; mf++) {
                uint32_t bo = (uint32_t)((wm * 64 + mf * 16 + a_row) * 128 + ks * 32 + a_cb);
                uint32_t sw = swz(bo);
                ldsm4(ah[mf], base + sw);
                ldsm4(al[mf], base + 32768 + sw);
            }
            uint32_t bh[4][4], bl[4][4];
#pragma unroll
            for (int bq = 0; bq < 4; bq++) {
                uint32_t bo = (uint32_t)((wn * 64 + bq * 16 + b_row) * 128 + ks * 32 + b_cb);
                uint32_t sw = swz(bo);
                ldsm4(bh[bq], base + 65536 + sw);
                ldsm4(bl[bq], base + 81920 + sw);
            }
            // 3 passes: same-accumulator reuse distance = 32 MMAs
#pragma unroll
            for (int mf = 0; mf < 4; mf++)
#pragma unroll
                for (int bq = 0; bq < 4; bq++) {
                    mma16816(acc[mf][2 * bq],     ah[mf], &bh[bq][0]);
                    mma16816(acc[mf][2 * bq + 1], ah[mf], &bh[bq][2]);
                }
#pragma unroll
            for (int mf = 0; mf < 4; mf++)
#pragma unroll
                for (int bq = 0; bq < 4; bq++) {
                    mma16816(acc[mf][2 * bq],     ah[mf], &bl[bq][0]);
                    mma16816(acc[mf][2 * bq + 1], ah[mf], &bl[bq][2]);
                }
#pragma unroll
            for (int mf = 0; mf < 4; mf++)
#pragma unroll
                for (int bq = 0; bq < 4; bq++) {
                    mma16816(acc[mf][2 * bq],     al[mf], &bh[bq][0]);
                    mma16816(acc[mf][2 * bq + 1], al[mf], &bh[bq][2]);
                }
        }
        __syncthreads();
    }

    const int r_in = lane >> 2, c_in = (lane & 3) * 2;
#pragma unroll
    for (int mf = 0; mf < 4; mf++)
#pragma unroll
        for (int nf = 0; nf < 8; nf++) {
            int row0 = mbase + wm * 64 + mf * 16 + r_in;
            int col  = nbase + wn * 64 + nf * 8 + c_in;
            if (col >= Nout) continue;
            float* q = acc[mf][nf];
            float e0 = repi(q[0], epi, extra, col);
            float e1 = repi(q[1], epi, extra, col + 1);
            float e2 = repi(q[2], epi, extra, col);
            float e3 = repi(q[3], epi, extra, col + 1);
            if (Ch == nullptr) {
                *(float2*)(Cf + (size_t)row0 * Nout + col) = make_float2(e0, e1);
                *(float2*)(Cf + (size_t)(row0 + 8) * Nout + col) = make_float2(e2, e3);
            } else {
                size_t o0 = (size_t)row0 * Nout + col;
                size_t o1 = (size_t)(row0 + 8) * Nout + col;
                bf16 h;
                h = __float2bfloat16(e0); Ch[o0]     = h; Cl[o0]     = __float2bfloat16(e0 - __bfloat162float(h));
                h = __float2bfloat16(e1); Ch[o0 + 1] = h; Cl[o0 + 1] = __float2bfloat16(e1 - __bfloat162float(h));
                h = __float2bfloat16(e2); Ch[o1]     = h; Cl[o1]     = __float2bfloat16(e2 - __bfloat162float(h));
                h = __float2bfloat16(e3); Ch[o1 + 1] = h; Cl[o1 + 1] = __float2bfloat16(e3 - __bfloat162float(h));
            }
        }
}

__global__ void __launch_bounds__(256, 1) gemm_one(
    const bf16* __restrict__ Ah, const bf16* __restrict__ Al,
    const bf16* __restrict__ Bh, const bf16* __restrict__ Bl,
    float* __restrict__ Cf, bf16* __restrict__ Ch, bf16* __restrict__ Cl,
    int Nout, int K, const float* __restrict__ extra, int epi)
{
    gemm_core(Ah, Al, Bh, Bl, Cf, Ch, Cl, Nout, K, extra, epi);
}

// z = 0..3: r/k/v/g big GEMMs. z = 4: the small td1 GEMM (overlapped).
__global__ void __launch_bounds__(256, 1) gemm_rkvg(
    const bf16* rxh, const bf16* rxl, const bf16* wrh, const bf16* wrl, float* r,
    const bf16* kxh, const bf16* kxl, const bf16* wkh, const bf16* wkl, float* k,
    const bf16* vxh, const bf16* vxl, const bf16* wvh, const bf16* wvl, float* v,
    const bf16* gxh, const bf16* gxl, const bf16* wgh, const bf16* wgl, float* g,
    const bf16* wxh, const bf16* wxl, const bf16* td1h, const bf16* td1l,
    bf16* h1h, bf16* h1l)
{
    if (blockIdx.z == 4) {
        if (blockIdx.x != 0) return;
        gemm_core(wxh, wxl, td1h, td1l, nullptr, h1h, h1l, 64, Dd, nullptr, 2);
        return;
    }
    const bf16 *Ah, *Al, *Bh, *Bl; float* C; int epi;
    switch (blockIdx.z) {
        case 0:  Ah = rxh; Al = rxl; Bh = wrh; Bl = wrl; C = r; epi = 1; break;
        case 1:  Ah = kxh; Al = kxl; Bh = wkh; Bl = wkl; C = k; epi = 0; break;
        case 2:  Ah = vxh; Al = vxl; Bh = wvh; Bl = wvl; C = v; epi = 0; break;
        default: Ah = gxh; Al = gxl; Bh = wgh; Bl = wgl; C = g; epi = 3; break;
    }
    gemm_core(Ah, Al, Bh, Bl, C, nullptr, nullptr, Dd, Dd, nullptr, epi);
}

// ====================== all weight transposes + bf16 splits in ONE launch ===
struct TsArgs {
    const float* src[8];
    bf16* bh[8];
    bf16* bl[8];
    int K[8], N[8], gx[8], gy[8];
};

__global__ void __launch_bounds__(256) tsplit_all(TsArgs a)
{
    const int z = blockIdx.z;
    if ((int)blockIdx.x >= a.gx[z] || (int)blockIdx.y >= a.gy[z]) return;
    const float* __restrict__ W = a.src[z];
    bf16* __restrict__ bh = a.bh[z];
    bf16* __restrict__ bl = a.bl[z];
    const int K = a.K[z], N = a.N[z];

    __shared__ float t[32][33];
    const int k0 = blockIdx.x * 32, n0 = blockIdx.y * 32;
    const int tx = threadIdx.x & 31, ty = threadIdx.x >> 5;
#pragma unroll
    for (int i = 0; i < 4; i++) {
        int kk = ty + i * 8;
        int n = n0 + tx;
        t[kk][tx] = (n < N) ? W[(size_t)(k0 + kk) * N + n] : 0.f;
    }
    __syncthreads();
#pragma unroll
    for (int i = 0; i < 4; i++) {
        int nn = ty + i * 8;
        float v = t[tx][nn];
        bf16 h = __float2bfloat16(v);
        size_t o = (size_t)(n0 + nn) * K + k0 + tx;
        bh[o] = h;
        bl[o] = __float2bfloat16(v - __bfloat162float(h));
    }
}

// ====================== prep: split(xxx) ====================================
__global__ void __launch_bounds__(256) prep_k(
    const float* __restrict__ x, const float* __restrict__ prev,
    const float* __restrict__ xmaa,
    bf16* __restrict__ xh, bf16* __restrict__ xl)
{
    size_t i = (size_t)blockIdx.x * 256 + threadIdx.x;
    int d = (int)(i % Dd);
    size_t bt = i / Dd;
    int t = (int)(bt % Tt);
    int b = (int)(bt / Tt);
    float xv = x[i];
    float sh = (t == 0) ? prev[(size_t)b * Dd + d] : x[i - Dd];
    float s = sh - xv;
    float xxx = fmaf(s, xmaa[d], xv);
    bf16 h = __float2bfloat16(xxx);
    xh[i] = h;
    xl[i] = __float2bfloat16(xxx - __bfloat162float(h));
}

// ====================== mix v2: transposed msh + cp.async tiles =============
__global__ void __launch_bounds__(256) mix_k(
    const float* __restrict__ x, const float* __restrict__ prev,
    const float* __restrict__ m, const float* __restrict__ tmw2,
    const float* __restrict__ wmaa, const float* __restrict__ kmaa,
    const float* __restrict__ vmaa, const float* __restrict__ rmaa,
    const float* __restrict__ gmaa,
    bf16* __restrict__ wxh, bf16* __restrict__ wxl,
    bf16* __restrict__ kxh, bf16* __restrict__ kxl,
    bf16* __restrict__ vxh, bf16* __restrict__ vxl,
    bf16* __restrict__ rxh, bf16* __restrict__ rxl,
    bf16* __restrict__ gxh, bf16* __restrict__ gxl)
{
    __shared__ float msh[E5c][8];        // [e5][tok]  (5 KB)
    __shared__ float tile[2][32][256];   // double-buffered tm_w2 slice (64 KB)
    const int tid = threadIdx.x;
    const int dbase = blockIdx.x * 256;
    const int tb = blockIdx.y * 8;

    // stage f=0 tile
#pragma unroll
    for (int i = 0; i < 8; i++) {
        int j = i * 256 + tid;
        int e = j >> 6, c4 = (j & 63) << 2;
        CP_ASYNC16(smem_u32(&tile[0][e][c4]),
                   tmw2 + (size_t)e * Dd + dbase + c4);
    }
    CP_COMMIT();

    // load m transposed: msh[e5][tok]
    for (int i = tid; i < 8 * E5c; i += 256) {
        int tok = i / E5c, e5 = i % E5c;
        msh[e5][tok] = m[(size_t)(tb + tok) * E5c + e5];
    }

    float acc[8][5];
#pragma unroll
    for (int tok = 0; tok < 8; tok++)
#pragma unroll
        for (int f = 0; f < 5; f++) acc[tok][f] = 0.f;

#pragma unroll
    for (int f = 0; f < 5; f++) {
        if (f + 1 < 5) {
            const int nb = (f + 1) & 1;
#pragma unroll
            for (int i = 0; i < 8; i++) {
                int j = i * 256 + tid;
                int e = j >> 6, c4 = (j & 63) << 2;
                CP_ASYNC16(smem_u32(&tile[nb][e][c4]),
                           tmw2 + (size_t)((f + 1) * 32 + e) * Dd + dbase + c4);
            }
            CP_COMMIT();
            CP_WAIT1();
        } else {
            CP_WAIT0();
        }
        __syncthreads();

        const int cb = f & 1;
#pragma unroll
        for (int e = 0; e < 32; e++) {
            float tv = tile[cb][e][tid];
            float4 m0 = *(const float4*)&msh[f * 32 + e][0];
            float4 m1 = *(const float4*)&msh[f * 32 + e][4];
            acc[0][f] = fmaf(m0.x, tv, acc[0][f]);
            acc[1][f] = fmaf(m0.y, tv, acc[1][f]);
            acc[2][f] = fmaf(m0.z, tv, acc[2][f]);
            acc[3][f] = fmaf(m0.w, tv, acc[3][f]);
            acc[4][f] = fmaf(m1.x, tv, acc[4][f]);
            acc[5][f] = fmaf(m1.y, tv, acc[5][f]);
            acc[6][f] = fmaf(m1.z, tv, acc[6][f]);
            acc[7][f] = fmaf(m1.w, tv, acc[7][f]);
        }
        __syncthreads();
    }

    const int d = dbase + tid;
    const float wm = wmaa[d], km = kmaa[d], vm = vmaa[d], rm = rmaa[d], gm = gmaa[d];
#pragma unroll
    for (int tok = 0; tok < 8; tok++) {
        int bt = tb + tok;
        int t = bt & (Tt - 1), b = bt >> 11;
        size_t idx = (size_t)bt * Dd + d;
        float xv = x[idx];
        float sh = (t == 0) ? prev[(size_t)b * Dd + d] : x[idx - Dd];
        float sv = sh - xv;
        float w_ = fmaf(sv, wm + acc[tok][0], xv);
        float k_ = fmaf(sv, km + acc[tok][1], xv);
        float v_ = fmaf(sv, vm + acc[tok][2], xv);
        float r_ = fmaf(sv, rm + acc[tok][3], xv);
        float g_ = fmaf(sv, gm + acc[tok][4], xv);
        bf16 h;
        h = __float2bfloat16(w_); wxh[idx] = h; wxl[idx] = __float2bfloat16(w_ - __bfloat162float(h));
        h = __float2bfloat16(k_); kxh[idx] = h; kxl[idx] = __float2bfloat16(k_ - __bfloat162float(h));
        h = __float2bfloat16(v_); vxh[idx] = h; vxl[idx] = __float2bfloat16(v_ - __bfloat162float(h));
        h = __float2bfloat16(r_); rxh[idx] = h; rxl[idx] = __float2bfloat16(r_ - __bfloat162float(h));
        h = __float2bfloat16(g_); gxh[idx] = h; gxl[idx] = __float2bfloat16(g_ - __bfloat162float(h));
    }
}

// ====================== WKV scan: u in regs, cp.async pipelined =============
__global__ void __launch_bounds__(256) wkv_k(
    const float* __restrict__ r, const float* __restrict__ k,
    const float* __restrict__ v, const float* __restrict__ w,
    const float* __restrict__ u, const float* __restrict__ s0,
    float* __restrict__ att, float* __restrict__ sout)
{
    __shared__ float rs[3][8][64], ksm[3][8][64], wsm[3][8][64], vsm[3][8][64];
    __shared__ float osh[3][8][64];

    const int bh = blockIdx.x, b = bh >> 5, h = bh & 31;
    const int tid = threadIdx.x;
    const int vcol = tid >> 2, kg = tid & 3;
    const int st_ = tid >> 5;
    const int si  = (tid & 31) * 2;

    const size_t base0 = (size_t)b * Tt * Dd + h * 64;
    const size_t sbase = (size_t)bh * 4096;

    float s[16], uo[16];
#pragma unroll
    for (int j = 0; j < 16; j++) {
        s[j]  = s0[sbase + (size_t)(kg * 16 + j) * 64 + vcol];
        uo[j] = u[h * 64 + kg * 16 + j];
    }

    {
        size_t g = base0 + (size_t)st_ * Dd + si;
        CP_ASYNC8(smem_u32(&rs[0][st_][si]),  r + g);
        CP_ASYNC8(smem_u32(&ksm[0][st_][si]), k + g);
        CP_ASYNC8(smem_u32(&wsm[0][st_][si]), w + g);
        CP_ASYNC8(smem_u32(&vsm[0][st_][si]), v + g);
        CP_COMMIT();
    }

    const int NB = Tt / 8;
    int buf = 0;
    for (int nb = 0; nb < NB; nb++) {
        buf = nb % 3;
        const int nxt = (nb + 1) % 3;
        if (nb + 1 < NB) {
            size_t g = base0 + (size_t)((nb + 1) * 8 + st_) * Dd + si;
            CP_ASYNC8(smem_u32(&rs[nxt][st_][si]),  r + g);
            CP_ASYNC8(smem_u32(&ksm[nxt][st_][si]), k + g);
            CP_ASYNC8(smem_u32(&wsm[nxt][st_][si]), w + g);
            CP_ASYNC8(smem_u32(&vsm[nxt][st_][si]), v + g);
            CP_COMMIT();
            CP_WAIT1();
        } else {
            CP_WAIT0();
        }
        __syncthreads();

        if (nb > 0) {
            const int pb = (nb - 1) % 3;
            *(float2*)&att[base0 + (size_t)((nb - 1) * 8 + st_) * Dd + si] =
                *(const float2*)&osh[pb][st_][si];
        }

#pragma unroll
        for (int t = 0; t < 8; t++) {
            const float vm = vsm[buf][t][vcol];
            float a = 0.f;
            const float* rp = &rs[buf][t][kg * 16];
            const float* kp = &ksm[buf][t][kg * 16];
            const float* wp = &wsm[buf][t][kg * 16];
#pragma unroll
            for (int q = 0; q < 4; q++) {
                float4 r4 = *(const float4*)(rp + 4 * q);
                float4 k4 = *(const float4*)(kp + 4 * q);
                float4 w4 = *(const float4*)(wp + 4 * q);
                float kv, tt;
                kv = k4.x * vm; tt = fmaf(uo[4*q+0], kv, s[4*q+0]); a = fmaf(r4.x, tt, a); s[4*q+0] = fmaf(s[4*q+0], w4.x, kv);
                kv = k4.y * vm; tt = fmaf(uo[4*q+1], kv, s[4*q+1]); a = fmaf(r4.y, tt, a); s[4*q+1] = fmaf(s[4*q+1], w4.y, kv);
                kv = k4.z * vm; tt = fmaf(uo[4*q+2], kv, s[4*q+2]); a = fmaf(r4.z, tt, a); s[4*q+2] = fmaf(s[4*q+2], w4.z, kv);
                kv = k4.w * vm; tt = fmaf(uo[4*q+3], kv, s[4*q+3]); a = fmaf(r4.w, tt, a); s[4*q+3] = fmaf(s[4*q+3], w4.w, kv);
            }
            a += __shfl_xor_sync(0xffffffffu, a, 1);
            a += __shfl_xor_sync(0xffffffffu, a, 2);
            if (kg == 0) osh[buf][t][vcol] = a;
        }
    }
    __syncthreads();
    *(float2*)&att[base0 + (size_t)((NB - 1) * 8 + st_) * Dd + si] =
        *(const float2*)&osh[buf][st_][si];
#pragma unroll
    for (int j = 0; j < 16; j++)
        sout[sbase + (size_t)(kg * 16 + j) * 64 + vcol] = s[j];
}

// ====================== groupnorm + ln + *g, writes bf16 splits =============
__global__ void __launch_bounds__(256) gnorm_k(
    const float* __restrict__ att, const float* __restrict__ g,
    const float* __restrict__ lng, const float* __restrict__ lnb,
    bf16* __restrict__ oh, bf16* __restrict__ ol)
{
    const int grp = blockIdx.x * 8 + (threadIdx.x >> 5);
    const int lane = threadIdx.x & 31;
    const int bt = grp >> 5;
    const int h = grp & 31;
    size_t base = (size_t)bt * Dd + h * 64;
    float v0 = att[base + lane];
    float v1 = att[base + lane + 32];
    float sum = v0 + v1;
    float sq = v0 * v0 + v1 * v1;
#pragma unroll
    for (int o = 16; o > 0; o >>= 1) {
        sum += __shfl_xor_sync(0xffffffffu, sum, o);
        sq  += __shfl_xor_sync(0xffffffffu, sq, o);
    }
    float mu = sum * (1.f / 64.f);
    float var = sq * (1.f / 64.f) - mu * mu;
    float inv = rsqrtf(var + 1e-5f);
    int li = h * 64 + lane;
    float o0 = fmaf((v0 - mu) * inv, lng[li],      lnb[li])      * g[base + lane];
    float o1 = fmaf((v1 - mu) * inv, lng[li + 32], lnb[li + 32]) * g[base + lane + 32];
    bf16 hh;
    hh = __float2bfloat16(o0); oh[base + lane]      = hh; ol[base + lane]      = __float2bfloat16(o0 - __bfloat162float(hh));
    hh = __float2bfloat16(o1); oh[base + lane + 32] = hh; ol[base + lane + 32] = __float2bfloat16(o1 - __bfloat162float(hh));
}

// ====================== copy x[:, -1, :] ====================================
__global__ void __launch_bounds__(256) lastcopy_k(const float* __restrict__ x,
                                                  float* __restrict__ o)
{
    int i = blockIdx.x * 256 + threadIdx.x;
    int b = i / Dd, d = i % Dd;
    o[i] = x[((size_t)b * Tt + (Tt - 1)) * Dd + d];
}

// ====================== host ================================================
extern "C" void kernel_launch(void* const* d_in, const int* in_sizes, int n_in,
                              void* d_out, int out_size)
{
    const float* x     = (const float*)d_in[0];
    const float* prev  = (const float*)d_in[1];
    const float* state = (const float*)d_in[2];
    const float* x_maa = (const float*)d_in[3];
    const float* w_maa = (const float*)d_in[4];
    const float* k_maa = (const float*)d_in[5];
    const float* v_maa = (const float*)d_in[6];
    const float* r_maa = (const float*)d_in[7];
    const float* g_maa = (const float*)d_in[8];
    const float* tm_w1 = (const float*)d_in[9];
    const float* tm_w2 = (const float*)d_in[10];
    const float* td_w1 = (const float*)d_in[11];
    const float* td_w2 = (const float*)d_in[12];
    const float* tdec  = (const float*)d_in[13];
    const float* tfirst= (const float*)d_in[14];
    const float* W_r   = (const float*)d_in[15];
    const float* W_k   = (const float*)d_in[16];
    const float* W_v   = (const float*)d_in[17];
    const float* W_g   = (const float*)d_in[18];
    const float* W_o   = (const float*)d_in[19];
    const float* ln_g  = (const float*)d_in[20];
    const float* ln_b  = (const float*)d_in[21];

    float *m, *r, *k, *v, *g, *w, *att;
    cudaGetSymbolAddress((void**)&m,   g_m);
    cudaGetSymbolAddress((void**)&r,   g_r);
    cudaGetSymbolAddress((void**)&k,   g_k);
    cudaGetSymbolAddress((void**)&v,   g_v);
    cudaGetSymbolAddress((void**)&g,   g_g);
    cudaGetSymbolAddress((void**)&w,   g_w);
    cudaGetSymbolAddress((void**)&att, g_att);

    bf16 *xh, *xl, *wxh, *wxl, *kxh, *kxl, *vxh, *vxl, *rxh, *rxl, *gxh, *gxl;
    bf16 *gnh, *gnl, *h1h, *h1l;
    bf16 *wrh, *wrl, *wkh, *wkl, *wvh, *wvl, *wgh, *wgl, *woh, *wol;
    bf16 *tm1h, *tm1l, *td1h, *td1l, *td2h, *td2l;
    cudaGetSymbolAddress((void**)&xh,  g_xh);  cudaGetSymbolAddress((void**)&xl,  g_xl);
    cudaGetSymbolAddress((void**)&wxh, g_wxh); cudaGetSymbolAddress((void**)&wxl, g_wxl);
    cudaGetSymbolAddress((void**)&kxh, g_kxh); cudaGetSymbolAddress((void**)&kxl, g_kxl);
    cudaGetSymbolAddress((void**)&vxh, g_vxh); cudaGetSymbolAddress((void**)&vxl, g_vxl);
    cudaGetSymbolAddress((void**)&rxh, g_rxh); cudaGetSymbolAddress((void**)&rxl, g_rxl);
    cudaGetSymbolAddress((void**)&gxh, g_gxh); cudaGetSymbolAddress((void**)&gxl, g_gxl);
    cudaGetSymbolAddress((void**)&gnh, g_gnh); cudaGetSymbolAddress((void**)&gnl, g_gnl);
    cudaGetSymbolAddress((void**)&h1h, g_h1h); cudaGetSymbolAddress((void**)&h1l, g_h1l);
    cudaGetSymbolAddress((void**)&wrh, g_wrh); cudaGetSymbolAddress((void**)&wrl, g_wrl);
    cudaGetSymbolAddress((void**)&wkh, g_wkh); cudaGetSymbolAddress((void**)&wkl, g_wkl);
    cudaGetSymbolAddress((void**)&wvh, g_wvh); cudaGetSymbolAddress((void**)&wvl, g_wvl);
    cudaGetSymbolAddress((void**)&wgh, g_wgh); cudaGetSymbolAddress((void**)&wgl, g_wgl);
    cudaGetSymbolAddress((void**)&woh, g_woh); cudaGetSymbolAddress((void**)&wol, g_wol);
    cudaGetSymbolAddress((void**)&tm1h, g_tm1h); cudaGetSymbolAddress((void**)&tm1l, g_tm1l);
    cudaGetSymbolAddress((void**)&td1h, g_td1h); cudaGetSymbolAddress((void**)&td1l, g_td1l);
    cudaGetSymbolAddress((void**)&td2h, g_td2h); cudaGetSymbolAddress((void**)&td2l, g_td2l);

    float* out0 = (float*)d_out;
    float* out_xlast = out0 + (size_t)BT * Dd;
    float* out_state = out_xlast + (size_t)Bb * Dd;

    cudaFuncSetAttribute(gemm_one,  cudaFuncAttributeMaxDynamicSharedMemorySize, GEMM_SMEM);
    cudaFuncSetAttribute(gemm_rkvg, cudaFuncAttributeMaxDynamicSharedMemorySize, GEMM_SMEM);

    // ---- [0] all 8 weight transposes+splits in one launch ----
    TsArgs ta;
    ta.src[0]=W_r;  ta.bh[0]=wrh;  ta.bl[0]=wrl;  ta.K[0]=Dd; ta.N[0]=Dd;  ta.gx[0]=64; ta.gy[0]=64;
    ta.src[1]=W_k;  ta.bh[1]=wkh;  ta.bl[1]=wkl;  ta.K[1]=Dd; ta.N[1]=Dd;  ta.gx[1]=64; ta.gy[1]=64;
    ta.src[2]=W_v;  ta.bh[2]=wvh;  ta.bl[2]=wvl;  ta.K[2]=Dd; ta.N[2]=Dd;  ta.gx[2]=64; ta.gy[2]=64;
    ta.src[3]=W_g;  ta.bh[3]=wgh;  ta.bl[3]=wgl;  ta.K[3]=Dd; ta.N[3]=Dd;  ta.gx[3]=64; ta.gy[3]=64;
    ta.src[4]=W_o;  ta.bh[4]=woh;  ta.bl[4]=wol;  ta.K[4]=Dd; ta.N[4]=Dd;  ta.gx[4]=64; ta.gy[4]=64;
    ta.src[5]=tm_w1;ta.bh[5]=tm1h; ta.bl[5]=tm1l; ta.K[5]=Dd; ta.N[5]=E5c; ta.gx[5]=64; ta.gy[5]=8;
    ta.src[6]=td_w1;ta.bh[6]=td1h; ta.bl[6]=td1l; ta.K[6]=Dd; ta.N[6]=64;  ta.gx[6]=64; ta.gy[6]=4;
    ta.src[7]=td_w2;ta.bh[7]=td2h; ta.bl[7]=td2l; ta.K[7]=64; ta.N[7]=Dd;  ta.gx[7]=2;  ta.gy[7]=64;
    tsplit_all<<<dim3(64, 64, 8), 256>>>(ta);

    // ---- [1] shift + split(xxx) ----
    prep_k<<<(BT * Dd) / 256, 256>>>(x, prev, x_maa, xh, xl);
    // ---- [2] m = tanh(xxx @ tm_w1) ----
    gemm_one<<<dim3(2, BT/256), 256, GEMM_SMEM>>>(xh, xl, tm1h, tm1l,
        m, nullptr, nullptr, E5c, Dd, nullptr, 2);
    // ---- [3] mix + 5 lerps ----
    mix_k<<<dim3(Dd/256, BT/8), 256>>>(x, prev, m, tm_w2,
        w_maa, k_maa, v_maa, r_maa, g_maa,
        wxh, wxl, kxh, kxl, vxh, vxl, rxh, rxl, gxh, gxl);
    // ---- [4] x[:, -1] ----
    lastcopy_k<<<(Bb * Dd) / 256, 256>>>(x, out_xlast);
    // ---- [5] big GEMMs r/k/v/g + overlapped td1 (z=4) ----
    gemm_rkvg<<<dim3(Dd/128, BT/256, 5), 256, GEMM_SMEM>>>(
        rxh, rxl, wrh, wrl, r,
        kxh, kxl, wkh, wkl, k,
        vxh, vxl, wvh, wvl, v,
        gxh, gxl, wgh, wgl, g,
        wxh, wxl, td1h, td1l, h1h, h1l);
    // ---- [6] td2: w = exp(-exp(h1 @ td_w2 + decay)) ----
    gemm_one<<<dim3(Dd/128, BT/256), 256, GEMM_SMEM>>>(h1h, h1l, td2h, td2l,
        w, nullptr, nullptr, Dd, 64, tdec, 4);
    // ---- [7] WKV scan ----
    wkv_k<<<Bb * Hh, 256>>>(r, k, v, w, tfirst, state, att, out_state);
    // ---- [8] groupnorm * ln * g ----
    gnorm_k<<<(BT * Hh) / 8, 256>>>(att, g, ln_g, ln_b, gnh, gnl);
    // ---- [9] out = gn @ W_o ----
    gemm_one<<<dim3(Dd/128, BT/256), 256, GEMM_SMEM>>>(gnh, gnl, woh, wol,
        out0, nullptr, nullptr, Dd, Dd, nullptr, 0);
}

// round 8
// speedup vs baseline: 5.6392x; 1.2406x over previous
#include <cuda_runtime.h>
#include <cuda_fp16.h>
#include <math.h>
#include <stdint.h>

#define Bb 4
#define Tt 2048
#define Dd 2048
#define Hh 32
#define HSz 64
#define BT (Bb*Tt)
#define E5c 160

// ====================== device scratch (bss, no alloc) ======================
__device__ float g_m  [BT*E5c];
__device__ float g_r  [BT*Dd];
__device__ float g_k  [BT*Dd];
__device__ float g_v  [BT*Dd];
__device__ float g_g  [BT*Dd];
__device__ float g_w  [BT*Dd];
__device__ float g_att[BT*Dd];

__device__ __half g_xh [BT*Dd];
__device__ __half g_wxh[BT*Dd];
__device__ __half g_kxh[BT*Dd];
__device__ __half g_vxh[BT*Dd];
__device__ __half g_rxh[BT*Dd];
__device__ __half g_gxh[BT*Dd];
__device__ __half g_gnh[BT*Dd];
__device__ __half g_h1h[BT*64];

__device__ __half g_wrh[Dd*Dd], g_wrl[Dd*Dd];
__device__ __half g_wkh[Dd*Dd], g_wkl[Dd*Dd];
__device__ __half g_wvh[Dd*Dd], g_wvl[Dd*Dd];
__device__ __half g_wgh[Dd*Dd], g_wgl[Dd*Dd];
__device__ __half g_woh[Dd*Dd], g_wol[Dd*Dd];
__device__ __half g_tm1h[256*Dd], g_tm1l[256*Dd];
__device__ __half g_td1h[128*Dd], g_td1l[128*Dd];
__device__ __half g_td2h[Dd*64],  g_td2l[Dd*64];

// ====================== PTX helpers (sm_80-class only) ======================
__device__ __forceinline__ uint32_t smem_u32(const void* p) {
    uint32_t a;
    asm("{ .reg .u64 t; cvta.to.shared.u64 t, %1; cvt.u32.u64 %0, t; }"
        : "=r"(a) : "l"(p));
    return a;
}

#define CP_ASYNC16(dst, src) \
    asm volatile("cp.async.cg.shared.global [%0], [%1], 16;" \
        :: "r"(dst), "l"(src) : "memory")
#define CP_ASYNC8(dst, src) \
    asm volatile("cp.async.ca.shared.global [%0], [%1], 8;" \
        :: "r"(dst), "l"(src) : "memory")
#define CP_COMMIT() asm volatile("cp.async.commit_group;" ::: "memory")
#define CP_WAIT0()  asm volatile("cp.async.wait_group 0;" ::: "memory")
#define CP_WAIT1()  asm volatile("cp.async.wait_group 1;" ::: "memory")

__device__ __forceinline__ void ldsm4(uint32_t* r, uint32_t addr) {
    asm volatile("ldmatrix.sync.aligned.m8n8.x4.shared.b16 {%0,%1,%2,%3},[%4];"
        : "=r"(r[0]), "=r"(r[1]), "=r"(r[2]), "=r"(r[3]) : "r"(addr));
}

__device__ __forceinline__ void mma16816(float* c, const uint32_t* a, const uint32_t* b) {
    asm volatile(
        "mma.sync.aligned.m16n8k16.row.col.f32.f16.f16.f32 "
        "{%0,%1,%2,%3},{%4,%5,%6,%7},{%8,%9},{%0,%1,%2,%3};"
        : "+f"(c[0]), "+f"(c[1]), "+f"(c[2]), "+f"(c[3])
        : "r"(a[0]), "r"(a[1]), "r"(a[2]), "r"(a[3]), "r"(b[0]), "r"(b[1]));
}

__device__ __forceinline__ uint32_t swz(uint32_t bo) { return bo ^ ((bo >> 3) & 0x70); }

// ====================== tensor-core GEMM (HMMA fp16, 256x128 tile) ==========
// C = epi(A[M,K] @ (Bh+Bl)[Npad,K]^T); A single fp16, weights split exactly.
__device__ __forceinline__ float repi(float v, int epi, const float* extra, int n) {
    switch (epi) {
        case 1: return 1.f / (1.f + expf(-v));
        case 2: return tanhf(v);
        case 3: return v / (1.f + expf(-v));
        case 4: return expf(-expf(v + extra[n]));
        default: return v;
    }
}

template<int ROWS>
__device__ __forceinline__ void load_tile_async(uint32_t sbase,
    const __half* __restrict__ src, int row0, int k0, int ldK, int tid)
{
#pragma unroll
    for (int i = 0; i < ROWS / 32; i++) {
        int u = i * 256 + tid;
        int row = u >> 3, cc = u & 7;
        uint32_t bo = (uint32_t)(row * 128 + cc * 16);
        CP_ASYNC16(sbase + swz(bo),
                   src + (size_t)(row0 + row) * ldK + k0 + cc * 8);
    }
}

#define ST_SZ 65536u            // A 32K + Bh 16K + Bl 16K
#define GEMM_SMEM (2 * ST_SZ)   // 131072

__device__ __forceinline__ void gemm_stage(uint32_t st,
    const __half* A, const __half* Bh, const __half* Bl,
    int mbase, int nbase, int k0, int K, int tid)
{
    load_tile_async<256>(st +     0, A,  mbase, k0, K, tid);
    load_tile_async<128>(st + 32768, Bh, nbase, k0, K, tid);
    load_tile_async<128>(st + 49152, Bl, nbase, k0, K, tid);
    CP_COMMIT();
}

__device__ __forceinline__ void gemm_core(
    const __half* __restrict__ A,
    const __half* __restrict__ Bh, const __half* __restrict__ Bl,
    float* __restrict__ Cf, __half* __restrict__ Ch,
    int Nout, int K, const float* __restrict__ extra, int epi)
{
    extern __shared__ char sm[];
    const uint32_t sb = smem_u32(sm);
    const int tid = threadIdx.x, lane = tid & 31, wid = tid >> 5;
    const int wm = wid >> 1, wn = wid & 1;           // 4 x 2 warps, warp tile 64x64
    const int mbase = blockIdx.y * 256, nbase = blockIdx.x * 128;

    float acc[4][8][4];
#pragma unroll
    for (int mf = 0; mf < 4; mf++)
#pragma unroll
        for (int nf = 0; nf < 8; nf++)
#pragma unroll
            for (int q = 0; q < 4; q++) acc[mf][nf][q] = 0.f;

    const int nc = K / 64;
    gemm_stage(sb, A, Bh, Bl, mbase, nbase, 0, K, tid);

    const int a_row = (lane & 15);
    const int a_cb  = ((lane >> 4) & 1) * 16;
    const int mat   = lane >> 3;
    const int b_row = (lane & 7) + ((mat >> 1) & 1) * 8;
    const int b_cb  = (mat & 1) * 16;

    for (int c = 0; c < nc; c++) {
        if (c + 1 < nc) {
            gemm_stage(sb + ((c + 1) & 1) * ST_SZ, A, Bh, Bl,
                       mbase, nbase, (c + 1) * 64, K, tid);
            CP_WAIT1();
        } else {
            CP_WAIT0();
        }
        __syncthreads();

        const uint32_t base = sb + (c & 1) * ST_SZ;
#pragma unroll
        for (int ks = 0; ks < 4; ks++) {
            uint32_t av[4][4];
#pragma unroll
            for (int mf = 0; mf < 4; mf++) {
                uint32_t bo = (uint32_t)((wm * 64 + mf * 16 + a_row) * 128 + ks * 32 + a_cb);
                ldsm4(av[mf], base + swz(bo));
            }
            uint32_t bh[4][4], bl[4][4];
#pragma unroll
            for (int bq = 0; bq < 4; bq++) {
                uint32_t bo = (uint32_t)((wn * 64 + bq * 16 + b_row) * 128 + ks * 32 + b_cb);
                uint32_t sw = swz(bo);
                ldsm4(bh[bq], base + 32768 + sw);
                ldsm4(bl[bq], base + 49152 + sw);
            }
            // 2 passes: A*Bh then A*Bl (same-acc reuse distance = 32 MMAs)
#pragma unroll
            for (int mf = 0; mf < 4; mf++)
#pragma unroll
                for (int bq = 0; bq < 4; bq++) {
                    mma16816(acc[mf][2 * bq],     av[mf], &bh[bq][0]);
                    mma16816(acc[mf][2 * bq + 1], av[mf], &bh[bq][2]);
                }
#pragma unroll
            for (int mf = 0; mf < 4; mf++)
#pragma unroll
                for (int bq = 0; bq < 4; bq++) {
                    mma16816(acc[mf][2 * bq],     av[mf], &bl[bq][0]);
                    mma16816(acc[mf][2 * bq + 1], av[mf], &bl[bq][2]);
                }
        }
        __syncthreads();
    }

    const int r_in = lane >> 2, c_in = (lane & 3) * 2;
#pragma unroll
    for (int mf = 0; mf < 4; mf++)
#pragma unroll
        for (int nf = 0; nf < 8; nf++) {
            int row0 = mbase + wm * 64 + mf * 16 + r_in;
            int col  = nbase + wn * 64 + nf * 8 + c_in;
            if (col >= Nout) continue;
            float* q = acc[mf][nf];
            float e0 = repi(q[0], epi, extra, col);
            float e1 = repi(q[1], epi, extra, col + 1);
            float e2 = repi(q[2], epi, extra, col);
            float e3 = repi(q[3], epi, extra, col + 1);
            if (Ch == nullptr) {
                *(float2*)(Cf + (size_t)row0 * Nout + col) = make_float2(e0, e1);
                *(float2*)(Cf + (size_t)(row0 + 8) * Nout + col) = make_float2(e2, e3);
            } else {
                *(__half2*)(Ch + (size_t)row0 * Nout + col) =
                    __floats2half2_rn(e0, e1);
                *(__half2*)(Ch + (size_t)(row0 + 8) * Nout + col) =
                    __floats2half2_rn(e2, e3);
            }
        }
}

__global__ void __launch_bounds__(256, 1) gemm_one(
    const __half* __restrict__ A,
    const __half* __restrict__ Bh, const __half* __restrict__ Bl,
    float* __restrict__ Cf, __half* __restrict__ Ch,
    int Nout, int K, const float* __restrict__ extra, int epi)
{
    gemm_core(A, Bh, Bl, Cf, Ch, Nout, K, extra, epi);
}

// z = 0..3: r/k/v/g big GEMMs. z = 4: small td1 GEMM (overlapped).
__global__ void __launch_bounds__(256, 1) gemm_rkvg(
    const __half* rxh, const __half* wrh, const __half* wrl, float* r,
    const __half* kxh, const __half* wkh, const __half* wkl, float* k,
    const __half* vxh, const __half* wvh, const __half* wvl, float* v,
    const __half* gxh, const __half* wgh, const __half* wgl, float* g,
    const __half* wxh, const __half* td1h, const __half* td1l, __half* h1h)
{
    if (blockIdx.z == 4) {
        if (blockIdx.x != 0) return;
        gemm_core(wxh, td1h, td1l, nullptr, h1h, 64, Dd, nullptr, 2);
        return;
    }
    const __half *A, *Bh, *Bl; float* C; int epi;
    switch (blockIdx.z) {
        case 0:  A = rxh; Bh = wrh; Bl = wrl; C = r; epi = 1; break;
        case 1:  A = kxh; Bh = wkh; Bl = wkl; C = k; epi = 0; break;
        case 2:  A = vxh; Bh = wvh; Bl = wvl; C = v; epi = 0; break;
        default: A = gxh; Bh = wgh; Bl = wgl; C = g; epi = 3; break;
    }
    gemm_core(A, Bh, Bl, C, nullptr, Dd, Dd, nullptr, epi);
}

// ====================== all weight transposes + fp16 splits in ONE launch ===
struct TsArgs {
    const float* src[8];
    __half* bh[8];
    __half* bl[8];
    int K[8], N[8], gx[8], gy[8];
};

__global__ void __launch_bounds__(256) tsplit_all(TsArgs a)
{
    const int z = blockIdx.z;
    if ((int)blockIdx.x >= a.gx[z] || (int)blockIdx.y >= a.gy[z]) return;
    const float* __restrict__ W = a.src[z];
    __half* __restrict__ bh = a.bh[z];
    __half* __restrict__ bl = a.bl[z];
    const int K = a.K[z], N = a.N[z];

    __shared__ float t[32][33];
    const int k0 = blockIdx.x * 32, n0 = blockIdx.y * 32;
    const int tx = threadIdx.x & 31, ty = threadIdx.x >> 5;
#pragma unroll
    for (int i = 0; i < 4; i++) {
        int kk = ty + i * 8;
        int n = n0 + tx;
        t[kk][tx] = (n < N) ? W[(size_t)(k0 + kk) * N + n] : 0.f;
    }
    __syncthreads();
#pragma unroll
    for (int i = 0; i < 4; i++) {
        int nn = ty + i * 8;
        float v = t[tx][nn];
        __half h = __float2half_rn(v);
        size_t o = (size_t)(n0 + nn) * K + k0 + tx;
        bh[o] = h;
        bl[o] = __float2half_rn(v - __half2float(h));
    }
}

// ====================== prep: xxx -> fp16 ===================================
__global__ void __launch_bounds__(256) prep_k(
    const float* __restrict__ x, const float* __restrict__ prev,
    const float* __restrict__ xmaa, __half* __restrict__ xh)
{
    size_t i = (size_t)blockIdx.x * 256 + threadIdx.x;
    int d = (int)(i % Dd);
    size_t bt = i / Dd;
    int t = (int)(bt % Tt);
    int b = (int)(bt / Tt);
    float xv = x[i];
    float sh = (t == 0) ? prev[(size_t)b * Dd + d] : x[i - Dd];
    float s = sh - xv;
    xh[i] = __float2half_rn(fmaf(s, xmaa[d], xv));
}

// ====================== mix: transposed msh + cp.async tiles ================
__global__ void __launch_bounds__(256) mix_k(
    const float* __restrict__ x, const float* __restrict__ prev,
    const float* __restrict__ m, const float* __restrict__ tmw2,
    const float* __restrict__ wmaa, const float* __restrict__ kmaa,
    const float* __restrict__ vmaa, const float* __restrict__ rmaa,
    const float* __restrict__ gmaa,
    __half* __restrict__ wxh, __half* __restrict__ kxh,
    __half* __restrict__ vxh, __half* __restrict__ rxh,
    __half* __restrict__ gxh)
{
    __shared__ float msh[E5c][8];
    __shared__ float tile[2][32][256];
    const int tid = threadIdx.x;
    const int dbase = blockIdx.x * 256;
    const int tb = blockIdx.y * 8;

#pragma unroll
    for (int i = 0; i < 8; i++) {
        int j = i * 256 + tid;
        int e = j >> 6, c4 = (j & 63) << 2;
        CP_ASYNC16(smem_u32(&tile[0][e][c4]),
                   tmw2 + (size_t)e * Dd + dbase + c4);
    }
    CP_COMMIT();

    for (int i = tid; i < 8 * E5c; i += 256) {
        int tok = i / E5c, e5 = i % E5c;
        msh[e5][tok] = m[(size_t)(tb + tok) * E5c + e5];
    }

    float acc[8][5];
#pragma unroll
    for (int tok = 0; tok < 8; tok++)
#pragma unroll
        for (int f = 0; f < 5; f++) acc[tok][f] = 0.f;

#pragma unroll
    for (int f = 0; f < 5; f++) {
        if (f + 1 < 5) {
            const int nb = (f + 1) & 1;
#pragma unroll
            for (int i = 0; i < 8; i++) {
                int j = i * 256 + tid;
                int e = j >> 6, c4 = (j & 63) << 2;
                CP_ASYNC16(smem_u32(&tile[nb][e][c4]),
                           tmw2 + (size_t)((f + 1) * 32 + e) * Dd + dbase + c4);
            }
            CP_COMMIT();
            CP_WAIT1();
        } else {
            CP_WAIT0();
        }
        __syncthreads();

        const int cb = f & 1;
#pragma unroll
        for (int e = 0; e < 32; e++) {
            float tv = tile[cb][e][tid];
            float4 m0 = *(const float4*)&msh[f * 32 + e][0];
            float4 m1 = *(const float4*)&msh[f * 32 + e][4];
            acc[0][f] = fmaf(m0.x, tv, acc[0][f]);
            acc[1][f] = fmaf(m0.y, tv, acc[1][f]);
            acc[2][f] = fmaf(m0.z, tv, acc[2][f]);
            acc[3][f] = fmaf(m0.w, tv, acc[3][f]);
            acc[4][f] = fmaf(m1.x, tv, acc[4][f]);
            acc[5][f] = fmaf(m1.y, tv, acc[5][f]);
            acc[6][f] = fmaf(m1.z, tv, acc[6][f]);
            acc[7][f] = fmaf(m1.w, tv, acc[7][f]);
        }
        __syncthreads();
    }

    const int d = dbase + tid;
    const float wm = wmaa[d], km = kmaa[d], vm = vmaa[d], rm = rmaa[d], gm = gmaa[d];
#pragma unroll
    for (int tok = 0; tok < 8; tok++) {
        int bt = tb + tok;
        int t = bt & (Tt - 1), b = bt >> 11;
        size_t idx = (size_t)bt * Dd + d;
        float xv = x[idx];
        float sh = (t == 0) ? prev[(size_t)b * Dd + d] : x[idx - Dd];
        float sv = sh - xv;
        wxh[idx] = __float2half_rn(fmaf(sv, wm + acc[tok][0], xv));
        kxh[idx] = __float2half_rn(fmaf(sv, km + acc[tok][1], xv));
        vxh[idx] = __float2half_rn(fmaf(sv, vm + acc[tok][2], xv));
        rxh[idx] = __float2half_rn(fmaf(sv, rm + acc[tok][3], xv));
        gxh[idx] = __float2half_rn(fmaf(sv, gm + acc[tok][4], xv));
    }
}

// ====================== WKV scan: u in regs, cp.async pipelined =============
__global__ void __launch_bounds__(256) wkv_k(
    const float* __restrict__ r, const float* __restrict__ k,
    const float* __restrict__ v, const float* __restrict__ w,
    const float* __restrict__ u, const float* __restrict__ s0,
    float* __restrict__ att, float* __restrict__ sout)
{
    __shared__ float rs[3][8][64], ksm[3][8][64], wsm[3][8][64], vsm[3][8][64];
    __shared__ float osh[3][8][64];

    const int bh = blockIdx.x, b = bh >> 5, h = bh & 31;
    const int tid = threadIdx.x;
    const int vcol = tid >> 2, kg = tid & 3;
    const int st_ = tid >> 5;
    const int si  = (tid & 31) * 2;

    const size_t base0 = (size_t)b * Tt * Dd + h * 64;
    const size_t sbase = (size_t)bh * 4096;

    float s[16], uo[16];
#pragma unroll
    for (int j = 0; j < 16; j++) {
        s[j]  = s0[sbase + (size_t)(kg * 16 + j) * 64 + vcol];
        uo[j] = u[h * 64 + kg * 16 + j];
    }

    {
        size_t g = base0 + (size_t)st_ * Dd + si;
        CP_ASYNC8(smem_u32(&rs[0][st_][si]),  r + g);
        CP_ASYNC8(smem_u32(&ksm[0][st_][si]), k + g);
        CP_ASYNC8(smem_u32(&wsm[0][st_][si]), w + g);
        CP_ASYNC8(smem_u32(&vsm[0][st_][si]), v + g);
        CP_COMMIT();
    }

    const int NB = Tt / 8;
    int buf = 0;
    for (int nb = 0; nb < NB; nb++) {
        buf = nb % 3;
        const int nxt = (nb + 1) % 3;
        if (nb + 1 < NB) {
            size_t g = base0 + (size_t)((nb + 1) * 8 + st_) * Dd + si;
            CP_ASYNC8(smem_u32(&rs[nxt][st_][si]),  r + g);
            CP_ASYNC8(smem_u32(&ksm[nxt][st_][si]), k + g);
            CP_ASYNC8(smem_u32(&wsm[nxt][st_][si]), w + g);
            CP_ASYNC8(smem_u32(&vsm[nxt][st_][si]), v + g);
            CP_COMMIT();
            CP_WAIT1();
        } else {
            CP_WAIT0();
        }
        __syncthreads();

        if (nb > 0) {
            const int pb = (nb - 1) % 3;
            *(float2*)&att[base0 + (size_t)((nb - 1) * 8 + st_) * Dd + si] =
                *(const float2*)&osh[pb][st_][si];
        }

#pragma unroll
        for (int t = 0; t < 8; t++) {
            const float vm = vsm[buf][t][vcol];
            float a = 0.f;
            const float* rp = &rs[buf][t][kg * 16];
            const float* kp = &ksm[buf][t][kg * 16];
            const float* wp = &wsm[buf][t][kg * 16];
#pragma unroll
            for (int q = 0; q < 4; q++) {
                float4 r4 = *(const float4*)(rp + 4 * q);
                float4 k4 = *(const float4*)(kp + 4 * q);
                float4 w4 = *(const float4*)(wp + 4 * q);
                float kv, tt;
                kv = k4.x * vm; tt = fmaf(uo[4*q+0], kv, s[4*q+0]); a = fmaf(r4.x, tt, a); s[4*q+0] = fmaf(s[4*q+0], w4.x, kv);
                kv = k4.y * vm; tt = fmaf(uo[4*q+1], kv, s[4*q+1]); a = fmaf(r4.y, tt, a); s[4*q+1] = fmaf(s[4*q+1], w4.y, kv);
                kv = k4.z * vm; tt = fmaf(uo[4*q+2], kv, s[4*q+2]); a = fmaf(r4.z, tt, a); s[4*q+2] = fmaf(s[4*q+2], w4.z, kv);
                kv = k4.w * vm; tt = fmaf(uo[4*q+3], kv, s[4*q+3]); a = fmaf(r4.w, tt, a); s[4*q+3] = fmaf(s[4*q+3], w4.w, kv);
            }
            a += __shfl_xor_sync(0xffffffffu, a, 1);
            a += __shfl_xor_sync(0xffffffffu, a, 2);
            if (kg == 0) osh[buf][t][vcol] = a;
        }
    }
    __syncthreads();
    *(float2*)&att[base0 + (size_t)((NB - 1) * 8 + st_) * Dd + si] =
        *(const float2*)&osh[buf][st_][si];
#pragma unroll
    for (int j = 0; j < 16; j++)
        sout[sbase + (size_t)(kg * 16 + j) * 64 + vcol] = s[j];
}

// ====================== groupnorm + ln + *g, writes fp16 ====================
__global__ void __launch_bounds__(256) gnorm_k(
    const float* __restrict__ att, const float* __restrict__ g,
    const float* __restrict__ lng, const float* __restrict__ lnb,
    __half* __restrict__ oh)
{
    const int grp = blockIdx.x * 8 + (threadIdx.x >> 5);
    const int lane = threadIdx.x & 31;
    const int bt = grp >> 5;
    const int h = grp & 31;
    size_t base = (size_t)bt * Dd + h * 64;
    float v0 = att[base + lane];
    float v1 = att[base + lane + 32];
    float sum = v0 + v1;
    float sq = v0 * v0 + v1 * v1;
#pragma unroll
    for (int o = 16; o > 0; o >>= 1) {
        sum += __shfl_xor_sync(0xffffffffu, sum, o);
        sq  += __shfl_xor_sync(0xffffffffu, sq, o);
    }
    float mu = sum * (1.f / 64.f);
    float var = sq * (1.f / 64.f) - mu * mu;
    float inv = rsqrtf(var + 1e-5f);
    int li = h * 64 + lane;
    oh[base + lane] = __float2half_rn(
        fmaf((v0 - mu) * inv, lng[li], lnb[li]) * g[base + lane]);
    oh[base + lane + 32] = __float2half_rn(
        fmaf((v1 - mu) * inv, lng[li + 32], lnb[li + 32]) * g[base + lane + 32]);
}

// ====================== copy x[:, -1, :] ====================================
__global__ void __launch_bounds__(256) lastcopy_k(const float* __restrict__ x,
                                                  float* __restrict__ o)
{
    int i = blockIdx.x * 256 + threadIdx.x;
    int b = i / Dd, d = i % Dd;
    o[i] = x[((size_t)b * Tt + (Tt - 1)) * Dd + d];
}

// ====================== host ================================================
extern "C" void kernel_launch(void* const* d_in, const int* in_sizes, int n_in,
                              void* d_out, int out_size)
{
    const float* x     = (const float*)d_in[0];
    const float* prev  = (const float*)d_in[1];
    const float* state = (const float*)d_in[2];
    const float* x_maa = (const float*)d_in[3];
    const float* w_maa = (const float*)d_in[4];
    const float* k_maa = (const float*)d_in[5];
    const float* v_maa = (const float*)d_in[6];
    const float* r_maa = (const float*)d_in[7];
    const float* g_maa = (const float*)d_in[8];
    const float* tm_w1 = (const float*)d_in[9];
    const float* tm_w2 = (const float*)d_in[10];
    const float* td_w1 = (const float*)d_in[11];
    const float* td_w2 = (const float*)d_in[12];
    const float* tdec  = (const float*)d_in[13];
    const float* tfirst= (const float*)d_in[14];
    const float* W_r   = (const float*)d_in[15];
    const float* W_k   = (const float*)d_in[16];
    const float* W_v   = (const float*)d_in[17];
    const float* W_g   = (const float*)d_in[18];
    const float* W_o   = (const float*)d_in[19];
    const float* ln_g  = (const float*)d_in[20];
    const float* ln_b  = (const float*)d_in[21];

    float *m, *r, *k, *v, *g, *w, *att;
    cudaGetSymbolAddress((void**)&m,   g_m);
    cudaGetSymbolAddress((void**)&r,   g_r);
    cudaGetSymbolAddress((void**)&k,   g_k);
    cudaGetSymbolAddress((void**)&v,   g_v);
    cudaGetSymbolAddress((void**)&g,   g_g);
    cudaGetSymbolAddress((void**)&w,   g_w);
    cudaGetSymbolAddress((void**)&att, g_att);

    __half *xh, *wxh, *kxh, *vxh, *rxh, *gxh, *gnh, *h1h;
    __half *wrh, *wrl, *wkh, *wkl, *wvh, *wvl, *wgh, *wgl, *woh, *wol;
    __half *tm1h, *tm1l, *td1h, *td1l, *td2h, *td2l;
    cudaGetSymbolAddress((void**)&xh,  g_xh);
    cudaGetSymbolAddress((void**)&wxh, g_wxh);
    cudaGetSymbolAddress((void**)&kxh, g_kxh);
    cudaGetSymbolAddress((void**)&vxh, g_vxh);
    cudaGetSymbolAddress((void**)&rxh, g_rxh);
    cudaGetSymbolAddress((void**)&gxh, g_gxh);
    cudaGetSymbolAddress((void**)&gnh, g_gnh);
    cudaGetSymbolAddress((void**)&h1h, g_h1h);
    cudaGetSymbolAddress((void**)&wrh, g_wrh); cudaGetSymbolAddress((void**)&wrl, g_wrl);
    cudaGetSymbolAddress((void**)&wkh, g_wkh); cudaGetSymbolAddress((void**)&wkl, g_wkl);
    cudaGetSymbolAddress((void**)&wvh, g_wvh); cudaGetSymbolAddress((void**)&wvl, g_wvl);
    cudaGetSymbolAddress((void**)&wgh, g_wgh); cudaGetSymbolAddress((void**)&wgl, g_wgl);
    cudaGetSymbolAddress((void**)&woh, g_woh); cudaGetSymbolAddress((void**)&wol, g_wol);
    cudaGetSymbolAddress((void**)&tm1h, g_tm1h); cudaGetSymbolAddress((void**)&tm1l, g_tm1l);
    cudaGetSymbolAddress((void**)&td1h, g_td1h); cudaGetSymbolAddress((void**)&td1l, g_td1l);
    cudaGetSymbolAddress((void**)&td2h, g_td2h); cudaGetSymbolAddress((void**)&td2l, g_td2l);

    float* out0 = (float*)d_out;
    float* out_xlast = out0 + (size_t)BT * Dd;
    float* out_state = out_xlast + (size_t)Bb * Dd;

    cudaFuncSetAttribute(gemm_one,  cudaFuncAttributeMaxDynamicSharedMemorySize, GEMM_SMEM);
    cudaFuncSetAttribute(gemm_rkvg, cudaFuncAttributeMaxDynamicSharedMemorySize, GEMM_SMEM);

    // ---- [0] all 8 weight transposes+splits ----
    TsArgs ta;
    ta.src[0]=W_r;  ta.bh[0]=wrh;  ta.bl[0]=wrl;  ta.K[0]=Dd; ta.N[0]=Dd;  ta.gx[0]=64; ta.gy[0]=64;
    ta.src[1]=W_k;  ta.bh[1]=wkh;  ta.bl[1]=wkl;  ta.K[1]=Dd; ta.N[1]=Dd;  ta.gx[1]=64; ta.gy[1]=64;
    ta.src[2]=W_v;  ta.bh[2]=wvh;  ta.bl[2]=wvl;  ta.K[2]=Dd; ta.N[2]=Dd;  ta.gx[2]=64; ta.gy[2]=64;
    ta.src[3]=W_g;  ta.bh[3]=wgh;  ta.bl[3]=wgl;  ta.K[3]=Dd; ta.N[3]=Dd;  ta.gx[3]=64; ta.gy[3]=64;
    ta.src[4]=W_o;  ta.bh[4]=woh;  ta.bl[4]=wol;  ta.K[4]=Dd; ta.N[4]=Dd;  ta.gx[4]=64; ta.gy[4]=64;
    ta.src[5]=tm_w1;ta.bh[5]=tm1h; ta.bl[5]=tm1l; ta.K[5]=Dd; ta.N[5]=E5c; ta.gx[5]=64; ta.gy[5]=8;
    ta.src[6]=td_w1;ta.bh[6]=td1h; ta.bl[6]=td1l; ta.K[6]=Dd; ta.N[6]=64;  ta.gx[6]=64; ta.gy[6]=4;
    ta.src[7]=td_w2;ta.bh[7]=td2h; ta.bl[7]=td2l; ta.K[7]=64; ta.N[7]=Dd;  ta.gx[7]=2;  ta.gy[7]=64;
    tsplit_all<<<dim3(64, 64, 8), 256>>>(ta);

    // ---- [1] shift + fp16(xxx) ----
    prep_k<<<(BT * Dd) / 256, 256>>>(x, prev, x_maa, xh);
    // ---- [2] m = tanh(xxx @ tm_w1) ----
    gemm_one<<<dim3(2, BT/256), 256, GEMM_SMEM>>>(xh, tm1h, tm1l,
        m, nullptr, E5c, Dd, nullptr, 2);
    // ---- [3] mix + 5 lerps (fp16) ----
    mix_k<<<dim3(Dd/256, BT/8), 256>>>(x, prev, m, tm_w2,
        w_maa, k_maa, v_maa, r_maa, g_maa,
        wxh, kxh, vxh, rxh, gxh);
    // ---- [4] x[:, -1] ----
    lastcopy_k<<<(Bb * Dd) / 256, 256>>>(x, out_xlast);
    // ---- [5] big GEMMs r/k/v/g + overlapped td1 (z=4) ----
    gemm_rkvg<<<dim3(Dd/128, BT/256, 5), 256, GEMM_SMEM>>>(
        rxh, wrh, wrl, r,
        kxh, wkh, wkl, k,
        vxh, wvh, wvl, v,
        gxh, wgh, wgl, g,
        wxh, td1h, td1l, h1h);
    // ---- [6] td2: w = exp(-exp(h1 @ td_w2 + decay)) ----
    gemm_one<<<dim3(Dd/128, BT/256), 256, GEMM_SMEM>>>(h1h, td2h, td2l,
        w, nullptr, Dd, 64, tdec, 4);
    // ---- [7] WKV scan ----
    wkv_k<<<Bb * Hh, 256>>>(r, k, v, w, tfirst, state, att, out_state);
    // ---- [8] groupnorm * ln * g (fp16) ----
    gnorm_k<<<(BT * Hh) / 8, 256>>>(att, g, ln_g, ln_b, gnh);
    // ---- [9] out = gn @ W_o ----
    gemm_one<<<dim3(Dd/128, BT/256), 256, GEMM_SMEM>>>(gnh, woh, wol,
        out0, nullptr, Dd, Dd, nullptr, 0);
}

// round 11
// speedup vs baseline: 6.9776x; 1.2373x over previous
#include <cuda_runtime.h>
#include <cuda_fp16.h>
#include <math.h>
#include <stdint.h>

#define Bb 4
#define Tt 2048
#define Dd 2048
#define Hh 32
#define HSz 64
#define BT (Bb*Tt)
#define E5c 160

// ====================== device scratch (bss, no alloc) ======================
__device__ float g_m  [BT*E5c];
__device__ float g_r  [BT*Dd];
__device__ float g_k  [BT*Dd];
__device__ float g_v  [BT*Dd];
__device__ float g_g  [BT*Dd];
__device__ float g_w  [BT*Dd];
__device__ float g_att[BT*Dd];

__device__ __half g_xh [BT*Dd];
__device__ __half g_wxh[BT*Dd];
__device__ __half g_kxh[BT*Dd];
__device__ __half g_vxh[BT*Dd];
__device__ __half g_rxh[BT*Dd];
__device__ __half g_gxh[BT*Dd];
__device__ __half g_gnh[BT*Dd];
__device__ __half g_h1h[BT*64];

__device__ __half g_wrh[Dd*Dd];
__device__ __half g_wkh[Dd*Dd];
__device__ __half g_wvh[Dd*Dd];
__device__ __half g_wgh[Dd*Dd];
__device__ __half g_woh[Dd*Dd], g_wol[Dd*Dd];   // W_o keeps exact split
__device__ __half g_tm1h[256*Dd];
__device__ __half g_td1h[128*Dd];
__device__ __half g_td2h[Dd*64];

// ====================== PTX helpers (sm_80-class only) ======================
__device__ __forceinline__ uint32_t smem_u32(const void* p) {
    uint32_t a;
    asm("{ .reg .u64 t; cvta.to.shared.u64 t, %1; cvt.u32.u64 %0, t; }"
        : "=r"(a) : "l"(p));
    return a;
}

#define CP_ASYNC16(dst, src) \
    asm volatile("cp.async.cg.shared.global [%0], [%1], 16;" \
        :: "r"(dst), "l"(src) : "memory")
#define CP_ASYNC8(dst, src) \
    asm volatile("cp.async.ca.shared.global [%0], [%1], 8;" \
        :: "r"(dst), "l"(src) : "memory")
#define CP_COMMIT() asm volatile("cp.async.commit_group;" ::: "memory")
#define CP_WAIT0()  asm volatile("cp.async.wait_group 0;" ::: "memory")
#define CP_WAIT1()  asm volatile("cp.async.wait_group 1;" ::: "memory")
#define CP_WAIT2()  asm volatile("cp.async.wait_group 2;" ::: "memory")

__device__ __forceinline__ void ldsm4(uint32_t* r, uint32_t addr) {
    asm volatile("ldmatrix.sync.aligned.m8n8.x4.shared.b16 {%0,%1,%2,%3},[%4];"
        : "=r"(r[0]), "=r"(r[1]), "=r"(r[2]), "=r"(r[3]) : "r"(addr));
}

__device__ __forceinline__ void mma16816(float* c, const uint32_t* a, const uint32_t* b) {
    asm volatile(
        "mma.sync.aligned.m16n8k16.row.col.f32.f16.f16.f32 "
        "{%0,%1,%2,%3},{%4,%5,%6,%7},{%8,%9},{%0,%1,%2,%3};"
        : "+f"(c[0]), "+f"(c[1]), "+f"(c[2]), "+f"(c[3])
        : "r"(a[0]), "r"(a[1]), "r"(a[2]), "r"(a[3]), "r"(b[0]), "r"(b[1]));
}

__device__ __forceinline__ uint32_t swz(uint32_t bo) { return bo ^ ((bo >> 3) & 0x70); }

// ====================== tensor-core GEMM (HMMA fp16, 256x128 tile) ==========
__device__ __forceinline__ float repi(float v, int epi, const float* extra, int n) {
    switch (epi) {
        case 1: return 1.f / (1.f + expf(-v));
        case 2: return tanhf(v);
        case 3: return v / (1.f + expf(-v));
        case 4: return expf(-expf(v + extra[n]));
        default: return v;
    }
}

template<int ROWS>
__device__ __forceinline__ void load_tile_async(uint32_t sbase,
    const __half* __restrict__ src, int row0, int k0, int ldK, int tid)
{
#pragma unroll
    for (int i = 0; i < ROWS / 32; i++) {
        int u = i * 256 + tid;
        int row = u >> 3, cc = u & 7;
        uint32_t bo = (uint32_t)(row * 128 + cc * 16);
        CP_ASYNC16(sbase + swz(bo),
                   src + (size_t)(row0 + row) * ldK + k0 + cc * 8);
    }
}

// SPLIT=0: stage = A 32K + B 16K = 48K; SPLIT=1: +Bl 16K = 64K. 3 stages.
#define ST0 49152u
#define ST1 65536u
#define GEMM_SMEM0 (3 * ST0)    // 147456
#define GEMM_SMEM1 (3 * ST1)    // 196608

template<int SPLIT>
__device__ __forceinline__ void gemm_stage(uint32_t st,
    const __half* A, const __half* Bh, const __half* Bl,
    int mbase, int nbase, int k0, int K, int tid)
{
    load_tile_async<256>(st +     0, A,  mbase, k0, K, tid);
    load_tile_async<128>(st + 32768, Bh, nbase, k0, K, tid);
    if (SPLIT) load_tile_async<128>(st + 49152, Bl, nbase, k0, K, tid);
    CP_COMMIT();
}

template<int SPLIT>
__device__ __forceinline__ void gemm_core(
    const __half* __restrict__ A,
    const __half* __restrict__ Bh, const __half* __restrict__ Bl,
    float* __restrict__ Cf, __half* __restrict__ Ch,
    int Nout, int K, const float* __restrict__ extra, int epi)
{
    extern __shared__ char sm[];
    const uint32_t sb = smem_u32(sm);
    const uint32_t ST = SPLIT ? ST1 : ST0;
    const int tid = threadIdx.x, lane = tid & 31, wid = tid >> 5;
    const int wm = wid >> 1, wn = wid & 1;           // 4 x 2 warps, warp tile 64x64
    const int mbase = blockIdx.y * 256, nbase = blockIdx.x * 128;

    float acc[4][8][4];
#pragma unroll
    for (int mf = 0; mf < 4; mf++)
#pragma unroll
        for (int nf = 0; nf < 8; nf++)
#pragma unroll
            for (int q = 0; q < 4; q++) acc[mf][nf][q] = 0.f;

    const int nc = K / 64;
    gemm_stage<SPLIT>(sb, A, Bh, Bl, mbase, nbase, 0, K, tid);
    if (nc > 1)
        gemm_stage<SPLIT>(sb + ST, A, Bh, Bl, mbase, nbase, 64, K, tid);

    const int a_row = (lane & 15);
    const int a_cb  = ((lane >> 4) & 1) * 16;
    const int mat   = lane >> 3;
    const int b_row = (lane & 7) + ((mat >> 1) & 1) * 8;
    const int b_cb  = (mat & 1) * 16;

    for (int c = 0; c < nc; c++) {
        if (c + 2 < nc) {
            gemm_stage<SPLIT>(sb + ((c + 2) % 3) * ST, A, Bh, Bl,
                              mbase, nbase, (c + 2) * 64, K, tid);
            CP_WAIT2();
        } else if (c + 1 < nc) {
            CP_WAIT1();
        } else {
            CP_WAIT0();
        }
        __syncthreads();

        const uint32_t base = sb + (c % 3) * ST;
#pragma unroll
        for (int ks = 0; ks < 4; ks++) {
            uint32_t av[4][4];
#pragma unroll
            for (int mf = 0; mf < 4; mf++) {
                uint32_t bo = (uint32_t)((wm * 64 + mf * 16 + a_row) * 128 + ks * 32 + a_cb);
                ldsm4(av[mf], base + swz(bo));
            }
            uint32_t bh[4][4];
#pragma unroll
            for (int bq = 0; bq < 4; bq++) {
                uint32_t bo = (uint32_t)((wn * 64 + bq * 16 + b_row) * 128 + ks * 32 + b_cb);
                ldsm4(bh[bq], base + 32768 + swz(bo));
            }
#pragma unroll
            for (int mf = 0; mf < 4; mf++)
#pragma unroll
                for (int bq = 0; bq < 4; bq++) {
                    mma16816(acc[mf][2 * bq],     av[mf], &bh[bq][0]);
                    mma16816(acc[mf][2 * bq + 1], av[mf], &bh[bq][2]);
                }
            if (SPLIT) {
                uint32_t bl[4][4];
#pragma unroll
                for (int bq = 0; bq < 4; bq++) {
                    uint32_t bo = (uint32_t)((wn * 64 + bq * 16 + b_row) * 128 + ks * 32 + b_cb);
                    ldsm4(bl[bq], base + 49152 + swz(bo));
                }
#pragma unroll
                for (int mf = 0; mf < 4; mf++)
#pragma unroll
                    for (int bq = 0; bq < 4; bq++) {
                        mma16816(acc[mf][2 * bq],     av[mf], &bl[bq][0]);
                        mma16816(acc[mf][2 * bq + 1], av[mf], &bl[bq][2]);
                    }
            }
        }
        __syncthreads();
    }

    const int r_in = lane >> 2, c_in = (lane & 3) * 2;
#pragma unroll
    for (int mf = 0; mf < 4; mf++)
#pragma unroll
        for (int nf = 0; nf < 8; nf++) {
            int row0 = mbase + wm * 64 + mf * 16 + r_in;
            int col  = nbase + wn * 64 + nf * 8 + c_in;
            if (col >= Nout) continue;
            float* q = acc[mf][nf];
            float e0 = repi(q[0], epi, extra, col);
            float e1 = repi(q[1], epi, extra, col + 1);
            float e2 = repi(q[2], epi, extra, col);
            float e3 = repi(q[3], epi, extra, col + 1);
            if (Ch == nullptr) {
                *(float2*)(Cf + (size_t)row0 * Nout + col) = make_float2(e0, e1);
                *(float2*)(Cf + (size_t)(row0 + 8) * Nout + col) = make_float2(e2, e3);
            } else {
                *(__half2*)(Ch + (size_t)row0 * Nout + col) =
                    __floats2half2_rn(e0, e1);
                *(__half2*)(Ch + (size_t)(row0 + 8) * Nout + col) =
                    __floats2half2_rn(e2, e3);
            }
        }
}

template<int SPLIT>
__global__ void __launch_bounds__(256, 1) gemm_one(
    const __half* __restrict__ A,
    const __half* __restrict__ Bh, const __half* __restrict__ Bl,
    float* __restrict__ Cf, __half* __restrict__ Ch,
    int Nout, int K, const float* __restrict__ extra, int epi)
{
    gemm_core<SPLIT>(A, Bh, Bl, Cf, Ch, Nout, K, extra, epi);
}

// z = 0..3: r/k/v/g big GEMMs. z = 4: small td1 GEMM (overlapped).
__global__ void __launch_bounds__(256, 1) gemm_rkvg(
    const __half* rxh, const __half* wrh, float* r,
    const __half* kxh, const __half* wkh, float* k,
    const __half* vxh, const __half* wvh, float* v,
    const __half* gxh, const __half* wgh, float* g,
    const __half* wxh, const __half* td1h, __half* h1h)
{
    if (blockIdx.z == 4) {
        if (blockIdx.x != 0) return;
        gemm_core<0>(wxh, td1h, nullptr, nullptr, h1h, 64, Dd, nullptr, 2);
        return;
    }
    const __half *A, *Bh; float* C; int epi;
    switch (blockIdx.z) {
        case 0:  A = rxh; Bh = wrh; C = r; epi = 1; break;
        case 1:  A = kxh; Bh = wkh; C = k; epi = 0; break;
        case 2:  A = vxh; Bh = wvh; C = v; epi = 0; break;
        default: A = gxh; Bh = wgh; C = g; epi = 3; break;
    }
    gemm_core<0>(A, Bh, nullptr, C, nullptr, Dd, Dd, nullptr, epi);
}

// ====================== all weight transposes + fp16 (opt split) ============
struct TsArgs {
    const float* src[8];
    __half* bh[8];
    __half* bl[8];      // nullptr -> no lo term
    int K[8], N[8], gx[8], gy[8];
};

__global__ void __launch_bounds__(256) tsplit_all(TsArgs a)
{
    const int z = blockIdx.z;
    if ((int)blockIdx.x >= a.gx[z] || (int)blockIdx.y >= a.gy[z]) return;
    const float* __restrict__ W = a.src[z];
    __half* __restrict__ bh = a.bh[z];
    __half* __restrict__ bl = a.bl[z];
    const int K = a.K[z], N = a.N[z];

    __shared__ float t[32][33];
    const int k0 = blockIdx.x * 32, n0 = blockIdx.y * 32;
    const int tx = threadIdx.x & 31, ty = threadIdx.x >> 5;
#pragma unroll
    for (int i = 0; i < 4; i++) {
        int kk = ty + i * 8;
        int n = n0 + tx;
        t[kk][tx] = (n < N) ? W[(size_t)(k0 + kk) * N + n] : 0.f;
    }
    __syncthreads();
#pragma unroll
    for (int i = 0; i < 4; i++) {
        int nn = ty + i * 8;
        float v = t[tx][nn];
        __half h = __float2half_rn(v);
        size_t o = (size_t)(n0 + nn) * K + k0 + tx;
        bh[o] = h;
        if (bl) bl[o] = __float2half_rn(v - __half2float(h));
    }
}

// ====================== prep: xxx -> fp16 ===================================
__global__ void __launch_bounds__(256) prep_k(
    const float* __restrict__ x, const float* __restrict__ prev,
    const float* __restrict__ xmaa, __half* __restrict__ xh)
{
    size_t i = (size_t)blockIdx.x * 256 + threadIdx.x;
    int d = (int)(i % Dd);
    size_t bt = i / Dd;
    int t = (int)(bt % Tt);
    int b = (int)(bt / Tt);
    float xv = x[i];
    float sh = (t == 0) ? prev[(size_t)b * Dd + d] : x[i - Dd];
    float s = sh - xv;
    xh[i] = __float2half_rn(fmaf(s, xmaa[d], xv));
}

// ====================== mix: transposed msh + cp.async tiles ================
__global__ void __launch_bounds__(256) mix_k(
    const float* __restrict__ x, const float* __restrict__ prev,
    const float* __restrict__ m, const float* __restrict__ tmw2,
    const float* __restrict__ wmaa, const float* __restrict__ kmaa,
    const float* __restrict__ vmaa, const float* __restrict__ rmaa,
    const float* __restrict__ gmaa,
    __half* __restrict__ wxh, __half* __restrict__ kxh,
    __half* __restrict__ vxh, __half* __restrict__ rxh,
    __half* __restrict__ gxh)
{
    __shared__ float msh[E5c][8];
    __shared__ float tile[2][32][256];
    const int tid = threadIdx.x;
    const int dbase = blockIdx.x * 256;
    const int tb = blockIdx.y * 8;

#pragma unroll
    for (int i = 0; i < 8; i++) {
        int j = i * 256 + tid;
        int e = j >> 6, c4 = (j & 63) << 2;
        CP_ASYNC16(smem_u32(&tile[0][e][c4]),
                   tmw2 + (size_t)e * Dd + dbase + c4);
    }
    CP_COMMIT();

    for (int i = tid; i < 8 * E5c; i += 256) {
        int tok = i / E5c, e5 = i % E5c;
        msh[e5][tok] = m[(size_t)(tb + tok) * E5c + e5];
    }

    float acc[8][5];
#pragma unroll
    for (int tok = 0; tok < 8; tok++)
#pragma unroll
        for (int f = 0; f < 5; f++) acc[tok][f] = 0.f;

#pragma unroll
    for (int f = 0; f < 5; f++) {
        if (f + 1 < 5) {
            const int nb = (f + 1) & 1;
#pragma unroll
            for (int i = 0; i < 8; i++) {
                int j = i * 256 + tid;
                int e = j >> 6, c4 = (j & 63) << 2;
                CP_ASYNC16(smem_u32(&tile[nb][e][c4]),
                           tmw2 + (size_t)((f + 1) * 32 + e) * Dd + dbase + c4);
            }
            CP_COMMIT();
            CP_WAIT1();
        } else {
            CP_WAIT0();
        }
        __syncthreads();

        const int cb = f & 1;
#pragma unroll
        for (int e = 0; e < 32; e++) {
            float tv = tile[cb][e][tid];
            float4 m0 = *(const float4*)&msh[f * 32 + e][0];
            float4 m1 = *(const float4*)&msh[f * 32 + e][4];
            acc[0][f] = fmaf(m0.x, tv, acc[0][f]);
            acc[1][f] = fmaf(m0.y, tv, acc[1][f]);
            acc[2][f] = fmaf(m0.z, tv, acc[2][f]);
            acc[3][f] = fmaf(m0.w, tv, acc[3][f]);
            acc[4][f] = fmaf(m1.x, tv, acc[4][f]);
            acc[5][f] = fmaf(m1.y, tv, acc[5][f]);
            acc[6][f] = fmaf(m1.z, tv, acc[6][f]);
            acc[7][f] = fmaf(m1.w, tv, acc[7][f]);
        }
        __syncthreads();
    }

    const int d = dbase + tid;
    const float wm = wmaa[d], km = kmaa[d], vm = vmaa[d], rm = rmaa[d], gm = gmaa[d];
#pragma unroll
    for (int tok = 0; tok < 8; tok++) {
        int bt = tb + tok;
        int t = bt & (Tt - 1), b = bt >> 11;
        size_t idx = (size_t)bt * Dd + d;
        float xv = x[idx];
        float sh = (t == 0) ? prev[(size_t)b * Dd + d] : x[idx - Dd];
        float sv = sh - xv;
        wxh[idx] = __float2half_rn(fmaf(sv, wm + acc[tok][0], xv));
        kxh[idx] = __float2half_rn(fmaf(sv, km + acc[tok][1], xv));
        vxh[idx] = __float2half_rn(fmaf(sv, vm + acc[tok][2], xv));
        rxh[idx] = __float2half_rn(fmaf(sv, rm + acc[tok][3], xv));
        gxh[idx] = __float2half_rn(fmaf(sv, gm + acc[tok][4], xv));
    }
}

// ====================== WKV scan: u in regs, cp.async pipelined =============
__global__ void __launch_bounds__(256) wkv_k(
    const float* __restrict__ r, const float* __restrict__ k,
    const float* __restrict__ v, const float* __restrict__ w,
    const float* __restrict__ u, const float* __restrict__ s0,
    float* __restrict__ att, float* __restrict__ sout)
{
    __shared__ float rs[3][8][64], ksm[3][8][64], wsm[3][8][64], vsm[3][8][64];
    __shared__ float osh[3][8][64];

    const int bh = blockIdx.x, b = bh >> 5, h = bh & 31;
    const int tid = threadIdx.x;
    const int vcol = tid >> 2, kg = tid & 3;
    const int st_ = tid >> 5;
    const int si  = (tid & 31) * 2;

    const size_t base0 = (size_t)b * Tt * Dd + h * 64;
    const size_t sbase = (size_t)bh * 4096;

    float s[16], uo[16];
#pragma unroll
    for (int j = 0; j < 16; j++) {
        s[j]  = s0[sbase + (size_t)(kg * 16 + j) * 64 + vcol];
        uo[j] = u[h * 64 + kg * 16 + j];
    }

    {
        size_t g = base0 + (size_t)st_ * Dd + si;
        CP_ASYNC8(smem_u32(&rs[0][st_][si]),  r + g);
        CP_ASYNC8(smem_u32(&ksm[0][st_][si]), k + g);
        CP_ASYNC8(smem_u32(&wsm[0][st_][si]), w + g);
        CP_ASYNC8(smem_u32(&vsm[0][st_][si]), v + g);
        CP_COMMIT();
    }

    const int NB = Tt / 8;
    int buf = 0;
    for (int nb = 0; nb < NB; nb++) {
        buf = nb % 3;
        const int nxt = (nb + 1) % 3;
        if (nb + 1 < NB) {
            size_t g = base0 + (size_t)((nb + 1) * 8 + st_) * Dd + si;
            CP_ASYNC8(smem_u32(&rs[nxt][st_][si]),  r + g);
            CP_ASYNC8(smem_u32(&ksm[nxt][st_][si]), k + g);
            CP_ASYNC8(smem_u32(&wsm[nxt][st_][si]), w + g);
            CP_ASYNC8(smem_u32(&vsm[nxt][st_][si]), v + g);
            CP_COMMIT();
            CP_WAIT1();
        } else {
            CP_WAIT0();
        }
        __syncthreads();

        if (nb > 0) {
            const int pb = (nb - 1) % 3;
            *(float2*)&att[base0 + (size_t)((nb - 1) * 8 + st_) * Dd + si] =
                *(const float2*)&osh[pb][st_][si];
        }

#pragma unroll
        for (int t = 0; t < 8; t++) {
            const float vm = vsm[buf][t][vcol];
            float a = 0.f;
            const float* rp = &rs[buf][t][kg * 16];
            const float* kp = &ksm[buf][t][kg * 16];
            const float* wp = &wsm[buf][t][kg * 16];
#pragma unroll
            for (int q = 0; q < 4; q++) {
                float4 r4 = *(const float4*)(rp + 4 * q);
                float4 k4 = *(const float4*)(kp + 4 * q);
                float4 w4 = *(const float4*)(wp + 4 * q);
                float kv, tt;
                kv = k4.x * vm; tt = fmaf(uo[4*q+0], kv, s[4*q+0]); a = fmaf(r4.x, tt, a); s[4*q+0] = fmaf(s[4*q+0], w4.x, kv);
                kv = k4.y * vm; tt = fmaf(uo[4*q+1], kv, s[4*q+1]); a = fmaf(r4.y, tt, a); s[4*q+1] = fmaf(s[4*q+1], w4.y, kv);
                kv = k4.z * vm; tt = fmaf(uo[4*q+2], kv, s[4*q+2]); a = fmaf(r4.z, tt, a); s[4*q+2] = fmaf(s[4*q+2], w4.z, kv);
                kv = k4.w * vm; tt = fmaf(uo[4*q+3], kv, s[4*q+3]); a = fmaf(r4.w, tt, a); s[4*q+3] = fmaf(s[4*q+3], w4.w, kv);
            }
            a += __shfl_xor_sync(0xffffffffu, a, 1);
            a += __shfl_xor_sync(0xffffffffu, a, 2);
            if (kg == 0) osh[buf][t][vcol] = a;
        }
    }
    __syncthreads();
    *(float2*)&att[base0 + (size_t)((NB - 1) * 8 + st_) * Dd + si] =
        *(const float2*)&osh[buf][st_][si];
#pragma unroll
    for (int j = 0; j < 16; j++)
        sout[sbase + (size_t)(kg * 16 + j) * 64 + vcol] = s[j];
}

// ====================== groupnorm + ln + *g, writes fp16 ====================
__global__ void __launch_bounds__(256) gnorm_k(
    const float* __restrict__ att, const float* __restrict__ g,
    const float* __restrict__ lng, const float* __restrict__ lnb,
    __half* __restrict__ oh)
{
    const int grp = blockIdx.x * 8 + (threadIdx.x >> 5);
    const int lane = threadIdx.x & 31;
    const int bt = grp >> 5;
    const int h = grp & 31;
    size_t base = (size_t)bt * Dd + h * 64;
    float v0 = att[base + lane];
    float v1 = att[base + lane + 32];
    float sum = v0 + v1;
    float sq = v0 * v0 + v1 * v1;
#pragma unroll
    for (int o = 16; o > 0; o >>= 1) {
        sum += __shfl_xor_sync(0xffffffffu, sum, o);
        sq  += __shfl_xor_sync(0xffffffffu, sq, o);
    }
    float mu = sum * (1.f / 64.f);
    float var = sq * (1.f / 64.f) - mu * mu;
    float inv = rsqrtf(var + 1e-5f);
    int li = h * 64 + lane;
    oh[base + lane] = __float2half_rn(
        fmaf((v0 - mu) * inv, lng[li], lnb[li]) * g[base + lane]);
    oh[base + lane + 32] = __float2half_rn(
        fmaf((v1 - mu) * inv, lng[li + 32], lnb[li + 32]) * g[base + lane + 32]);
}

// ====================== copy x[:, -1, :] ====================================
__global__ void __launch_bounds__(256) lastcopy_k(const float* __restrict__ x,
                                                  float* __restrict__ o)
{
    int i = blockIdx.x * 256 + threadIdx.x;
    int b = i / Dd, d = i % Dd;
    o[i] = x[((size_t)b * Tt + (Tt - 1)) * Dd + d];
}

// ====================== host ================================================
extern "C" void kernel_launch(void* const* d_in, const int* in_sizes, int n_in,
                              void* d_out, int out_size)
{
    const float* x     = (const float*)d_in[0];
    const float* prev  = (const float*)d_in[1];
    const float* state = (const float*)d_in[2];
    const float* x_maa = (const float*)d_in[3];
    const float* w_maa = (const float*)d_in[4];
    const float* k_maa = (const float*)d_in[5];
    const float* v_maa = (const float*)d_in[6];
    const float* r_maa = (const float*)d_in[7];
    const float* g_maa = (const float*)d_in[8];
    const float* tm_w1 = (const float*)d_in[9];
    const float* tm_w2 = (const float*)d_in[10];
    const float* td_w1 = (const float*)d_in[11];
    const float* td_w2 = (const float*)d_in[12];
    const float* tdec  = (const float*)d_in[13];
    const float* tfirst= (const float*)d_in[14];
    const float* W_r   = (const float*)d_in[15];
    const float* W_k   = (const float*)d_in[16];
    const float* W_v   = (const float*)d_in[17];
    const float* W_g   = (const float*)d_in[18];
    const float* W_o   = (const float*)d_in[19];
    const float* ln_g  = (const float*)d_in[20];
    const float* ln_b  = (const float*)d_in[21];

    float *m, *r, *k, *v, *g, *w, *att;
    cudaGetSymbolAddress((void**)&m,   g_m);
    cudaGetSymbolAddress((void**)&r,   g_r);
    cudaGetSymbolAddress((void**)&k,   g_k);
    cudaGetSymbolAddress((void**)&v,   g_v);
    cudaGetSymbolAddress((void**)&g,   g_g);
    cudaGetSymbolAddress((void**)&w,   g_w);
    cudaGetSymbolAddress((void**)&att, g_att);

    __half *xh, *wxh, *kxh, *vxh, *rxh, *gxh, *gnh, *h1h;
    __half *wrh, *wkh, *wvh, *wgh, *woh, *wol, *tm1h, *td1h, *td2h;
    cudaGetSymbolAddress((void**)&xh,  g_xh);
    cudaGetSymbolAddress((void**)&wxh, g_wxh);
    cudaGetSymbolAddress((void**)&kxh, g_kxh);
    cudaGetSymbolAddress((void**)&vxh, g_vxh);
    cudaGetSymbolAddress((void**)&rxh, g_rxh);
    cudaGetSymbolAddress((void**)&gxh, g_gxh);
    cudaGetSymbolAddress((void**)&gnh, g_gnh);
    cudaGetSymbolAddress((void**)&h1h, g_h1h);
    cudaGetSymbolAddress((void**)&wrh, g_wrh);
    cudaGetSymbolAddress((void**)&wkh, g_wkh);
    cudaGetSymbolAddress((void**)&wvh, g_wvh);
    cudaGetSymbolAddress((void**)&wgh, g_wgh);
    cudaGetSymbolAddress((void**)&woh, g_woh);
    cudaGetSymbolAddress((void**)&wol, g_wol);
    cudaGetSymbolAddress((void**)&tm1h, g_tm1h);
    cudaGetSymbolAddress((void**)&td1h, g_td1h);
    cudaGetSymbolAddress((void**)&td2h, g_td2h);

    float* out0 = (float*)d_out;
    float* out_xlast = out0 + (size_t)BT * Dd;
    float* out_state = out_xlast + (size_t)Bb * Dd;

    cudaFuncSetAttribute(gemm_one<0>, cudaFuncAttributeMaxDynamicSharedMemorySize, GEMM_SMEM0);
    cudaFuncSetAttribute(gemm_one<1>, cudaFuncAttributeMaxDynamicSharedMemorySize, GEMM_SMEM1);
    cudaFuncSetAttribute(gemm_rkvg,   cudaFuncAttributeMaxDynamicSharedMemorySize, GEMM_SMEM0);

    // ---- [0] weight transposes + fp16 (W_o keeps exact hi/lo split) ----
    TsArgs ta;
    ta.src[0]=W_r;  ta.bh[0]=wrh;  ta.bl[0]=nullptr; ta.K[0]=Dd; ta.N[0]=Dd;  ta.gx[0]=64; ta.gy[0]=64;
    ta.src[1]=W_k;  ta.bh[1]=wkh;  ta.bl[1]=nullptr; ta.K[1]=Dd; ta.N[1]=Dd;  ta.gx[1]=64; ta.gy[1]=64;
    ta.src[2]=W_v;  ta.bh[2]=wvh;  ta.bl[2]=nullptr; ta.K[2]=Dd; ta.N[2]=Dd;  ta.gx[2]=64; ta.gy[2]=64;
    ta.src[3]=W_g;  ta.bh[3]=wgh;  ta.bl[3]=nullptr; ta.K[3]=Dd; ta.N[3]=Dd;  ta.gx[3]=64; ta.gy[3]=64;
    ta.src[4]=W_o;  ta.bh[4]=woh;  ta.bl[4]=wol;     ta.K[4]=Dd; ta.N[4]=Dd;  ta.gx[4]=64; ta.gy[4]=64;
    ta.src[5]=tm_w1;ta.bh[5]=tm1h; ta.bl[5]=nullptr; ta.K[5]=Dd; ta.N[5]=E5c; ta.gx[5]=64; ta.gy[5]=8;
    ta.src[6]=td_w1;ta.bh[6]=td1h; ta.bl[6]=nullptr; ta.K[6]=Dd; ta.N[6]=64;  ta.gx[6]=64; ta.gy[6]=4;
    ta.src[7]=td_w2;ta.bh[7]=td2h; ta.bl[7]=nullptr; ta.K[7]=64; ta.N[7]=Dd;  ta.gx[7]=2;  ta.gy[7]=64;
    tsplit_all<<<dim3(64, 64, 8), 256>>>(ta);

    // ---- [1] shift + fp16(xxx) ----
    prep_k<<<(BT * Dd) / 256, 256>>>(x, prev, x_maa, xh);
    // ---- [2] m = tanh(xxx @ tm_w1) ----
    gemm_one<0><<<dim3(2, BT/256), 256, GEMM_SMEM0>>>(xh, tm1h, nullptr,
        m, nullptr, E5c, Dd, nullptr, 2);
    // ---- [3] mix + 5 lerps (fp16) ----
    mix_k<<<dim3(Dd/256, BT/8), 256>>>(x, prev, m, tm_w2,
        w_maa, k_maa, v_maa, r_maa, g_maa,
        wxh, kxh, vxh, rxh, gxh);
    // ---- [4] x[:, -1] ----
    lastcopy_k<<<(Bb * Dd) / 256, 256>>>(x, out_xlast);
    // ---- [5] big GEMMs r/k/v/g + overlapped td1 (z=4) ----
    gemm_rkvg<<<dim3(Dd/128, BT/256, 5), 256, GEMM_SMEM0>>>(
        rxh, wrh, r,
        kxh, wkh, k,
        vxh, wvh, v,
        gxh, wgh, g,
        wxh, td1h, h1h);
    // ---- [6] td2: w = exp(-exp(h1 @ td_w2 + decay)) ----
    gemm_one<0><<<dim3(Dd/128, BT/256), 256, GEMM_SMEM0>>>(h1h, td2h, nullptr,
        w, nullptr, Dd, 64, tdec, 4);
    // ---- [7] WKV scan ----
    wkv_k<<<Bb * Hh, 256>>>(r, k, v, w, tfirst, state, att, out_state);
    // ---- [8] groupnorm * ln * g (fp16) ----
    gnorm_k<<<(BT * Hh) / 8, 256>>>(att, g, ln_g, ln_b, gnh);
    // ---- [9] out = gn @ W_o (exact split weights) ----
    gemm_one<1><<<dim3(Dd/128, BT/256), 256, GEMM_SMEM1>>>(gnh, woh, wol,
        out0, nullptr, Dd, Dd, nullptr, 0);
}

// round 12
// speedup vs baseline: 7.2156x; 1.0341x over previous
#include <cuda_runtime.h>
#include <cuda_fp16.h>
#include <math.h>
#include <stdint.h>

#define Bb 4
#define Tt 2048
#define Dd 2048
#define Hh 32
#define HSz 64
#define BT (Bb*Tt)
#define E5c 160

// ====================== device scratch (bss, no alloc) ======================
__device__ float g_m  [BT*E5c];
__device__ float g_r  [BT*Dd];
__device__ float g_k  [BT*Dd];
__device__ float g_v  [BT*Dd];
__device__ float g_g  [BT*Dd];
__device__ float g_w  [BT*Dd];
__device__ float g_att[BT*Dd];

__device__ __half g_xh [BT*Dd];
__device__ __half g_wxh[BT*Dd];
__device__ __half g_kxh[BT*Dd];
__device__ __half g_vxh[BT*Dd];
__device__ __half g_rxh[BT*Dd];
__device__ __half g_gxh[BT*Dd];
__device__ __half g_gnh[BT*Dd];
__device__ __half g_h1h[BT*64];

__device__ __half g_wrh[Dd*Dd];
__device__ __half g_wkh[Dd*Dd];
__device__ __half g_wvh[Dd*Dd];
__device__ __half g_wgh[Dd*Dd];
__device__ __half g_woh[Dd*Dd], g_wol[Dd*Dd];   // W_o keeps exact split
__device__ __half g_tm1h[256*Dd];
__device__ __half g_td1h[128*Dd];
__device__ __half g_td2h[Dd*64];
__device__ __half g_tm2h[5*32*Dd];              // tm_w2 in fp16

// ====================== PTX helpers (sm_80-class only) ======================
__device__ __forceinline__ uint32_t smem_u32(const void* p) {
    uint32_t a;
    asm("{ .reg .u64 t; cvta.to.shared.u64 t, %1; cvt.u32.u64 %0, t; }"
        : "=r"(a) : "l"(p));
    return a;
}

#define CP_ASYNC16(dst, src) \
    asm volatile("cp.async.cg.shared.global [%0], [%1], 16;" \
        :: "r"(dst), "l"(src) : "memory")
#define CP_COMMIT() asm volatile("cp.async.commit_group;" ::: "memory")
#define CP_WAIT0()  asm volatile("cp.async.wait_group 0;" ::: "memory")
#define CP_WAIT1()  asm volatile("cp.async.wait_group 1;" ::: "memory")

__device__ __forceinline__ void ldsm4(uint32_t* r, uint32_t addr) {
    asm volatile("ldmatrix.sync.aligned.m8n8.x4.shared.b16 {%0,%1,%2,%3},[%4];"
        : "=r"(r[0]), "=r"(r[1]), "=r"(r[2]), "=r"(r[3]) : "r"(addr));
}

__device__ __forceinline__ void mma16816(float* c, const uint32_t* a, const uint32_t* b) {
    asm volatile(
        "mma.sync.aligned.m16n8k16.row.col.f32.f16.f16.f32 "
        "{%0,%1,%2,%3},{%4,%5,%6,%7},{%8,%9},{%0,%1,%2,%3};"
        : "+f"(c[0]), "+f"(c[1]), "+f"(c[2]), "+f"(c[3])
        : "r"(a[0]), "r"(a[1]), "r"(a[2]), "r"(a[3]), "r"(b[0]), "r"(b[1]));
}

__device__ __forceinline__ uint32_t swz(uint32_t bo) { return bo ^ ((bo >> 3) & 0x70); }

// ====================== tensor-core GEMM (HMMA fp16, 256x128 tile) ==========
__device__ __forceinline__ float repi(float v, int epi, const float* extra, int n) {
    switch (epi) {
        case 1: return 1.f / (1.f + expf(-v));
        case 2: return tanhf(v);
        case 3: return v / (1.f + expf(-v));
        case 4: return expf(-expf(v + extra[n]));
        default: return v;
    }
}

template<int ROWS>
__device__ __forceinline__ void load_tile_async(uint32_t sbase,
    const __half* __restrict__ src, int row0, int k0, int ldK, int tid)
{
#pragma unroll
    for (int i = 0; i < ROWS / 32; i++) {
        int u = i * 256 + tid;
        int row = u >> 3, cc = u & 7;
        uint32_t bo = (uint32_t)(row * 128 + cc * 16);
        CP_ASYNC16(sbase + swz(bo),
                   src + (size_t)(row0 + row) * ldK + k0 + cc * 8);
    }
}

// SPLIT=0: stage = A 32K + B 16K = 48K; SPLIT=1: +Bl 16K = 64K. 3 stages.
#define ST0 49152u
#define ST1 65536u
#define GEMM_SMEM0 (3 * ST0)    // 147456
#define GEMM_SMEM1 (3 * ST1)    // 196608

template<int SPLIT>
__device__ __forceinline__ void gemm_stage(uint32_t st,
    const __half* A, const __half* Bh, const __half* Bl,
    int mbase, int nbase, int k0, int K, int tid)
{
    load_tile_async<256>(st +     0, A,  mbase, k0, K, tid);
    load_tile_async<128>(st + 32768, Bh, nbase, k0, K, tid);
    if (SPLIT) load_tile_async<128>(st + 49152, Bl, nbase, k0, K, tid);
    CP_COMMIT();
}

template<int SPLIT>
__device__ __forceinline__ void gemm_core(
    const __half* __restrict__ A,
    const __half* __restrict__ Bh, const __half* __restrict__ Bl,
    float* __restrict__ Cf, __half* __restrict__ Ch,
    int Nout, int K, const float* __restrict__ extra, int epi)
{
    extern __shared__ char sm[];
    const uint32_t sb = smem_u32(sm);
    const uint32_t ST = SPLIT ? ST1 : ST0;
    const int tid = threadIdx.x, lane = tid & 31, wid = tid >> 5;
    const int wm = wid >> 1, wn = wid & 1;           // 4 x 2 warps, warp tile 64x64
    const int mbase = blockIdx.y * 256, nbase = blockIdx.x * 128;

    float acc[4][8][4];
#pragma unroll
    for (int mf = 0; mf < 4; mf++)
#pragma unroll
        for (int nf = 0; nf < 8; nf++)
#pragma unroll
            for (int q = 0; q < 4; q++) acc[mf][nf][q] = 0.f;

    const int nc = K / 64;
    gemm_stage<SPLIT>(sb, A, Bh, Bl, mbase, nbase, 0, K, tid);
    if (nc > 1)
        gemm_stage<SPLIT>(sb + ST, A, Bh, Bl, mbase, nbase, 64, K, tid);

    const int a_row = (lane & 15);
    const int a_cb  = ((lane >> 4) & 1) * 16;
    const int mat   = lane >> 3;
    const int b_row = (lane & 7) + ((mat >> 1) & 1) * 8;
    const int b_cb  = (mat & 1) * 16;

    for (int c = 0; c < nc; c++) {
        // single-sync pipeline: wait(c) -> sync -> stage(c+2) -> compute(c)
        if (c + 1 < nc) { CP_WAIT1(); } else { CP_WAIT0(); }
        __syncthreads();
        if (c + 2 < nc)
            gemm_stage<SPLIT>(sb + ((c + 2) % 3) * ST, A, Bh, Bl,
                              mbase, nbase, (c + 2) * 64, K, tid);

        const uint32_t base = sb + (c % 3) * ST;
#pragma unroll
        for (int ks = 0; ks < 4; ks++) {
            uint32_t av[4][4];
#pragma unroll
            for (int mf = 0; mf < 4; mf++) {
                uint32_t bo = (uint32_t)((wm * 64 + mf * 16 + a_row) * 128 + ks * 32 + a_cb);
                ldsm4(av[mf], base + swz(bo));
            }
            uint32_t bh[4][4];
#pragma unroll
            for (int bq = 0; bq < 4; bq++) {
                uint32_t bo = (uint32_t)((wn * 64 + bq * 16 + b_row) * 128 + ks * 32 + b_cb);
                ldsm4(bh[bq], base + 32768 + swz(bo));
            }
#pragma unroll
            for (int mf = 0; mf < 4; mf++)
#pragma unroll
                for (int bq = 0; bq < 4; bq++) {
                    mma16816(acc[mf][2 * bq],     av[mf], &bh[bq][0]);
                    mma16816(acc[mf][2 * bq + 1], av[mf], &bh[bq][2]);
                }
            if (SPLIT) {
                uint32_t bl[4][4];
#pragma unroll
                for (int bq = 0; bq < 4; bq++) {
                    uint32_t bo = (uint32_t)((wn * 64 + bq * 16 + b_row) * 128 + ks * 32 + b_cb);
                    ldsm4(bl[bq], base + 49152 + swz(bo));
                }
#pragma unroll
                for (int mf = 0; mf < 4; mf++)
#pragma unroll
                    for (int bq = 0; bq < 4; bq++) {
                        mma16816(acc[mf][2 * bq],     av[mf], &bl[bq][0]);
                        mma16816(acc[mf][2 * bq + 1], av[mf], &bl[bq][2]);
                    }
            }
        }
    }

    const int r_in = lane >> 2, c_in = (lane & 3) * 2;
#pragma unroll
    for (int mf = 0; mf < 4; mf++)
#pragma unroll
        for (int nf = 0; nf < 8; nf++) {
            int row0 = mbase + wm * 64 + mf * 16 + r_in;
            int col  = nbase + wn * 64 + nf * 8 + c_in;
            if (col >= Nout) continue;
            float* q = acc[mf][nf];
            float e0 = repi(q[0], epi, extra, col);
            float e1 = repi(q[1], epi, extra, col + 1);
            float e2 = repi(q[2], epi, extra, col);
            float e3 = repi(q[3], epi, extra, col + 1);
            if (Ch == nullptr) {
                *(float2*)(Cf + (size_t)row0 * Nout + col) = make_float2(e0, e1);
                *(float2*)(Cf + (size_t)(row0 + 8) * Nout + col) = make_float2(e2, e3);
            } else {
                *(__half2*)(Ch + (size_t)row0 * Nout + col) =
                    __floats2half2_rn(e0, e1);
                *(__half2*)(Ch + (size_t)(row0 + 8) * Nout + col) =
                    __floats2half2_rn(e2, e3);
            }
        }
}

template<int SPLIT>
__global__ void __launch_bounds__(256, 1) gemm_one(
    const __half* __restrict__ A,
    const __half* __restrict__ Bh, const __half* __restrict__ Bl,
    float* __restrict__ Cf, __half* __restrict__ Ch,
    int Nout, int K, const float* __restrict__ extra, int epi)
{
    gemm_core<SPLIT>(A, Bh, Bl, Cf, Ch, Nout, K, extra, epi);
}

// z = 0..3: r/k/v/g big GEMMs. z = 4: small td1 GEMM (overlapped).
__global__ void __launch_bounds__(256, 1) gemm_rkvg(
    const __half* rxh, const __half* wrh, float* r,
    const __half* kxh, const __half* wkh, float* k,
    const __half* vxh, const __half* wvh, float* v,
    const __half* gxh, const __half* wgh, float* g,
    const __half* wxh, const __half* td1h, __half* h1h)
{
    if (blockIdx.z == 4) {
        if (blockIdx.x != 0) return;
        gemm_core<0>(wxh, td1h, nullptr, nullptr, h1h, 64, Dd, nullptr, 2);
        return;
    }
    const __half *A, *Bh; float* C; int epi;
    switch (blockIdx.z) {
        case 0:  A = rxh; Bh = wrh; C = r; epi = 1; break;
        case 1:  A = kxh; Bh = wkh; C = k; epi = 0; break;
        case 2:  A = vxh; Bh = wvh; C = v; epi = 0; break;
        default: A = gxh; Bh = wgh; C = g; epi = 3; break;
    }
    gemm_core<0>(A, Bh, nullptr, C, nullptr, Dd, Dd, nullptr, epi);
}

// ====================== mega prologue launch ================================
// z 0..7: weight transpose+fp16 (z=4 with exact lo split)
// z = 8: tm_w2 fp32 -> fp16 copy; z = 9: prep; z = 10: lastcopy
struct TsArgs {
    const float* src[8];
    __half* bh[8];
    __half* bl[8];      // nullptr -> no lo term
    int K[8], N[8], gx[8], gy[8];
};

__global__ void __launch_bounds__(256) tsplit_all(TsArgs a,
    const float* __restrict__ tmw2, __half* __restrict__ tm2h,
    const float* __restrict__ x, const float* __restrict__ prev,
    const float* __restrict__ xmaa, __half* __restrict__ xh,
    float* __restrict__ xlast)
{
    const int z = blockIdx.z;
    const int tid = threadIdx.x;

    if (z == 8) {   // tm_w2 convert: 5*32*2048 = 327680 = 1280 CTAs x 256
        if (blockIdx.x >= 40 || blockIdx.y >= 32) return;
        int id = ((int)blockIdx.x * 32 + (int)blockIdx.y) * 256 + tid;
        tm2h[id] = __float2half_rn(tmw2[id]);
        return;
    }
    if (z == 9) {   // prep: xh = fp16(x + (shift - x) * x_maa)
        size_t base = ((size_t)blockIdx.x * 64 + blockIdx.y) * 4096;
#pragma unroll 4
        for (int j = 0; j < 16; j++) {
            size_t i = base + j * 256 + tid;
            int d = (int)(i % Dd);
            size_t bt = i / Dd;
            int t = (int)(bt & (Tt - 1));
            int b = (int)(bt >> 11);
            float xv = x[i];
            float sh = (t == 0) ? prev[(size_t)b * Dd + d] : x[i - Dd];
            xh[i] = __float2half_rn(fmaf(sh - xv, xmaa[d], xv));
        }
        return;
    }
    if (z == 10) {  // lastcopy: x[:, -1, :]
        if (blockIdx.y != 0 || blockIdx.x >= 32) return;
        int i = (int)blockIdx.x * 256 + tid;
        int b = i / Dd, d = i % Dd;
        xlast[i] = x[((size_t)b * Tt + (Tt - 1)) * Dd + d];
        return;
    }

    if ((int)blockIdx.x >= a.gx[z] || (int)blockIdx.y >= a.gy[z]) return;
    const float* __restrict__ W = a.src[z];
    __half* __restrict__ bh = a.bh[z];
    __half* __restrict__ bl = a.bl[z];
    const int K = a.K[z], N = a.N[z];

    __shared__ float t[32][33];
    const int k0 = blockIdx.x * 32, n0 = blockIdx.y * 32;
    const int tx = tid & 31, ty = tid >> 5;
#pragma unroll
    for (int i = 0; i < 4; i++) {
        int kk = ty + i * 8;
        int n = n0 + tx;
        t[kk][tx] = (n < N) ? W[(size_t)(k0 + kk) * N + n] : 0.f;
    }
    __syncthreads();
#pragma unroll
    for (int i = 0; i < 4; i++) {
        int nn = ty + i * 8;
        float v = t[tx][nn];
        __half h = __float2half_rn(v);
        size_t o = (size_t)(n0 + nn) * K + k0 + tx;
        bh[o] = h;
        if (bl) bl[o] = __float2half_rn(v - __half2float(h));
    }
}

// ====================== mix: fp16 tiles, single-sync pipeline ===============
__global__ void __launch_bounds__(256) mix_k(
    const float* __restrict__ x, const float* __restrict__ prev,
    const float* __restrict__ m, const __half* __restrict__ tm2h,
    const float* __restrict__ wmaa, const float* __restrict__ kmaa,
    const float* __restrict__ vmaa, const float* __restrict__ rmaa,
    const float* __restrict__ gmaa,
    __half* __restrict__ wxh, __half* __restrict__ kxh,
    __half* __restrict__ vxh, __half* __restrict__ rxh,
    __half* __restrict__ gxh)
{
    __shared__ float msh[E5c][8];
    __shared__ __half tileh[2][32][256];   // 2 x 16 KB
    const int tid = threadIdx.x;
    const int dbase = blockIdx.x * 256;
    const int tb = blockIdx.y * 8;

    // stage f=0 tile (8192 halves = 1024 x 16B)
#pragma unroll
    for (int i = 0; i < 4; i++) {
        int j = i * 256 + tid;
        int e = j >> 5, c8 = (j & 31) << 3;
        CP_ASYNC16(smem_u32(&tileh[0][e][c8]),
                   tm2h + (size_t)e * Dd + dbase + c8);
    }
    CP_COMMIT();

    for (int i = tid; i < 8 * E5c; i += 256) {
        int tok = i / E5c, e5 = i % E5c;
        msh[e5][tok] = m[(size_t)(tb + tok) * E5c + e5];
    }

    float acc[8][5];
#pragma unroll
    for (int tok = 0; tok < 8; tok++)
#pragma unroll
        for (int f = 0; f < 5; f++) acc[tok][f] = 0.f;

#pragma unroll
    for (int f = 0; f < 5; f++) {
        CP_WAIT0();
        __syncthreads();
        if (f + 1 < 5) {
            const int nb = (f + 1) & 1;
#pragma unroll
            for (int i = 0; i < 4; i++) {
                int j = i * 256 + tid;
                int e = j >> 5, c8 = (j & 31) << 3;
                CP_ASYNC16(smem_u32(&tileh[nb][e][c8]),
                           tm2h + (size_t)((f + 1) * 32 + e) * Dd + dbase + c8);
            }
            CP_COMMIT();
        }

        const int cb = f & 1;
#pragma unroll
        for (int e = 0; e < 32; e++) {
            float tv = __half2float(tileh[cb][e][tid]);
            float4 m0 = *(const float4*)&msh[f * 32 + e][0];
            float4 m1 = *(const float4*)&msh[f * 32 + e][4];
            acc[0][f] = fmaf(m0.x, tv, acc[0][f]);
            acc[1][f] = fmaf(m0.y, tv, acc[1][f]);
            acc[2][f] = fmaf(m0.z, tv, acc[2][f]);
            acc[3][f] = fmaf(m0.w, tv, acc[3][f]);
            acc[4][f] = fmaf(m1.x, tv, acc[4][f]);
            acc[5][f] = fmaf(m1.y, tv, acc[5][f]);
            acc[6][f] = fmaf(m1.z, tv, acc[6][f]);
            acc[7][f] = fmaf(m1.w, tv, acc[7][f]);
        }
    }

    const int d = dbase + tid;
    const float wm = wmaa[d], km = kmaa[d], vm = vmaa[d], rm = rmaa[d], gm = gmaa[d];
#pragma unroll
    for (int tok = 0; tok < 8; tok++) {
        int bt = tb + tok;
        int t = bt & (Tt - 1), b = bt >> 11;
        size_t idx = (size_t)bt * Dd + d;
        float xv = x[idx];
        float sh = (t == 0) ? prev[(size_t)b * Dd + d] : x[idx - Dd];
        float sv = sh - xv;
        wxh[idx] = __float2half_rn(fmaf(sv, wm + acc[tok][0], xv));
        kxh[idx] = __float2half_rn(fmaf(sv, km + acc[tok][1], xv));
        vxh[idx] = __float2half_rn(fmaf(sv, vm + acc[tok][2], xv));
        rxh[idx] = __float2half_rn(fmaf(sv, rm + acc[tok][3], xv));
        gxh[idx] = __float2half_rn(fmaf(sv, gm + acc[tok][4], xv));
    }
}

// ====================== WKV scan: 16-step blocks, float4 staging ============
__global__ void __launch_bounds__(256) wkv_k(
    const float* __restrict__ r, const float* __restrict__ k,
    const float* __restrict__ v, const float* __restrict__ w,
    const float* __restrict__ u, const float* __restrict__ s0,
    float* __restrict__ att, float* __restrict__ sout)
{
    __shared__ float rs[3][16][64], ksm[3][16][64], wsm[3][16][64], vsm[3][16][64];
    __shared__ float osh[3][16][64];

    const int bh = blockIdx.x, b = bh >> 5, h = bh & 31;
    const int tid = threadIdx.x;
    const int vcol = tid >> 2, kg = tid & 3;
    const int st_ = tid >> 4;          // 0..15 (timestep in block)
    const int si  = (tid & 15) * 4;    // 0..60 (4 floats)

    const size_t base0 = (size_t)b * Tt * Dd + h * 64;
    const size_t sbase = (size_t)bh * 4096;

    float s[16], uo[16];
#pragma unroll
    for (int j = 0; j < 16; j++) {
        s[j]  = s0[sbase + (size_t)(kg * 16 + j) * 64 + vcol];
        uo[j] = u[h * 64 + kg * 16 + j];
    }

    {
        size_t g = base0 + (size_t)st_ * Dd + si;
        CP_ASYNC16(smem_u32(&rs[0][st_][si]),  r + g);
        CP_ASYNC16(smem_u32(&ksm[0][st_][si]), k + g);
        CP_ASYNC16(smem_u32(&wsm[0][st_][si]), w + g);
        CP_ASYNC16(smem_u32(&vsm[0][st_][si]), v + g);
        CP_COMMIT();
    }

    const int NB = Tt / 16;   // 128
    int buf = 0;
    for (int nb = 0; nb < NB; nb++) {
        buf = nb % 3;
        const int nxt = (nb + 1) % 3;
        if (nb + 1 < NB) {
            size_t g = base0 + (size_t)((nb + 1) * 16 + st_) * Dd + si;
            CP_ASYNC16(smem_u32(&rs[nxt][st_][si]),  r + g);
            CP_ASYNC16(smem_u32(&ksm[nxt][st_][si]), k + g);
            CP_ASYNC16(smem_u32(&wsm[nxt][st_][si]), w + g);
            CP_ASYNC16(smem_u32(&vsm[nxt][st_][si]), v + g);
            CP_COMMIT();
            CP_WAIT1();
        } else {
            CP_WAIT0();
        }
        __syncthreads();

        if (nb > 0) {
            const int pb = (nb - 1) % 3;
            *(float4*)&att[base0 + (size_t)((nb - 1) * 16 + st_) * Dd + si] =
                *(const float4*)&osh[pb][st_][si];
        }

#pragma unroll 4
        for (int t = 0; t < 16; t++) {
            const float vm = vsm[buf][t][vcol];
            float a = 0.f;
            const float* rp = &rs[buf][t][kg * 16];
            const float* kp = &ksm[buf][t][kg * 16];
            const float* wp = &wsm[buf][t][kg * 16];
#pragma unroll
            for (int q = 0; q < 4; q++) {
                float4 r4 = *(const float4*)(rp + 4 * q);
                float4 k4 = *(const float4*)(kp + 4 * q);
                float4 w4 = *(const float4*)(wp + 4 * q);
                float kv, tt;
                kv = k4.x * vm; tt = fmaf(uo[4*q+0], kv, s[4*q+0]); a = fmaf(r4.x, tt, a); s[4*q+0] = fmaf(s[4*q+0], w4.x, kv);
                kv = k4.y * vm; tt = fmaf(uo[4*q+1], kv, s[4*q+1]); a = fmaf(r4.y, tt, a); s[4*q+1] = fmaf(s[4*q+1], w4.y, kv);
                kv = k4.z * vm; tt = fmaf(uo[4*q+2], kv, s[4*q+2]); a = fmaf(r4.z, tt, a); s[4*q+2] = fmaf(s[4*q+2], w4.z, kv);
                kv = k4.w * vm; tt = fmaf(uo[4*q+3], kv, s[4*q+3]); a = fmaf(r4.w, tt, a); s[4*q+3] = fmaf(s[4*q+3], w4.w, kv);
            }
            a += __shfl_xor_sync(0xffffffffu, a, 1);
            a += __shfl_xor_sync(0xffffffffu, a, 2);
            if (kg == 0) osh[buf][t][vcol] = a;
        }
    }
    __syncthreads();
    *(float4*)&att[base0 + (size_t)((NB - 1) * 16 + st_) * Dd + si] =
        *(const float4*)&osh[buf][st_][si];
#pragma unroll
    for (int j = 0; j < 16; j++)
        sout[sbase + (size_t)(kg * 16 + j) * 64 + vcol] = s[j];
}

// ====================== groupnorm + ln + *g, writes fp16 ====================
__global__ void __launch_bounds__(256) gnorm_k(
    const float* __restrict__ att, const float* __restrict__ g,
    const float* __restrict__ lng, const float* __restrict__ lnb,
    __half* __restrict__ oh)
{
    const int grp = blockIdx.x * 8 + (threadIdx.x >> 5);
    const int lane = threadIdx.x & 31;
    const int bt = grp >> 5;
    const int h = grp & 31;
    size_t base = (size_t)bt * Dd + h * 64;
    float v0 = att[base + lane];
    float v1 = att[base + lane + 32];
    float sum = v0 + v1;
    float sq = v0 * v0 + v1 * v1;
#pragma unroll
    for (int o = 16; o > 0; o >>= 1) {
        sum += __shfl_xor_sync(0xffffffffu, sum, o);
        sq  += __shfl_xor_sync(0xffffffffu, sq, o);
    }
    float mu = sum * (1.f / 64.f);
    float var = sq * (1.f / 64.f) - mu * mu;
    float inv = rsqrtf(var + 1e-5f);
    int li = h * 64 + lane;
    oh[base + lane] = __float2half_rn(
        fmaf((v0 - mu) * inv, lng[li], lnb[li]) * g[base + lane]);
    oh[base + lane + 32] = __float2half_rn(
        fmaf((v1 - mu) * inv, lng[li + 32], lnb[li + 32]) * g[base + lane + 32]);
}

// ====================== host ================================================
extern "C" void kernel_launch(void* const* d_in, const int* in_sizes, int n_in,
                              void* d_out, int out_size)
{
    const float* x     = (const float*)d_in[0];
    const float* prev  = (const float*)d_in[1];
    const float* state = (const float*)d_in[2];
    const float* x_maa = (const float*)d_in[3];
    const float* w_maa = (const float*)d_in[4];
    const float* k_maa = (const float*)d_in[5];
    const float* v_maa = (const float*)d_in[6];
    const float* r_maa = (const float*)d_in[7];
    const float* g_maa = (const float*)d_in[8];
    const float* tm_w1 = (const float*)d_in[9];
    const float* tm_w2 = (const float*)d_in[10];
    const float* td_w1 = (const float*)d_in[11];
    const float* td_w2 = (const float*)d_in[12];
    const float* tdec  = (const float*)d_in[13];
    const float* tfirst= (const float*)d_in[14];
    const float* W_r   = (const float*)d_in[15];
    const float* W_k   = (const float*)d_in[16];
    const float* W_v   = (const float*)d_in[17];
    const float* W_g   = (const float*)d_in[18];
    const float* W_o   = (const float*)d_in[19];
    const float* ln_g  = (const float*)d_in[20];
    const float* ln_b  = (const float*)d_in[21];

    float *m, *r, *k, *v, *g, *w, *att;
    cudaGetSymbolAddress((void**)&m,   g_m);
    cudaGetSymbolAddress((void**)&r,   g_r);
    cudaGetSymbolAddress((void**)&k,   g_k);
    cudaGetSymbolAddress((void**)&v,   g_v);
    cudaGetSymbolAddress((void**)&g,   g_g);
    cudaGetSymbolAddress((void**)&w,   g_w);
    cudaGetSymbolAddress((void**)&att, g_att);

    __half *xh, *wxh, *kxh, *vxh, *rxh, *gxh, *gnh, *h1h;
    __half *wrh, *wkh, *wvh, *wgh, *woh, *wol, *tm1h, *td1h, *td2h, *tm2h;
    cudaGetSymbolAddress((void**)&xh,  g_xh);
    cudaGetSymbolAddress((void**)&wxh, g_wxh);
    cudaGetSymbolAddress((void**)&kxh, g_kxh);
    cudaGetSymbolAddress((void**)&vxh, g_vxh);
    cudaGetSymbolAddress((void**)&rxh, g_rxh);
    cudaGetSymbolAddress((void**)&gxh, g_gxh);
    cudaGetSymbolAddress((void**)&gnh, g_gnh);
    cudaGetSymbolAddress((void**)&h1h, g_h1h);
    cudaGetSymbolAddress((void**)&wrh, g_wrh);
    cudaGetSymbolAddress((void**)&wkh, g_wkh);
    cudaGetSymbolAddress((void**)&wvh, g_wvh);
    cudaGetSymbolAddress((void**)&wgh, g_wgh);
    cudaGetSymbolAddress((void**)&woh, g_woh);
    cudaGetSymbolAddress((void**)&wol, g_wol);
    cudaGetSymbolAddress((void**)&tm1h, g_tm1h);
    cudaGetSymbolAddress((void**)&td1h, g_td1h);
    cudaGetSymbolAddress((void**)&td2h, g_td2h);
    cudaGetSymbolAddress((void**)&tm2h, g_tm2h);

    float* out0 = (float*)d_out;
    float* out_xlast = out0 + (size_t)BT * Dd;
    float* out_state = out_xlast + (size_t)Bb * Dd;

    cudaFuncSetAttribute(gemm_one<0>, cudaFuncAttributeMaxDynamicSharedMemorySize, GEMM_SMEM0);
    cudaFuncSetAttribute(gemm_one<1>, cudaFuncAttributeMaxDynamicSharedMemorySize, GEMM_SMEM1);
    cudaFuncSetAttribute(gemm_rkvg,   cudaFuncAttributeMaxDynamicSharedMemorySize, GEMM_SMEM0);

    // ---- [0] mega prologue: weights + tm_w2 fp16 + prep + lastcopy ----
    TsArgs ta;
    ta.src[0]=W_r;  ta.bh[0]=wrh;  ta.bl[0]=nullptr; ta.K[0]=Dd; ta.N[0]=Dd;  ta.gx[0]=64; ta.gy[0]=64;
    ta.src[1]=W_k;  ta.bh[1]=wkh;  ta.bl[1]=nullptr; ta.K[1]=Dd; ta.N[1]=Dd;  ta.gx[1]=64; ta.gy[1]=64;
    ta.src[2]=W_v;  ta.bh[2]=wvh;  ta.bl[2]=nullptr; ta.K[2]=Dd; ta.N[2]=Dd;  ta.gx[2]=64; ta.gy[2]=64;
    ta.src[3]=W_g;  ta.bh[3]=wgh;  ta.bl[3]=nullptr; ta.K[3]=Dd; ta.N[3]=Dd;  ta.gx[3]=64; ta.gy[3]=64;
    ta.src[4]=W_o;  ta.bh[4]=woh;  ta.bl[4]=wol;     ta.K[4]=Dd; ta.N[4]=Dd;  ta.gx[4]=64; ta.gy[4]=64;
    ta.src[5]=tm_w1;ta.bh[5]=tm1h; ta.bl[5]=nullptr; ta.K[5]=Dd; ta.N[5]=E5c; ta.gx[5]=64; ta.gy[5]=8;
    ta.src[6]=td_w1;ta.bh[6]=td1h; ta.bl[6]=nullptr; ta.K[6]=Dd; ta.N[6]=64;  ta.gx[6]=64; ta.gy[6]=4;
    ta.src[7]=td_w2;ta.bh[7]=td2h; ta.bl[7]=nullptr; ta.K[7]=64; ta.N[7]=Dd;  ta.gx[7]=2;  ta.gy[7]=64;
    tsplit_all<<<dim3(64, 64, 11), 256>>>(ta, tm_w2, tm2h,
                                          x, prev, x_maa, xh, out_xlast);

    // ---- [1] m = tanh(xxx @ tm_w1) ----
    gemm_one<0><<<dim3(2, BT/256), 256, GEMM_SMEM0>>>(xh, tm1h, nullptr,
        m, nullptr, E5c, Dd, nullptr, 2);
    // ---- [2] mix + 5 lerps (fp16) ----
    mix_k<<<dim3(Dd/256, BT/8), 256>>>(x, prev, m, tm2h,
        w_maa, k_maa, v_maa, r_maa, g_maa,
        wxh, kxh, vxh, rxh, gxh);
    // ---- [3] big GEMMs r/k/v/g + overlapped td1 (ncu -s 5 target) ----
    gemm_rkvg<<<dim3(Dd/128, BT/256, 5), 256, GEMM_SMEM0>>>(
        rxh, wrh, r,
        kxh, wkh, k,
        vxh, wvh, v,
        gxh, wgh, g,
        wxh, td1h, h1h);
    // ---- [4] td2: w = exp(-exp(h1 @ td_w2 + decay)) ----
    gemm_one<0><<<dim3(Dd/128, BT/256), 256, GEMM_SMEM0>>>(h1h, td2h, nullptr,
        w, nullptr, Dd, 64, tdec, 4);
    // ---- [5] WKV scan ----
    wkv_k<<<Bb * Hh, 256>>>(r, k, v, w, tfirst, state, att, out_state);
    // ---- [6] groupnorm * ln * g (fp16) ----
    gnorm_k<<<(BT * Hh) / 8, 256>>>(att, g, ln_g, ln_b, gnh);
    // ---- [7] out = gn @ W_o (exact split weights) ----
    gemm_one<1><<<dim3(Dd/128, BT/256), 256, GEMM_SMEM1>>>(gnh, woh, wol,
        out0, nullptr, Dd, Dd, nullptr, 0);
}

// round 15
// speedup vs baseline: 7.7614x; 1.0756x over previous
#include <cuda_runtime.h>
#include <cuda_fp16.h>
#include <math.h>
#include <stdint.h>

#define Bb 4
#define Tt 2048
#define Dd 2048
#define Hh 32
#define HSz 64
#define BT (Bb*Tt)
#define E5c 160

// ====================== device scratch (bss, no alloc) ======================
__device__ float g_m  [BT*E5c];
__device__ float g_r  [BT*Dd];
__device__ float g_k  [BT*Dd];
__device__ float g_v  [BT*Dd];
__device__ float g_g  [BT*Dd];
__device__ float g_w  [BT*Dd];
__device__ float g_att[BT*Dd];

__device__ __half g_xh [BT*Dd];
__device__ __half g_wxh[BT*Dd];
__device__ __half g_kxh[BT*Dd];
__device__ __half g_vxh[BT*Dd];
__device__ __half g_rxh[BT*Dd];
__device__ __half g_gxh[BT*Dd];
__device__ __half g_gnh[BT*Dd];
__device__ __half g_h1h[BT*64];

__device__ __half g_wrh[Dd*Dd];
__device__ __half g_wkh[Dd*Dd];
__device__ __half g_wvh[Dd*Dd];
__device__ __half g_wgh[Dd*Dd];
__device__ __half g_woh[Dd*Dd], g_wol[Dd*Dd];   // W_o keeps exact split
__device__ __half g_tm1h[256*Dd];
__device__ __half g_td1h[128*Dd];
__device__ __half g_td2h[Dd*64];
__device__ __half g_tm2h[5*32*Dd];              // tm_w2 in fp16

// ====================== PTX helpers (sm_80-class only) ======================
__device__ __forceinline__ uint32_t smem_u32(const void* p) {
    uint32_t a;
    asm("{ .reg .u64 t; cvta.to.shared.u64 t, %1; cvt.u32.u64 %0, t; }"
        : "=r"(a) : "l"(p));
    return a;
}

#define CP_ASYNC16(dst, src) \
    asm volatile("cp.async.cg.shared.global [%0], [%1], 16;" \
        :: "r"(dst), "l"(src) : "memory")
#define CP_COMMIT() asm volatile("cp.async.commit_group;" ::: "memory")
#define CP_WAIT0()  asm volatile("cp.async.wait_group 0;" ::: "memory")
#define CP_WAIT1()  asm volatile("cp.async.wait_group 1;" ::: "memory")

__device__ __forceinline__ void ldsm4(uint32_t* r, uint32_t addr) {
    asm volatile("ldmatrix.sync.aligned.m8n8.x4.shared.b16 {%0,%1,%2,%3},[%4];"
        : "=r"(r[0]), "=r"(r[1]), "=r"(r[2]), "=r"(r[3]) : "r"(addr));
}

__device__ __forceinline__ void mma16816(float* c, const uint32_t* a, const uint32_t* b) {
    asm volatile(
        "mma.sync.aligned.m16n8k16.row.col.f32.f16.f16.f32 "
        "{%0,%1,%2,%3},{%4,%5,%6,%7},{%8,%9},{%0,%1,%2,%3};"
        : "+f"(c[0]), "+f"(c[1]), "+f"(c[2]), "+f"(c[3])
        : "r"(a[0]), "r"(a[1]), "r"(a[2]), "r"(a[3]), "r"(b[0]), "r"(b[1]));
}

__device__ __forceinline__ uint32_t swz(uint32_t bo) { return bo ^ ((bo >> 3) & 0x70); }

__device__ __forceinline__ float repi(float v, int epi, const float* extra, int n) {
    switch (epi) {
        case 1: return 1.f / (1.f + expf(-v));
        case 2: return tanhf(v);
        case 3: return v / (1.f + expf(-v));
        case 4: return expf(-expf(v + extra[n]));
        default: return v;
    }
}

template<int ROWS>
__device__ __forceinline__ void load_tile_async(uint32_t sbase,
    const __half* __restrict__ src, int row0, int k0, int ldK, int tid)
{
#pragma unroll
    for (int i = 0; i < ROWS / 32; i++) {
        int u = i * 256 + tid;
        int row = u >> 3, cc = u & 7;
        uint32_t bo = (uint32_t)(row * 128 + cc * 16);
        CP_ASYNC16(sbase + swz(bo),
                   src + (size_t)(row0 + row) * ldK + k0 + cc * 8);
    }
}

// ============ 128x128 tile GEMM core (2 CTAs/SM; non-split weights) =========
#define ST128 32768u
#define GEMM_SMEM128 (3 * ST128)    // 98304

__device__ __forceinline__ void gemm_stage128(uint32_t st,
    const __half* A, const __half* B,
    int mbase, int nbase, int k0, int K, int tid)
{
    load_tile_async<128>(st +     0, A, mbase, k0, K, tid);
    load_tile_async<128>(st + 16384, B, nbase, k0, K, tid);
    CP_COMMIT();
}

__device__ __forceinline__ void gemm_core128(
    const __half* __restrict__ A, const __half* __restrict__ B,
    float* __restrict__ Cf, __half* __restrict__ Ch,
    int Nout, int K, const float* __restrict__ extra, int epi)
{
    extern __shared__ char sm[];
    const uint32_t sb = smem_u32(sm);
    const int tid = threadIdx.x, lane = tid & 31, wid = tid >> 5;
    const int wm = wid >> 1, wn = wid & 1;           // warp tile 32x64
    const int mbase = blockIdx.y * 128, nbase = blockIdx.x * 128;

    float acc[2][8][4];
#pragma unroll
    for (int mf = 0; mf < 2; mf++)
#pragma unroll
        for (int nf = 0; nf < 8; nf++)
#pragma unroll
            for (int q = 0; q < 4; q++) acc[mf][nf][q] = 0.f;

    const int nc = K / 64;
    gemm_stage128(sb, A, B, mbase, nbase, 0, K, tid);
    if (nc > 1) gemm_stage128(sb + ST128, A, B, mbase, nbase, 64, K, tid);

    const int a_row = (lane & 15);
    const int a_cb  = ((lane >> 4) & 1) * 16;
    const int mat   = lane >> 3;
    const int b_row = (lane & 7) + ((mat >> 1) & 1) * 8;
    const int b_cb  = (mat & 1) * 16;

    for (int c = 0; c < nc; c++) {
        if (c + 1 < nc) { CP_WAIT1(); } else { CP_WAIT0(); }
        __syncthreads();
        if (c + 2 < nc)
            gemm_stage128(sb + ((c + 2) % 3) * ST128, A, B,
                          mbase, nbase, (c + 2) * 64, K, tid);

        const uint32_t base = sb + (c % 3) * ST128;
#pragma unroll
        for (int ks = 0; ks < 4; ks++) {
            uint32_t av[2][4];
#pragma unroll
            for (int mf = 0; mf < 2; mf++) {
                uint32_t bo = (uint32_t)((wm * 32 + mf * 16 + a_row) * 128 + ks * 32 + a_cb);
                ldsm4(av[mf], base + swz(bo));
            }
            uint32_t bh[4][4];
#pragma unroll
            for (int bq = 0; bq < 4; bq++) {
                uint32_t bo = (uint32_t)((wn * 64 + bq * 16 + b_row) * 128 + ks * 32 + b_cb);
                ldsm4(bh[bq], base + 16384 + swz(bo));
            }
#pragma unroll
            for (int mf = 0; mf < 2; mf++)
#pragma unroll
                for (int bq = 0; bq < 4; bq++) {
                    mma16816(acc[mf][2 * bq],     av[mf], &bh[bq][0]);
                    mma16816(acc[mf][2 * bq + 1], av[mf], &bh[bq][2]);
                }
        }
    }

    const int r_in = lane >> 2, c_in = (lane & 3) * 2;
#pragma unroll
    for (int mf = 0; mf < 2; mf++)
#pragma unroll
        for (int nf = 0; nf < 8; nf++) {
            int row0 = mbase + wm * 32 + mf * 16 + r_in;
            int col  = nbase + wn * 64 + nf * 8 + c_in;
            if (col >= Nout) continue;
            float* q = acc[mf][nf];
            float e0 = repi(q[0], epi, extra, col);
            float e1 = repi(q[1], epi, extra, col + 1);
            float e2 = repi(q[2], epi, extra, col);
            float e3 = repi(q[3], epi, extra, col + 1);
            if (Ch == nullptr) {
                *(float2*)(Cf + (size_t)row0 * Nout + col) = make_float2(e0, e1);
                *(float2*)(Cf + (size_t)(row0 + 8) * Nout + col) = make_float2(e2, e3);
            } else {
                *(__half2*)(Ch + (size_t)row0 * Nout + col) = __floats2half2_rn(e0, e1);
                *(__half2*)(Ch + (size_t)(row0 + 8) * Nout + col) = __floats2half2_rn(e2, e3);
            }
        }
}

__global__ void __launch_bounds__(256, 2) gemm_one128(
    const __half* __restrict__ A, const __half* __restrict__ B,
    float* __restrict__ Cf, __half* __restrict__ Ch,
    int Nout, int K, const float* __restrict__ extra, int epi)
{
    gemm_core128(A, B, Cf, Ch, Nout, K, extra, epi);
}

// z = 0..3: r/k/v/g big GEMMs. z = 4: small td1 GEMM (overlapped).
__global__ void __launch_bounds__(256, 2) gemm_rkvg(
    const __half* rxh, const __half* wrh, float* r,
    const __half* kxh, const __half* wkh, float* k,
    const __half* vxh, const __half* wvh, float* v,
    const __half* gxh, const __half* wgh, float* g,
    const __half* wxh, const __half* td1h, __half* h1h)
{
    if (blockIdx.z == 4) {
        if (blockIdx.x != 0) return;
        gemm_core128(wxh, td1h, nullptr, h1h, 64, Dd, nullptr, 2);
        return;
    }
    const __half *A, *Bh; float* C; int epi;
    switch (blockIdx.z) {
        case 0:  A = rxh; Bh = wrh; C = r; epi = 1; break;
        case 1:  A = kxh; Bh = wkh; C = k; epi = 0; break;
        case 2:  A = vxh; Bh = wvh; C = v; epi = 0; break;
        default: A = gxh; Bh = wgh; C = g; epi = 3; break;
    }
    gemm_core128(A, Bh, C, nullptr, Dd, Dd, nullptr, epi);
}

// ============ 256x128 split-weight GEMM (W_o only; exact hi+lo) =============
#define ST1 65536u
#define GEMM_SMEM1 (3 * ST1)    // 196608

__device__ __forceinline__ void gemm_stage256s(uint32_t st,
    const __half* A, const __half* Bh, const __half* Bl,
    int mbase, int nbase, int k0, int K, int tid)
{
    load_tile_async<256>(st +     0, A,  mbase, k0, K, tid);
    load_tile_async<128>(st + 32768, Bh, nbase, k0, K, tid);
    load_tile_async<128>(st + 49152, Bl, nbase, k0, K, tid);
    CP_COMMIT();
}

__global__ void __launch_bounds__(256, 1) gemm_wo(
    const __half* __restrict__ A,
    const __half* __restrict__ Bh, const __half* __restrict__ Bl,
    float* __restrict__ Cf, int Nout, int K)
{
    extern __shared__ char sm[];
    const uint32_t sb = smem_u32(sm);
    const int tid = threadIdx.x, lane = tid & 31, wid = tid >> 5;
    const int wm = wid >> 1, wn = wid & 1;           // warp tile 64x64
    const int mbase = blockIdx.y * 256, nbase = blockIdx.x * 128;

    float acc[4][8][4];
#pragma unroll
    for (int mf = 0; mf < 4; mf++)
#pragma unroll
        for (int nf = 0; nf < 8; nf++)
#pragma unroll
            for (int q = 0; q < 4; q++) acc[mf][nf][q] = 0.f;

    const int nc = K / 64;
    gemm_stage256s(sb, A, Bh, Bl, mbase, nbase, 0, K, tid);
    if (nc > 1) gemm_stage256s(sb + ST1, A, Bh, Bl, mbase, nbase, 64, K, tid);

    const int a_row = (lane & 15);
    const int a_cb  = ((lane >> 4) & 1) * 16;
    const int mat   = lane >> 3;
    const int b_row = (lane & 7) + ((mat >> 1) & 1) * 8;
    const int b_cb  = (mat & 1) * 16;

    for (int c = 0; c < nc; c++) {
        if (c + 1 < nc) { CP_WAIT1(); } else { CP_WAIT0(); }
        __syncthreads();
        if (c + 2 < nc)
            gemm_stage256s(sb + ((c + 2) % 3) * ST1, A, Bh, Bl,
                           mbase, nbase, (c + 2) * 64, K, tid);

        const uint32_t base = sb + (c % 3) * ST1;
#pragma unroll
        for (int ks = 0; ks < 4; ks++) {
            uint32_t av[4][4];
#pragma unroll
            for (int mf = 0; mf < 4; mf++) {
                uint32_t bo = (uint32_t)((wm * 64 + mf * 16 + a_row) * 128 + ks * 32 + a_cb);
                ldsm4(av[mf], base + swz(bo));
            }
            uint32_t bh[4][4];
#pragma unroll
            for (int bq = 0; bq < 4; bq++) {
                uint32_t bo = (uint32_t)((wn * 64 + bq * 16 + b_row) * 128 + ks * 32 + b_cb);
                ldsm4(bh[bq], base + 32768 + swz(bo));
            }
#pragma unroll
            for (int mf = 0; mf < 4; mf++)
#pragma unroll
                for (int bq = 0; bq < 4; bq++) {
                    mma16816(acc[mf][2 * bq],     av[mf], &bh[bq][0]);
                    mma16816(acc[mf][2 * bq + 1], av[mf], &bh[bq][2]);
                }
            uint32_t bl[4][4];
#pragma unroll
            for (int bq = 0; bq < 4; bq++) {
                uint32_t bo = (uint32_t)((wn * 64 + bq * 16 + b_row) * 128 + ks * 32 + b_cb);
                ldsm4(bl[bq], base + 49152 + swz(bo));
            }
#pragma unroll
            for (int mf = 0; mf < 4; mf++)
#pragma unroll
                for (int bq = 0; bq < 4; bq++) {
                    mma16816(acc[mf][2 * bq],     av[mf], &bl[bq][0]);
                    mma16816(acc[mf][2 * bq + 1], av[mf], &bl[bq][2]);
                }
        }
    }

    const int r_in = lane >> 2, c_in = (lane & 3) * 2;
#pragma unroll
    for (int mf = 0; mf < 4; mf++)
#pragma unroll
        for (int nf = 0; nf < 8; nf++) {
            int row0 = mbase + wm * 64 + mf * 16 + r_in;
            int col  = nbase + wn * 64 + nf * 8 + c_in;
            float* q = acc[mf][nf];
            *(float2*)(Cf + (size_t)row0 * Nout + col) = make_float2(q[0], q[1]);
            *(float2*)(Cf + (size_t)(row0 + 8) * Nout + col) = make_float2(q[2], q[3]);
        }
}

// ====================== mega prologue launch ================================
struct TsArgs {
    const float* src[8];
    __half* bh[8];
    __half* bl[8];
    int K[8], N[8], gx[8], gy[8];
};

__global__ void __launch_bounds__(256) tsplit_all(TsArgs a,
    const float* __restrict__ tmw2, __half* __restrict__ tm2h,
    const float* __restrict__ x, const float* __restrict__ prev,
    const float* __restrict__ xmaa, __half* __restrict__ xh,
    float* __restrict__ xlast)
{
    const int z = blockIdx.z;
    const int tid = threadIdx.x;

    if (z == 8) {
        if (blockIdx.x >= 40 || blockIdx.y >= 32) return;
        int id = ((int)blockIdx.x * 32 + (int)blockIdx.y) * 256 + tid;
        tm2h[id] = __float2half_rn(tmw2[id]);
        return;
    }
    if (z == 9) {
        size_t base = ((size_t)blockIdx.x * 64 + blockIdx.y) * 4096;
#pragma unroll 4
        for (int j = 0; j < 16; j++) {
            size_t i = base + j * 256 + tid;
            int d = (int)(i % Dd);
            size_t bt = i / Dd;
            int t = (int)(bt & (Tt - 1));
            int b = (int)(bt >> 11);
            float xv = x[i];
            float sh = (t == 0) ? prev[(size_t)b * Dd + d] : x[i - Dd];
            xh[i] = __float2half_rn(fmaf(sh - xv, xmaa[d], xv));
        }
        return;
    }
    if (z == 10) {
        if (blockIdx.y != 0 || blockIdx.x >= 32) return;
        int i = (int)blockIdx.x * 256 + tid;
        int b = i / Dd, d = i % Dd;
        xlast[i] = x[((size_t)b * Tt + (Tt - 1)) * Dd + d];
        return;
    }

    if ((int)blockIdx.x >= a.gx[z] || (int)blockIdx.y >= a.gy[z]) return;
    const float* __restrict__ W = a.src[z];
    __half* __restrict__ bh = a.bh[z];
    __half* __restrict__ bl = a.bl[z];
    const int K = a.K[z], N = a.N[z];

    __shared__ float t[32][33];
    const int k0 = blockIdx.x * 32, n0 = blockIdx.y * 32;
    const int tx = tid & 31, ty = tid >> 5;
#pragma unroll
    for (int i = 0; i < 4; i++) {
        int kk = ty + i * 8;
        int n = n0 + tx;
        t[kk][tx] = (n < N) ? W[(size_t)(k0 + kk) * N + n] : 0.f;
    }
    __syncthreads();
#pragma unroll
    for (int i = 0; i < 4; i++) {
        int nn = ty + i * 8;
        float v = t[tx][nn];
        __half h = __float2half_rn(v);
        size_t o = (size_t)(n0 + nn) * K + k0 + tx;
        bh[o] = h;
        if (bl) bl[o] = __float2half_rn(v - __half2float(h));
    }
}

// ====================== mix: fp16 tiles, single-sync pipeline ===============
__global__ void __launch_bounds__(256) mix_k(
    const float* __restrict__ x, const float* __restrict__ prev,
    const float* __restrict__ m, const __half* __restrict__ tm2h,
    const float* __restrict__ wmaa, const float* __restrict__ kmaa,
    const float* __restrict__ vmaa, const float* __restrict__ rmaa,
    const float* __restrict__ gmaa,
    __half* __restrict__ wxh, __half* __restrict__ kxh,
    __half* __restrict__ vxh, __half* __restrict__ rxh,
    __half* __restrict__ gxh)
{
    __shared__ float msh[E5c][8];
    __shared__ __half tileh[2][32][256];
    const int tid = threadIdx.x;
    const int dbase = blockIdx.x * 256;
    const int tb = blockIdx.y * 8;

#pragma unroll
    for (int i = 0; i < 4; i++) {
        int j = i * 256 + tid;
        int e = j >> 5, c8 = (j & 31) << 3;
        CP_ASYNC16(smem_u32(&tileh[0][e][c8]),
                   tm2h + (size_t)e * Dd + dbase + c8);
    }
    CP_COMMIT();

    for (int i = tid; i < 8 * E5c; i += 256) {
        int tok = i / E5c, e5 = i % E5c;
        msh[e5][tok] = m[(size_t)(tb + tok) * E5c + e5];
    }

    float acc[8][5];
#pragma unroll
    for (int tok = 0; tok < 8; tok++)
#pragma unroll
        for (int f = 0; f < 5; f++) acc[tok][f] = 0.f;

#pragma unroll
    for (int f = 0; f < 5; f++) {
        CP_WAIT0();
        __syncthreads();
        if (f + 1 < 5) {
            const int nb = (f + 1) & 1;
#pragma unroll
            for (int i = 0; i < 4; i++) {
                int j = i * 256 + tid;
                int e = j >> 5, c8 = (j & 31) << 3;
                CP_ASYNC16(smem_u32(&tileh[nb][e][c8]),
                           tm2h + (size_t)((f + 1) * 32 + e) * Dd + dbase + c8);
            }
            CP_COMMIT();
        }

        const int cb = f & 1;
#pragma unroll
        for (int e = 0; e < 32; e++) {
            float tv = __half2float(tileh[cb][e][tid]);
            float4 m0 = *(const float4*)&msh[f * 32 + e][0];
            float4 m1 = *(const float4*)&msh[f * 32 + e][4];
            acc[0][f] = fmaf(m0.x, tv, acc[0][f]);
            acc[1][f] = fmaf(m0.y, tv, acc[1][f]);
            acc[2][f] = fmaf(m0.z, tv, acc[2][f]);
            acc[3][f] = fmaf(m0.w, tv, acc[3][f]);
            acc[4][f] = fmaf(m1.x, tv, acc[4][f]);
            acc[5][f] = fmaf(m1.y, tv, acc[5][f]);
            acc[6][f] = fmaf(m1.z, tv, acc[6][f]);
            acc[7][f] = fmaf(m1.w, tv, acc[7][f]);
        }
    }

    const int d = dbase + tid;
    const float wm = wmaa[d], km = kmaa[d], vm = vmaa[d], rm = rmaa[d], gm = gmaa[d];
#pragma unroll
    for (int tok = 0; tok < 8; tok++) {
        int bt = tb + tok;
        int t = bt & (Tt - 1), b = bt >> 11;
        size_t idx = (size_t)bt * Dd + d;
        float xv = x[idx];
        float sh = (t == 0) ? prev[(size_t)b * Dd + d] : x[idx - Dd];
        float sv = sh - xv;
        wxh[idx] = __float2half_rn(fmaf(sv, wm + acc[tok][0], xv));
        kxh[idx] = __float2half_rn(fmaf(sv, km + acc[tok][1], xv));
        vxh[idx] = __float2half_rn(fmaf(sv, vm + acc[tok][2], xv));
        rxh[idx] = __float2half_rn(fmaf(sv, rm + acc[tok][3], xv));
        gxh[idx] = __float2half_rn(fmaf(sv, gm + acc[tok][4], xv));
    }
}

// ====================== WKV scan: 16-step blocks, float4 staging ============
__global__ void __launch_bounds__(256) wkv_k(
    const float* __restrict__ r, const float* __restrict__ k,
    const float* __restrict__ v, const float* __restrict__ w,
    const float* __restrict__ u, const float* __restrict__ s0,
    float* __restrict__ att, float* __restrict__ sout)
{
    __shared__ float rs[3][16][64], ksm[3][16][64], wsm[3][16][64], vsm[3][16][64];
    __shared__ float osh[3][16][64];

    const int bh = blockIdx.x, b = bh >> 5, h = bh & 31;
    const int tid = threadIdx.x;
    const int vcol = tid >> 2, kg = tid & 3;
    const int st_ = tid >> 4;
    const int si  = (tid & 15) * 4;

    const size_t base0 = (size_t)b * Tt * Dd + h * 64;
    const size_t sbase = (size_t)bh * 4096;

    float s[16], uo[16];
#pragma unroll
    for (int j = 0; j < 16; j++) {
        s[j]  = s0[sbase + (size_t)(kg * 16 + j) * 64 + vcol];
        uo[j] = u[h * 64 + kg * 16 + j];
    }

    {
        size_t g = base0 + (size_t)st_ * Dd + si;
        CP_ASYNC16(smem_u32(&rs[0][st_][si]),  r + g);
        CP_ASYNC16(smem_u32(&ksm[0][st_][si]), k + g);
        CP_ASYNC16(smem_u32(&wsm[0][st_][si]), w + g);
        CP_ASYNC16(smem_u32(&vsm[0][st_][si]), v + g);
        CP_COMMIT();
    }

    const int NB = Tt / 16;
    int buf = 0;
    for (int nb = 0; nb < NB; nb++) {
        buf = nb % 3;
        const int nxt = (nb + 1) % 3;
        if (nb + 1 < NB) {
            size_t g = base0 + (size_t)((nb + 1) * 16 + st_) * Dd + si;
            CP_ASYNC16(smem_u32(&rs[nxt][st_][si]),  r + g);
            CP_ASYNC16(smem_u32(&ksm[nxt][st_][si]), k + g);
            CP_ASYNC16(smem_u32(&wsm[nxt][st_][si]), w + g);
            CP_ASYNC16(smem_u32(&vsm[nxt][st_][si]), v + g);
            CP_COMMIT();
            CP_WAIT1();
        } else {
            CP_WAIT0();
        }
        __syncthreads();

        if (nb > 0) {
            const int pb = (nb - 1) % 3;
            *(float4*)&att[base0 + (size_t)((nb - 1) * 16 + st_) * Dd + si] =
                *(const float4*)&osh[pb][st_][si];
        }

#pragma unroll 4
        for (int t = 0; t < 16; t++) {
            const float vm = vsm[buf][t][vcol];
            float a = 0.f;
            const float* rp = &rs[buf][t][kg * 16];
            const float* kp = &ksm[buf][t][kg * 16];
            const float* wp = &wsm[buf][t][kg * 16];
#pragma unroll
            for (int q = 0; q < 4; q++) {
                float4 r4 = *(const float4*)(rp + 4 * q);
                float4 k4 = *(const float4*)(kp + 4 * q);
                float4 w4 = *(const float4*)(wp + 4 * q);
                float kv, tt;
                kv = k4.x * vm; tt = fmaf(uo[4*q+0], kv, s[4*q+0]); a = fmaf(r4.x, tt, a); s[4*q+0] = fmaf(s[4*q+0], w4.x, kv);
                kv = k4.y * vm; tt = fmaf(uo[4*q+1], kv, s[4*q+1]); a = fmaf(r4.y, tt, a); s[4*q+1] = fmaf(s[4*q+1], w4.y, kv);
                kv = k4.z * vm; tt = fmaf(uo[4*q+2], kv, s[4*q+2]); a = fmaf(r4.z, tt, a); s[4*q+2] = fmaf(s[4*q+2], w4.z, kv);
                kv = k4.w * vm; tt = fmaf(uo[4*q+3], kv, s[4*q+3]); a = fmaf(r4.w, tt, a); s[4*q+3] = fmaf(s[4*q+3], w4.w, kv);
            }
            a += __shfl_xor_sync(0xffffffffu, a, 1);
            a += __shfl_xor_sync(0xffffffffu, a, 2);
            if (kg == 0) osh[buf][t][vcol] = a;
        }
    }
    __syncthreads();
    *(float4*)&att[base0 + (size_t)((NB - 1) * 16 + st_) * Dd + si] =
        *(const float4*)&osh[buf][st_][si];
#pragma unroll
    for (int j = 0; j < 16; j++)
        sout[sbase + (size_t)(kg * 16 + j) * 64 + vcol] = s[j];
}

// ====================== groupnorm + ln + *g, writes fp16 ====================
__global__ void __launch_bounds__(256) gnorm_k(
    const float* __restrict__ att, const float* __restrict__ g,
    const float* __restrict__ lng, const float* __restrict__ lnb,
    __half* __restrict__ oh)
{
    const int grp = blockIdx.x * 8 + (threadIdx.x >> 5);
    const int lane = threadIdx.x & 31;
    const int bt = grp >> 5;
    const int h = grp & 31;
    size_t base = (size_t)bt * Dd + h * 64;
    float v0 = att[base + lane];
    float v1 = att[base + lane + 32];
    float sum = v0 + v1;
    float sq = v0 * v0 + v1 * v1;
#pragma unroll
    for (int o = 16; o > 0; o >>= 1) {
        sum += __shfl_xor_sync(0xffffffffu, sum, o);
        sq  += __shfl_xor_sync(0xffffffffu, sq, o);
    }
    float mu = sum * (1.f / 64.f);
    float var = sq * (1.f / 64.f) - mu * mu;
    float inv = rsqrtf(var + 1e-5f);
    int li = h * 64 + lane;
    oh[base + lane] = __float2half_rn(
        fmaf((v0 - mu) * inv, lng[li], lnb[li]) * g[base + lane]);
    oh[base + lane + 32] = __float2half_rn(
        fmaf((v1 - mu) * inv, lng[li + 32], lnb[li + 32]) * g[base + lane + 32]);
}

// ====================== host ================================================
extern "C" void kernel_launch(void* const* d_in, const int* in_sizes, int n_in,
                              void* d_out, int out_size)
{
    const float* x     = (const float*)d_in[0];
    const float* prev  = (const float*)d_in[1];
    const float* state = (const float*)d_in[2];
    const float* x_maa = (const float*)d_in[3];
    const float* w_maa = (const float*)d_in[4];
    const float* k_maa = (const float*)d_in[5];
    const float* v_maa = (const float*)d_in[6];
    const float* r_maa = (const float*)d_in[7];
    const float* g_maa = (const float*)d_in[8];
    const float* tm_w1 = (const float*)d_in[9];
    const float* tm_w2 = (const float*)d_in[10];
    const float* td_w1 = (const float*)d_in[11];
    const float* td_w2 = (const float*)d_in[12];
    const float* tdec  = (const float*)d_in[13];
    const float* tfirst= (const float*)d_in[14];
    const float* W_r   = (const float*)d_in[15];
    const float* W_k   = (const float*)d_in[16];
    const float* W_v   = (const float*)d_in[17];
    const float* W_g   = (const float*)d_in[18];
    const float* W_o   = (const float*)d_in[19];
    const float* ln_g  = (const float*)d_in[20];
    const float* ln_b  = (const float*)d_in[21];

    float *m, *r, *k, *v, *g, *w, *att;
    cudaGetSymbolAddress((void**)&m,   g_m);
    cudaGetSymbolAddress((void**)&r,   g_r);
    cudaGetSymbolAddress((void**)&k,   g_k);
    cudaGetSymbolAddress((void**)&v,   g_v);
    cudaGetSymbolAddress((void**)&g,   g_g);
    cudaGetSymbolAddress((void**)&w,   g_w);
    cudaGetSymbolAddress((void**)&att, g_att);

    __half *xh, *wxh, *kxh, *vxh, *rxh, *gxh, *gnh, *h1h;
    __half *wrh, *wkh, *wvh, *wgh, *woh, *wol, *tm1h, *td1h, *td2h, *tm2h;
    cudaGetSymbolAddress((void**)&xh,  g_xh);
    cudaGetSymbolAddress((void**)&wxh, g_wxh);
    cudaGetSymbolAddress((void**)&kxh, g_kxh);
    cudaGetSymbolAddress((void**)&vxh, g_vxh);
    cudaGetSymbolAddress((void**)&rxh, g_rxh);
    cudaGetSymbolAddress((void**)&gxh, g_gxh);
    cudaGetSymbolAddress((void**)&gnh, g_gnh);
    cudaGetSymbolAddress((void**)&h1h, g_h1h);
    cudaGetSymbolAddress((void**)&wrh, g_wrh);
    cudaGetSymbolAddress((void**)&wkh, g_wkh);
    cudaGetSymbolAddress((void**)&wvh, g_wvh);
    cudaGetSymbolAddress((void**)&wgh, g_wgh);
    cudaGetSymbolAddress((void**)&woh, g_woh);
    cudaGetSymbolAddress((void**)&wol, g_wol);
    cudaGetSymbolAddress((void**)&tm1h, g_tm1h);
    cudaGetSymbolAddress((void**)&td1h, g_td1h);
    cudaGetSymbolAddress((void**)&td2h, g_td2h);
    cudaGetSymbolAddress((void**)&tm2h, g_tm2h);

    float* out0 = (float*)d_out;
    float* out_xlast = out0 + (size_t)BT * Dd;
    float* out_state = out_xlast + (size_t)Bb * Dd;

    cudaFuncSetAttribute(gemm_one128, cudaFuncAttributeMaxDynamicSharedMemorySize, GEMM_SMEM128);
    cudaFuncSetAttribute(gemm_rkvg,   cudaFuncAttributeMaxDynamicSharedMemorySize, GEMM_SMEM128);
    cudaFuncSetAttribute(gemm_wo,     cudaFuncAttributeMaxDynamicSharedMemorySize, GEMM_SMEM1);

    // ---- [0] mega prologue: weights + tm_w2 fp16 + prep + lastcopy ----
    TsArgs ta;
    ta.src[0]=W_r;  ta.bh[0]=wrh;  ta.bl[0]=nullptr; ta.K[0]=Dd; ta.N[0]=Dd;  ta.gx[0]=64; ta.gy[0]=64;
    ta.src[1]=W_k;  ta.bh[1]=wkh;  ta.bl[1]=nullptr; ta.K[1]=Dd; ta.N[1]=Dd;  ta.gx[1]=64; ta.gy[1]=64;
    ta.src[2]=W_v;  ta.bh[2]=wvh;  ta.bl[2]=nullptr; ta.K[2]=Dd; ta.N[2]=Dd;  ta.gx[2]=64; ta.gy[2]=64;
    ta.src[3]=W_g;  ta.bh[3]=wgh;  ta.bl[3]=nullptr; ta.K[3]=Dd; ta.N[3]=Dd;  ta.gx[3]=64; ta.gy[3]=64;
    ta.src[4]=W_o;  ta.bh[4]=woh;  ta.bl[4]=wol;     ta.K[4]=Dd; ta.N[4]=Dd;  ta.gx[4]=64; ta.gy[4]=64;
    ta.src[5]=tm_w1;ta.bh[5]=tm1h; ta.bl[5]=nullptr; ta.K[5]=Dd; ta.N[5]=E5c; ta.gx[5]=64; ta.gy[5]=8;
    ta.src[6]=td_w1;ta.bh[6]=td1h; ta.bl[6]=nullptr; ta.K[6]=Dd; ta.N[6]=64;  ta.gx[6]=64; ta.gy[6]=4;
    ta.src[7]=td_w2;ta.bh[7]=td2h; ta.bl[7]=nullptr; ta.K[7]=64; ta.N[7]=Dd;  ta.gx[7]=2;  ta.gy[7]=64;
    tsplit_all<<<dim3(64, 64, 11), 256>>>(ta, tm_w2, tm2h,
                                          x, prev, x_maa, xh, out_xlast);

    // ---- [1] m = tanh(xxx @ tm_w1) ----
    gemm_one128<<<dim3(2, BT/128), 256, GEMM_SMEM128>>>(xh, tm1h,
        m, nullptr, E5c, Dd, nullptr, 2);
    // ---- [2] mix + 5 lerps (fp16) ----
    mix_k<<<dim3(Dd/256, BT/8), 256>>>(x, prev, m, tm2h,
        w_maa, k_maa, v_maa, r_maa, g_maa,
        wxh, kxh, vxh, rxh, gxh);
    // ---- [3] big GEMMs r/k/v/g + overlapped td1 (z=4) ----
    gemm_rkvg<<<dim3(Dd/128, BT/128, 5), 256, GEMM_SMEM128>>>(
        rxh, wrh, r,
        kxh, wkh, k,
        vxh, wvh, v,
        gxh, wgh, g,
        wxh, td1h, h1h);
    // ---- [4] td2: w = exp(-exp(h1 @ td_w2 + decay)) ----
    gemm_one128<<<dim3(Dd/128, BT/128), 256, GEMM_SMEM128>>>(h1h, td2h,
        w, nullptr, Dd, 64, tdec, 4);
    // ---- [5] WKV scan ----
    wkv_k<<<Bb * Hh, 256>>>(r, k, v, w, tfirst, state, att, out_state);
    // ---- [6] groupnorm * ln * g (fp16) ----
    gnorm_k<<<(BT * Hh) / 8, 256>>>(att, g, ln_g, ln_b, gnh);
    // ---- [7] out = gn @ W_o (exact split weights, 256-tile) ----
    gemm_wo<<<dim3(Dd/128, BT/256), 256, GEMM_SMEM1>>>(gnh, woh, wol,
        out0, Dd, Dd);
}

// round 16
// speedup vs baseline: 8.4134x; 1.0840x over previous
#include <cuda_runtime.h>
#include <cuda_fp16.h>
#include <math.h>
#include <stdint.h>

#define Bb 4
#define Tt 2048
#define Dd 2048
#define Hh 32
#define HSz 64
#define BT (Bb*Tt)
#define E5c 160

// ====================== device scratch (bss, no alloc) ======================
__device__ float g_m  [BT*E5c];
__device__ float g_r  [BT*Dd];
__device__ float g_k  [BT*Dd];
__device__ float g_v  [BT*Dd];
__device__ float g_g  [BT*Dd];
__device__ float g_w  [BT*Dd];
__device__ float g_att[BT*Dd];

__device__ __half g_xh [BT*Dd];
__device__ __half g_wxh[BT*Dd];
__device__ __half g_kxh[BT*Dd];
__device__ __half g_vxh[BT*Dd];
__device__ __half g_rxh[BT*Dd];
__device__ __half g_gxh[BT*Dd];
__device__ __half g_gnh[BT*Dd];
__device__ __half g_h1h[BT*64];

__device__ __half g_wrh[Dd*Dd];
__device__ __half g_wkh[Dd*Dd];
__device__ __half g_wvh[Dd*Dd];
__device__ __half g_wgh[Dd*Dd];
__device__ __half g_woh[Dd*Dd];
__device__ __half g_tm1h[256*Dd];
__device__ __half g_td1h[128*Dd];
__device__ __half g_td2h[Dd*64];
__device__ __half g_tm2h[5*32*Dd];              // tm_w2 in fp16

// ====================== PTX helpers (sm_80-class only) ======================
__device__ __forceinline__ uint32_t smem_u32(const void* p) {
    uint32_t a;
    asm("{ .reg .u64 t; cvta.to.shared.u64 t, %1; cvt.u32.u64 %0, t; }"
        : "=r"(a) : "l"(p));
    return a;
}

#define CP_ASYNC16(dst, src) \
    asm volatile("cp.async.cg.shared.global [%0], [%1], 16;" \
        :: "r"(dst), "l"(src) : "memory")
#define CP_COMMIT() asm volatile("cp.async.commit_group;" ::: "memory")
#define CP_WAIT0()  asm volatile("cp.async.wait_group 0;" ::: "memory")
#define CP_WAIT1()  asm volatile("cp.async.wait_group 1;" ::: "memory")

__device__ __forceinline__ void ldsm4(uint32_t* r, uint32_t addr) {
    asm volatile("ldmatrix.sync.aligned.m8n8.x4.shared.b16 {%0,%1,%2,%3},[%4];"
        : "=r"(r[0]), "=r"(r[1]), "=r"(r[2]), "=r"(r[3]) : "r"(addr));
}

__device__ __forceinline__ void mma16816(float* c, const uint32_t* a, const uint32_t* b) {
    asm volatile(
        "mma.sync.aligned.m16n8k16.row.col.f32.f16.f16.f32 "
        "{%0,%1,%2,%3},{%4,%5,%6,%7},{%8,%9},{%0,%1,%2,%3};"
        : "+f"(c[0]), "+f"(c[1]), "+f"(c[2]), "+f"(c[3])
        : "r"(a[0]), "r"(a[1]), "r"(a[2]), "r"(a[3]), "r"(b[0]), "r"(b[1]));
}

__device__ __forceinline__ uint32_t swz(uint32_t bo) { return bo ^ ((bo >> 3) & 0x70); }

__device__ __forceinline__ float repi(float v, int epi, const float* extra, int n) {
    switch (epi) {
        case 1: return 1.f / (1.f + expf(-v));
        case 2: return tanhf(v);
        case 3: return v / (1.f + expf(-v));
        case 4: return expf(-expf(v + extra[n]));
        default: return v;
    }
}

template<int ROWS>
__device__ __forceinline__ void load_tile_async(uint32_t sbase,
    const __half* __restrict__ src, int row0, int k0, int ldK, int tid)
{
#pragma unroll
    for (int i = 0; i < ROWS / 32; i++) {
        int u = i * 256 + tid;
        int row = u >> 3, cc = u & 7;
        uint32_t bo = (uint32_t)(row * 128 + cc * 16);
        CP_ASYNC16(sbase + swz(bo),
                   src + (size_t)(row0 + row) * ldK + k0 + cc * 8);
    }
}

// ============ 128x128 tile GEMM core (2 CTAs/SM) ============================
#define ST128 32768u
#define GEMM_SMEM128 (3 * ST128)    // 98304

__device__ __forceinline__ void gemm_stage128(uint32_t st,
    const __half* A, const __half* B,
    int mbase, int nbase, int k0, int K, int tid)
{
    load_tile_async<128>(st +     0, A, mbase, k0, K, tid);
    load_tile_async<128>(st + 16384, B, nbase, k0, K, tid);
    CP_COMMIT();
}

__device__ __forceinline__ void gemm_core128(
    const __half* __restrict__ A, const __half* __restrict__ B,
    float* __restrict__ Cf, __half* __restrict__ Ch,
    int Nout, int K, const float* __restrict__ extra, int epi)
{
    extern __shared__ char sm[];
    const uint32_t sb = smem_u32(sm);
    const int tid = threadIdx.x, lane = tid & 31, wid = tid >> 5;
    const int wm = wid >> 1, wn = wid & 1;           // warp tile 32x64
    const int mbase = blockIdx.y * 128, nbase = blockIdx.x * 128;

    float acc[2][8][4];
#pragma unroll
    for (int mf = 0; mf < 2; mf++)
#pragma unroll
        for (int nf = 0; nf < 8; nf++)
#pragma unroll
            for (int q = 0; q < 4; q++) acc[mf][nf][q] = 0.f;

    const int nc = K / 64;
    gemm_stage128(sb, A, B, mbase, nbase, 0, K, tid);
    if (nc > 1) gemm_stage128(sb + ST128, A, B, mbase, nbase, 64, K, tid);

    const int a_row = (lane & 15);
    const int a_cb  = ((lane >> 4) & 1) * 16;
    const int mat   = lane >> 3;
    const int b_row = (lane & 7) + ((mat >> 1) & 1) * 8;
    const int b_cb  = (mat & 1) * 16;

    for (int c = 0; c < nc; c++) {
        if (c + 1 < nc) { CP_WAIT1(); } else { CP_WAIT0(); }
        __syncthreads();
        if (c + 2 < nc)
            gemm_stage128(sb + ((c + 2) % 3) * ST128, A, B,
                          mbase, nbase, (c + 2) * 64, K, tid);

        const uint32_t base = sb + (c % 3) * ST128;
#pragma unroll
        for (int ks = 0; ks < 4; ks++) {
            uint32_t av[2][4];
#pragma unroll
            for (int mf = 0; mf < 2; mf++) {
                uint32_t bo = (uint32_t)((wm * 32 + mf * 16 + a_row) * 128 + ks * 32 + a_cb);
                ldsm4(av[mf], base + swz(bo));
            }
            uint32_t bh[4][4];
#pragma unroll
            for (int bq = 0; bq < 4; bq++) {
                uint32_t bo = (uint32_t)((wn * 64 + bq * 16 + b_row) * 128 + ks * 32 + b_cb);
                ldsm4(bh[bq], base + 16384 + swz(bo));
            }
#pragma unroll
            for (int mf = 0; mf < 2; mf++)
#pragma unroll
                for (int bq = 0; bq < 4; bq++) {
                    mma16816(acc[mf][2 * bq],     av[mf], &bh[bq][0]);
                    mma16816(acc[mf][2 * bq + 1], av[mf], &bh[bq][2]);
                }
        }
    }

    const int r_in = lane >> 2, c_in = (lane & 3) * 2;
#pragma unroll
    for (int mf = 0; mf < 2; mf++)
#pragma unroll
        for (int nf = 0; nf < 8; nf++) {
            int row0 = mbase + wm * 32 + mf * 16 + r_in;
            int col  = nbase + wn * 64 + nf * 8 + c_in;
            if (col >= Nout) continue;
            float* q = acc[mf][nf];
            float e0 = repi(q[0], epi, extra, col);
            float e1 = repi(q[1], epi, extra, col + 1);
            float e2 = repi(q[2], epi, extra, col);
            float e3 = repi(q[3], epi, extra, col + 1);
            if (Ch == nullptr) {
                *(float2*)(Cf + (size_t)row0 * Nout + col) = make_float2(e0, e1);
                *(float2*)(Cf + (size_t)(row0 + 8) * Nout + col) = make_float2(e2, e3);
            } else {
                *(__half2*)(Ch + (size_t)row0 * Nout + col) = __floats2half2_rn(e0, e1);
                *(__half2*)(Ch + (size_t)(row0 + 8) * Nout + col) = __floats2half2_rn(e2, e3);
            }
        }
}

__global__ void __launch_bounds__(256, 2) gemm_one128(
    const __half* __restrict__ A, const __half* __restrict__ B,
    float* __restrict__ Cf, __half* __restrict__ Ch,
    int Nout, int K, const float* __restrict__ extra, int epi)
{
    gemm_core128(A, B, Cf, Ch, Nout, K, extra, epi);
}

// z = 0..3: r/k/v/g big GEMMs. z = 4: small td1 GEMM (overlapped).
__global__ void __launch_bounds__(256, 2) gemm_rkvg(
    const __half* rxh, const __half* wrh, float* r,
    const __half* kxh, const __half* wkh, float* k,
    const __half* vxh, const __half* wvh, float* v,
    const __half* gxh, const __half* wgh, float* g,
    const __half* wxh, const __half* td1h, __half* h1h)
{
    if (blockIdx.z == 4) {
        if (blockIdx.x != 0) return;
        gemm_core128(wxh, td1h, nullptr, h1h, 64, Dd, nullptr, 2);
        return;
    }
    const __half *A, *Bh; float* C; int epi;
    switch (blockIdx.z) {
        case 0:  A = rxh; Bh = wrh; C = r; epi = 1; break;
        case 1:  A = kxh; Bh = wkh; C = k; epi = 0; break;
        case 2:  A = vxh; Bh = wvh; C = v; epi = 0; break;
        default: A = gxh; Bh = wgh; C = g; epi = 3; break;
    }
    gemm_core128(A, Bh, C, nullptr, Dd, Dd, nullptr, epi);
}

// ====================== mega prologue launch ================================
struct TsArgs {
    const float* src[8];
    __half* bh[8];
    int K[8], N[8], gx[8], gy[8];
};

__global__ void __launch_bounds__(256) tsplit_all(TsArgs a,
    const float* __restrict__ tmw2, __half* __restrict__ tm2h,
    const float* __restrict__ x, const float* __restrict__ prev,
    const float* __restrict__ xmaa, __half* __restrict__ xh,
    float* __restrict__ xlast)
{
    const int z = blockIdx.z;
    const int tid = threadIdx.x;

    if (z == 8) {
        if (blockIdx.x >= 40 || blockIdx.y >= 32) return;
        int id = ((int)blockIdx.x * 32 + (int)blockIdx.y) * 256 + tid;
        tm2h[id] = __float2half_rn(tmw2[id]);
        return;
    }
    if (z == 9) {
        size_t base = ((size_t)blockIdx.x * 64 + blockIdx.y) * 4096;
#pragma unroll 4
        for (int j = 0; j < 16; j++) {
            size_t i = base + j * 256 + tid;
            int d = (int)(i % Dd);
            size_t bt = i / Dd;
            int t = (int)(bt & (Tt - 1));
            int b = (int)(bt >> 11);
            float xv = x[i];
            float sh = (t == 0) ? prev[(size_t)b * Dd + d] : x[i - Dd];
            xh[i] = __float2half_rn(fmaf(sh - xv, xmaa[d], xv));
        }
        return;
    }
    if (z == 10) {
        if (blockIdx.y != 0 || blockIdx.x >= 32) return;
        int i = (int)blockIdx.x * 256 + tid;
        int b = i / Dd, d = i % Dd;
        xlast[i] = x[((size_t)b * Tt + (Tt - 1)) * Dd + d];
        return;
    }

    if ((int)blockIdx.x >= a.gx[z] || (int)blockIdx.y >= a.gy[z]) return;
    const float* __restrict__ W = a.src[z];
    __half* __restrict__ bh = a.bh[z];
    const int K = a.K[z], N = a.N[z];

    __shared__ float t[32][33];
    const int k0 = blockIdx.x * 32, n0 = blockIdx.y * 32;
    const int tx = tid & 31, ty = tid >> 5;
#pragma unroll
    for (int i = 0; i < 4; i++) {
        int kk = ty + i * 8;
        int n = n0 + tx;
        t[kk][tx] = (n < N) ? W[(size_t)(k0 + kk) * N + n] : 0.f;
    }
    __syncthreads();
#pragma unroll
    for (int i = 0; i < 4; i++) {
        int nn = ty + i * 8;
        bh[(size_t)(n0 + nn) * K + k0 + tx] = __float2half_rn(t[tx][nn]);
    }
}

// ====================== mix: fp16 tiles, single-sync pipeline ===============
__global__ void __launch_bounds__(256) mix_k(
    const float* __restrict__ x, const float* __restrict__ prev,
    const float* __restrict__ m, const __half* __restrict__ tm2h,
    const float* __restrict__ wmaa, const float* __restrict__ kmaa,
    const float* __restrict__ vmaa, const float* __restrict__ rmaa,
    const float* __restrict__ gmaa,
    __half* __restrict__ wxh, __half* __restrict__ kxh,
    __half* __restrict__ vxh, __half* __restrict__ rxh,
    __half* __restrict__ gxh)
{
    __shared__ float msh[E5c][8];
    __shared__ __half tileh[2][32][256];
    const int tid = threadIdx.x;
    const int dbase = blockIdx.x * 256;
    const int tb = blockIdx.y * 8;

#pragma unroll
    for (int i = 0; i < 4; i++) {
        int j = i * 256 + tid;
        int e = j >> 5, c8 = (j & 31) << 3;
        CP_ASYNC16(smem_u32(&tileh[0][e][c8]),
                   tm2h + (size_t)e * Dd + dbase + c8);
    }
    CP_COMMIT();

    for (int i = tid; i < 8 * E5c; i += 256) {
        int tok = i / E5c, e5 = i % E5c;
        msh[e5][tok] = m[(size_t)(tb + tok) * E5c + e5];
    }

    float acc[8][5];
#pragma unroll
    for (int tok = 0; tok < 8; tok++)
#pragma unroll
        for (int f = 0; f < 5; f++) acc[tok][f] = 0.f;

#pragma unroll
    for (int f = 0; f < 5; f++) {
        CP_WAIT0();
        __syncthreads();
        if (f + 1 < 5) {
            const int nb = (f + 1) & 1;
#pragma unroll
            for (int i = 0; i < 4; i++) {
                int j = i * 256 + tid;
                int e = j >> 5, c8 = (j & 31) << 3;
                CP_ASYNC16(smem_u32(&tileh[nb][e][c8]),
                           tm2h + (size_t)((f + 1) * 32 + e) * Dd + dbase + c8);
            }
            CP_COMMIT();
        }

        const int cb = f & 1;
#pragma unroll
        for (int e = 0; e < 32; e++) {
            float tv = __half2float(tileh[cb][e][tid]);
            float4 m0 = *(const float4*)&msh[f * 32 + e][0];
            float4 m1 = *(const float4*)&msh[f * 32 + e][4];
            acc[0][f] = fmaf(m0.x, tv, acc[0][f]);
            acc[1][f] = fmaf(m0.y, tv, acc[1][f]);
            acc[2][f] = fmaf(m0.z, tv, acc[2][f]);
            acc[3][f] = fmaf(m0.w, tv, acc[3][f]);
            acc[4][f] = fmaf(m1.x, tv, acc[4][f]);
            acc[5][f] = fmaf(m1.y, tv, acc[5][f]);
            acc[6][f] = fmaf(m1.z, tv, acc[6][f]);
            acc[7][f] = fmaf(m1.w, tv, acc[7][f]);
        }
    }

    const int d = dbase + tid;
    const float wm = wmaa[d], km = kmaa[d], vm = vmaa[d], rm = rmaa[d], gm = gmaa[d];
#pragma unroll
    for (int tok = 0; tok < 8; tok++) {
        int bt = tb + tok;
        int t = bt & (Tt - 1), b = bt >> 11;
        size_t idx = (size_t)bt * Dd + d;
        float xv = x[idx];
        float sh = (t == 0) ? prev[(size_t)b * Dd + d] : x[idx - Dd];
        float sv = sh - xv;
        wxh[idx] = __float2half_rn(fmaf(sv, wm + acc[tok][0], xv));
        kxh[idx] = __float2half_rn(fmaf(sv, km + acc[tok][1], xv));
        vxh[idx] = __float2half_rn(fmaf(sv, vm + acc[tok][2], xv));
        rxh[idx] = __float2half_rn(fmaf(sv, rm + acc[tok][3], xv));
        gxh[idx] = __float2half_rn(fmaf(sv, gm + acc[tok][4], xv));
    }
}

// ====================== WKV scan: 16-step blocks, float4 staging ============
__global__ void __launch_bounds__(256) wkv_k(
    const float* __restrict__ r, const float* __restrict__ k,
    const float* __restrict__ v, const float* __restrict__ w,
    const float* __restrict__ u, const float* __restrict__ s0,
    float* __restrict__ att, float* __restrict__ sout)
{
    __shared__ float rs[3][16][64], ksm[3][16][64], wsm[3][16][64], vsm[3][16][64];
    __shared__ float osh[3][16][64];

    const int bh = blockIdx.x, b = bh >> 5, h = bh & 31;
    const int tid = threadIdx.x;
    const int vcol = tid >> 2, kg = tid & 3;
    const int st_ = tid >> 4;
    const int si  = (tid & 15) * 4;

    const size_t base0 = (size_t)b * Tt * Dd + h * 64;
    const size_t sbase = (size_t)bh * 4096;

    float s[16], uo[16];
#pragma unroll
    for (int j = 0; j < 16; j++) {
        s[j]  = s0[sbase + (size_t)(kg * 16 + j) * 64 + vcol];
        uo[j] = u[h * 64 + kg * 16 + j];
    }

    {
        size_t g = base0 + (size_t)st_ * Dd + si;
        CP_ASYNC16(smem_u32(&rs[0][st_][si]),  r + g);
        CP_ASYNC16(smem_u32(&ksm[0][st_][si]), k + g);
        CP_ASYNC16(smem_u32(&wsm[0][st_][si]), w + g);
        CP_ASYNC16(smem_u32(&vsm[0][st_][si]), v + g);
        CP_COMMIT();
    }

    const int NB = Tt / 16;
    int buf = 0;
    for (int nb = 0; nb < NB; nb++) {
        buf = nb % 3;
        const int nxt = (nb + 1) % 3;
        if (nb + 1 < NB) {
            size_t g = base0 + (size_t)((nb + 1) * 16 + st_) * Dd + si;
            CP_ASYNC16(smem_u32(&rs[nxt][st_][si]),  r + g);
            CP_ASYNC16(smem_u32(&ksm[nxt][st_][si]), k + g);
            CP_ASYNC16(smem_u32(&wsm[nxt][st_][si]), w + g);
            CP_ASYNC16(smem_u32(&vsm[nxt][st_][si]), v + g);
            CP_COMMIT();
            CP_WAIT1();
        } else {
            CP_WAIT0();
        }
        __syncthreads();

        if (nb > 0) {
            const int pb = (nb - 1) % 3;
            *(float4*)&att[base0 + (size_t)((nb - 1) * 16 + st_) * Dd + si] =
                *(const float4*)&osh[pb][st_][si];
        }

#pragma unroll 4
        for (int t = 0; t < 16; t++) {
            const float vm = vsm[buf][t][vcol];
            float a = 0.f;
            const float* rp = &rs[buf][t][kg * 16];
            const float* kp = &ksm[buf][t][kg * 16];
            const float* wp = &wsm[buf][t][kg * 16];
#pragma unroll
            for (int q = 0; q < 4; q++) {
                float4 r4 = *(const float4*)(rp + 4 * q);
                float4 k4 = *(const float4*)(kp + 4 * q);
                float4 w4 = *(const float4*)(wp + 4 * q);
                float kv, tt;
                kv = k4.x * vm; tt = fmaf(uo[4*q+0], kv, s[4*q+0]); a = fmaf(r4.x, tt, a); s[4*q+0] = fmaf(s[4*q+0], w4.x, kv);
                kv = k4.y * vm; tt = fmaf(uo[4*q+1], kv, s[4*q+1]); a = fmaf(r4.y, tt, a); s[4*q+1] = fmaf(s[4*q+1], w4.y, kv);
                kv = k4.z * vm; tt = fmaf(uo[4*q+2], kv, s[4*q+2]); a = fmaf(r4.z, tt, a); s[4*q+2] = fmaf(s[4*q+2], w4.z, kv);
                kv = k4.w * vm; tt = fmaf(uo[4*q+3], kv, s[4*q+3]); a = fmaf(r4.w, tt, a); s[4*q+3] = fmaf(s[4*q+3], w4.w, kv);
            }
            a += __shfl_xor_sync(0xffffffffu, a, 1);
            a += __shfl_xor_sync(0xffffffffu, a, 2);
            if (kg == 0) osh[buf][t][vcol] = a;
        }
    }
    __syncthreads();
    *(float4*)&att[base0 + (size_t)((NB - 1) * 16 + st_) * Dd + si] =
        *(const float4*)&osh[buf][st_][si];
#pragma unroll
    for (int j = 0; j < 16; j++)
        sout[sbase + (size_t)(kg * 16 + j) * 64 + vcol] = s[j];
}

// ====================== groupnorm + ln + *g, writes fp16 ====================
__global__ void __launch_bounds__(256) gnorm_k(
    const float* __restrict__ att, const float* __restrict__ g,
    const float* __restrict__ lng, const float* __restrict__ lnb,
    __half* __restrict__ oh)
{
    const int grp = blockIdx.x * 8 + (threadIdx.x >> 5);
    const int lane = threadIdx.x & 31;
    const int bt = grp >> 5;
    const int h = grp & 31;
    size_t base = (size_t)bt * Dd + h * 64;
    float v0 = att[base + lane];
    float v1 = att[base + lane + 32];
    float sum = v0 + v1;
    float sq = v0 * v0 + v1 * v1;
#pragma unroll
    for (int o = 16; o > 0; o >>= 1) {
        sum += __shfl_xor_sync(0xffffffffu, sum, o);
        sq  += __shfl_xor_sync(0xffffffffu, sq, o);
    }
    float mu = sum * (1.f / 64.f);
    float var = sq * (1.f / 64.f) - mu * mu;
    float inv = rsqrtf(var + 1e-5f);
    int li = h * 64 + lane;
    oh[base + lane] = __float2half_rn(
        fmaf((v0 - mu) * inv, lng[li], lnb[li]) * g[base + lane]);
    oh[base + lane + 32] = __float2half_rn(
        fmaf((v1 - mu) * inv, lng[li + 32], lnb[li + 32]) * g[base + lane + 32]);
}

// ====================== host ================================================
extern "C" void kernel_launch(void* const* d_in, const int* in_sizes, int n_in,
                              void* d_out, int out_size)
{
    const float* x     = (const float*)d_in[0];
    const float* prev  = (const float*)d_in[1];
    const float* state = (const float*)d_in[2];
    const float* x_maa = (const float*)d_in[3];
    const float* w_maa = (const float*)d_in[4];
    const float* k_maa = (const float*)d_in[5];
    const float* v_maa = (const float*)d_in[6];
    const float* r_maa = (const float*)d_in[7];
    const float* g_maa = (const float*)d_in[8];
    const float* tm_w1 = (const float*)d_in[9];
    const float* tm_w2 = (const float*)d_in[10];
    const float* td_w1 = (const float*)d_in[11];
    const float* td_w2 = (const float*)d_in[12];
    const float* tdec  = (const float*)d_in[13];
    const float* tfirst= (const float*)d_in[14];
    const float* W_r   = (const float*)d_in[15];
    const float* W_k   = (const float*)d_in[16];
    const float* W_v   = (const float*)d_in[17];
    const float* W_g   = (const float*)d_in[18];
    const float* W_o   = (const float*)d_in[19];
    const float* ln_g  = (const float*)d_in[20];
    const float* ln_b  = (const float*)d_in[21];

    float *m, *r, *k, *v, *g, *w, *att;
    cudaGetSymbolAddress((void**)&m,   g_m);
    cudaGetSymbolAddress((void**)&r,   g_r);
    cudaGetSymbolAddress((void**)&k,   g_k);
    cudaGetSymbolAddress((void**)&v,   g_v);
    cudaGetSymbolAddress((void**)&g,   g_g);
    cudaGetSymbolAddress((void**)&w,   g_w);
    cudaGetSymbolAddress((void**)&att, g_att);

    __half *xh, *wxh, *kxh, *vxh, *rxh, *gxh, *gnh, *h1h;
    __half *wrh, *wkh, *wvh, *wgh, *woh, *tm1h, *td1h, *td2h, *tm2h;
    cudaGetSymbolAddress((void**)&xh,  g_xh);
    cudaGetSymbolAddress((void**)&wxh, g_wxh);
    cudaGetSymbolAddress((void**)&kxh, g_kxh);
    cudaGetSymbolAddress((void**)&vxh, g_vxh);
    cudaGetSymbolAddress((void**)&rxh, g_rxh);
    cudaGetSymbolAddress((void**)&gxh, g_gxh);
    cudaGetSymbolAddress((void**)&gnh, g_gnh);
    cudaGetSymbolAddress((void**)&h1h, g_h1h);
    cudaGetSymbolAddress((void**)&wrh, g_wrh);
    cudaGetSymbolAddress((void**)&wkh, g_wkh);
    cudaGetSymbolAddress((void**)&wvh, g_wvh);
    cudaGetSymbolAddress((void**)&wgh, g_wgh);
    cudaGetSymbolAddress((void**)&woh, g_woh);
    cudaGetSymbolAddress((void**)&tm1h, g_tm1h);
    cudaGetSymbolAddress((void**)&td1h, g_td1h);
    cudaGetSymbolAddress((void**)&td2h, g_td2h);
    cudaGetSymbolAddress((void**)&tm2h, g_tm2h);

    float* out0 = (float*)d_out;
    float* out_xlast = out0 + (size_t)BT * Dd;
    float* out_state = out_xlast + (size_t)Bb * Dd;

    cudaFuncSetAttribute(gemm_one128, cudaFuncAttributeMaxDynamicSharedMemorySize, GEMM_SMEM128);
    cudaFuncSetAttribute(gemm_rkvg,   cudaFuncAttributeMaxDynamicSharedMemorySize, GEMM_SMEM128);

    // ---- [0] mega prologue: weights + tm_w2 fp16 + prep + lastcopy ----
    TsArgs ta;
    ta.src[0]=W_r;  ta.bh[0]=wrh;  ta.K[0]=Dd; ta.N[0]=Dd;  ta.gx[0]=64; ta.gy[0]=64;
    ta.src[1]=W_k;  ta.bh[1]=wkh;  ta.K[1]=Dd; ta.N[1]=Dd;  ta.gx[1]=64; ta.gy[1]=64;
    ta.src[2]=W_v;  ta.bh[2]=wvh;  ta.K[2]=Dd; ta.N[2]=Dd;  ta.gx[2]=64; ta.gy[2]=64;
    ta.src[3]=W_g;  ta.bh[3]=wgh;  ta.K[3]=Dd; ta.N[3]=Dd;  ta.gx[3]=64; ta.gy[3]=64;
    ta.src[4]=W_o;  ta.bh[4]=woh;  ta.K[4]=Dd; ta.N[4]=Dd;  ta.gx[4]=64; ta.gy[4]=64;
    ta.src[5]=tm_w1;ta.bh[5]=tm1h; ta.K[5]=Dd; ta.N[5]=E5c; ta.gx[5]=64; ta.gy[5]=8;
    ta.src[6]=td_w1;ta.bh[6]=td1h; ta.K[6]=Dd; ta.N[6]=64;  ta.gx[6]=64; ta.gy[6]=4;
    ta.src[7]=td_w2;ta.bh[7]=td2h; ta.K[7]=64; ta.N[7]=Dd;  ta.gx[7]=2;  ta.gy[7]=64;
    tsplit_all<<<dim3(64, 64, 11), 256>>>(ta, tm_w2, tm2h,
                                          x, prev, x_maa, xh, out_xlast);

    // ---- [1] m = tanh(xxx @ tm_w1) ----
    gemm_one128<<<dim3(2, BT/128), 256, GEMM_SMEM128>>>(xh, tm1h,
        m, nullptr, E5c, Dd, nullptr, 2);
    // ---- [2] mix + 5 lerps (fp16) ----
    mix_k<<<dim3(Dd/256, BT/8), 256>>>(x, prev, m, tm2h,
        w_maa, k_maa, v_maa, r_maa, g_maa,
        wxh, kxh, vxh, rxh, gxh);
    // ---- [3] big GEMMs r/k/v/g + overlapped td1 (z=4) ----
    gemm_rkvg<<<dim3(Dd/128, BT/128, 5), 256, GEMM_SMEM128>>>(
        rxh, wrh, r,
        kxh, wkh, k,
        vxh, wvh, v,
        gxh, wgh, g,
        wxh, td1h, h1h);
    // ---- [4] td2: w = exp(-exp(h1 @ td_w2 + decay)) ----
    gemm_one128<<<dim3(Dd/128, BT/128), 256, GEMM_SMEM128>>>(h1h, td2h,
        w, nullptr, Dd, 64, tdec, 4);
    // ---- [5] WKV scan ----
    wkv_k<<<Bb * Hh, 256>>>(r, k, v, w, tfirst, state, att, out_state);
    // ---- [6] groupnorm * ln * g (fp16) ----
    gnorm_k<<<(BT * Hh) / 8, 256>>>(att, g, ln_g, ln_b, gnh);
    // ---- [7] out = gn @ W_o (single-pass fp16) ----
    gemm_one128<<<dim3(Dd/128, BT/128), 256, GEMM_SMEM128>>>(gnh, woh,
        out0, nullptr, Dd, Dd, nullptr, 0);
}